// round 1
// baseline (speedup 1.0000x reference)
#include <cuda_runtime.h>
#include <math.h>

// Problem constants
constexpr int BATCH = 2;
constexpr int SEQ   = 2048;
constexpr int DMODEL= 1024;
constexpr int HEADS = 16;
constexpr int DHEAD = 64;
constexpr int MTOT  = BATCH * SEQ;           // 4096
constexpr float SCALE = 0.0220970869120796f; // 1/sqrt(2048)

// Scratch (allocation-free rule: __device__ globals)
__device__ float g_q[BATCH * HEADS * SEQ * DHEAD];
__device__ float g_k[BATCH * HEADS * SEQ * DHEAD];
__device__ float g_v[BATCH * HEADS * SEQ * DHEAD];
__device__ float g_ctx[BATCH * SEQ * DMODEL];

// ---------------------------------------------------------------------------
// Fused QKV projection: C[m][e] = sum_d X[m][d] * W[e][d]  (NT gemm)
// 64x64 tile, BK=16, 256 threads, 4x4 per thread.
// Epilogue scatters into [B, H, SEQ, DHEAD]. Since BN=64==DHEAD and D=1024,
// blockIdx.x IS the head index.
// ---------------------------------------------------------------------------
__global__ __launch_bounds__(256) void proj_qkv(const float* __restrict__ x,
                                                const float* __restrict__ Wq,
                                                const float* __restrict__ Wk,
                                                const float* __restrict__ Wv)
{
    const float* W   = (blockIdx.z == 0) ? Wq : (blockIdx.z == 1 ? Wk : Wv);
    float*       dst = (blockIdx.z == 0) ? g_q : (blockIdx.z == 1 ? g_k : g_v);

    __shared__ float As[16][64];
    __shared__ float Bs[16][64];

    const int tid = threadIdx.x;
    const int tx  = tid & 15;
    const int ty  = tid >> 4;

    // Each thread loads one float4 of A and one of B per K-step.
    const int lr = tid >> 2;          // 0..63 row within tile
    const int lc = (tid & 3) << 2;    // 0,4,8,12 col within BK
    const float* Arow = x + (size_t)(blockIdx.y * 64 + lr) * DMODEL + lc;
    const float* Brow = W + (size_t)(blockIdx.x * 64 + lr) * DMODEL + lc;

    float acc[4][4] = {};

    for (int k0 = 0; k0 < DMODEL; k0 += 16) {
        float4 a4 = *(const float4*)(Arow + k0);
        float4 b4 = *(const float4*)(Brow + k0);
        As[lc + 0][lr] = a4.x; As[lc + 1][lr] = a4.y;
        As[lc + 2][lr] = a4.z; As[lc + 3][lr] = a4.w;
        Bs[lc + 0][lr] = b4.x; Bs[lc + 1][lr] = b4.y;
        Bs[lc + 2][lr] = b4.z; Bs[lc + 3][lr] = b4.w;
        __syncthreads();

        #pragma unroll
        for (int kk = 0; kk < 16; kk++) {
            float a[4], b[4];
            #pragma unroll
            for (int i = 0; i < 4; i++) a[i] = As[kk][ty * 4 + i];
            #pragma unroll
            for (int j = 0; j < 4; j++) b[j] = Bs[kk][tx * 4 + j];
            #pragma unroll
            for (int i = 0; i < 4; i++)
                #pragma unroll
                for (int j = 0; j < 4; j++)
                    acc[i][j] += a[i] * b[j];
        }
        __syncthreads();
    }

    const int h = blockIdx.x;  // head index (BN == DHEAD)
    #pragma unroll
    for (int i = 0; i < 4; i++) {
        int m  = blockIdx.y * 64 + ty * 4 + i;
        int bi = m >> 11;            // / SEQ
        int n  = m & (SEQ - 1);
        float4 v = make_float4(acc[i][0], acc[i][1], acc[i][2], acc[i][3]);
        *(float4*)&dst[(((size_t)bi * HEADS + h) * SEQ + n) * DHEAD + tx * 4] = v;
    }
}

// ---------------------------------------------------------------------------
// Causal flash attention: 64 queries per block, 64-key tiles, online softmax.
// 256 threads, 4x4 register tiles for both S and O.
// ---------------------------------------------------------------------------
constexpr int PSTRIDE = 80;  // 64 + 16 pad, keeps rows 16B aligned
constexpr int ATTN_SMEM = (3 * 64 * 64 + 64 * PSTRIDE) * (int)sizeof(float); // 69632 B

__global__ __launch_bounds__(256) void attn_kernel()
{
    extern __shared__ float sm[];
    float (*Qst)[64]     = (float(*)[64])(sm);                 // [d][q]
    float (*Kst)[64]     = (float(*)[64])(sm + 64 * 64);       // [d][k]
    float (*Vs)[64]      = (float(*)[64])(sm + 2 * 64 * 64);   // [k][dh]
    float (*Pst)[PSTRIDE]= (float(*)[PSTRIDE])(sm + 3 * 64 * 64); // [k][q]

    const int qb = blockIdx.x;
    const int h  = blockIdx.y;
    const int bb = blockIdx.z;

    const size_t head_off = ((size_t)bb * HEADS + h) * SEQ * DHEAD;
    const float* Qg = g_q + head_off;
    const float* Kg = g_k + head_off;
    const float* Vg = g_v + head_off;

    const int tid = threadIdx.x;
    const int tx  = tid & 15;
    const int ty  = tid >> 4;

    // Load Q tile transposed: Qst[d][q]
    #pragma unroll
    for (int p = 0; p < 4; p++) {
        int f = p * 256 + tid;
        int r = f >> 4;            // local q row
        int c = (f & 15) << 2;     // d
        float4 v = *(const float4*)(Qg + (size_t)(qb * 64 + r) * DHEAD + c);
        Qst[c + 0][r] = v.x; Qst[c + 1][r] = v.y;
        Qst[c + 2][r] = v.z; Qst[c + 3][r] = v.w;
    }

    float m_i[4], l_i[4], o[4][4];
    #pragma unroll
    for (int i = 0; i < 4; i++) {
        m_i[i] = -INFINITY; l_i[i] = 0.f;
        #pragma unroll
        for (int j = 0; j < 4; j++) o[i][j] = 0.f;
    }

    for (int kt = 0; kt <= qb; kt++) {
        __syncthreads();  // previous iteration done with Kst/Vs/Pst

        // Load K (transposed) and V tiles
        #pragma unroll
        for (int p = 0; p < 4; p++) {
            int f = p * 256 + tid;
            int r = f >> 4;
            int c = (f & 15) << 2;
            float4 kv = *(const float4*)(Kg + (size_t)(kt * 64 + r) * DHEAD + c);
            Kst[c + 0][r] = kv.x; Kst[c + 1][r] = kv.y;
            Kst[c + 2][r] = kv.z; Kst[c + 3][r] = kv.w;
            float4 vv = *(const float4*)(Vg + (size_t)(kt * 64 + r) * DHEAD + c);
            *(float4*)&Vs[r][c] = vv;
        }
        __syncthreads();

        // S = Q @ K^T (4x4 per thread)
        float s[4][4] = {};
        #pragma unroll 16
        for (int d = 0; d < 64; d++) {
            float a[4], bv[4];
            #pragma unroll
            for (int i = 0; i < 4; i++) a[i] = Qst[d][ty * 4 + i];
            #pragma unroll
            for (int j = 0; j < 4; j++) bv[j] = Kst[d][tx * 4 + j];
            #pragma unroll
            for (int i = 0; i < 4; i++)
                #pragma unroll
                for (int j = 0; j < 4; j++)
                    s[i][j] += a[i] * bv[j];
        }

        const bool diag = (kt == qb);

        // Online softmax update
        #pragma unroll
        for (int i = 0; i < 4; i++) {
            int qglob = qb * 64 + ty * 4 + i;
            float mx = -INFINITY;
            #pragma unroll
            for (int j = 0; j < 4; j++) {
                float v = s[i][j] * SCALE;
                if (diag && (kt * 64 + tx * 4 + j) > qglob) v = -INFINITY;
                s[i][j] = v;
                mx = fmaxf(mx, v);
            }
            #pragma unroll
            for (int off = 8; off > 0; off >>= 1)
                mx = fmaxf(mx, __shfl_xor_sync(0xffffffffu, mx, off));

            float mnew  = fmaxf(m_i[i], mx);
            float alpha = __expf(m_i[i] - mnew);
            float rsum  = 0.f;
            #pragma unroll
            for (int j = 0; j < 4; j++) {
                float p = __expf(s[i][j] - mnew);
                s[i][j] = p;
                rsum += p;
            }
            #pragma unroll
            for (int off = 8; off > 0; off >>= 1)
                rsum += __shfl_xor_sync(0xffffffffu, rsum, off);

            l_i[i] = l_i[i] * alpha + rsum;
            m_i[i] = mnew;
            #pragma unroll
            for (int j = 0; j < 4; j++) o[i][j] *= alpha;
        }

        // Stage P transposed: Pst[k][q]
        #pragma unroll
        for (int i = 0; i < 4; i++)
            #pragma unroll
            for (int j = 0; j < 4; j++)
                Pst[tx * 4 + j][ty * 4 + i] = s[i][j];
        __syncthreads();

        // O += P @ V
        #pragma unroll 16
        for (int k = 0; k < 64; k++) {
            float a[4], bv[4];
            #pragma unroll
            for (int i = 0; i < 4; i++) a[i] = Pst[k][ty * 4 + i];
            #pragma unroll
            for (int j = 0; j < 4; j++) bv[j] = Vs[k][tx * 4 + j];
            #pragma unroll
            for (int i = 0; i < 4; i++)
                #pragma unroll
                for (int j = 0; j < 4; j++)
                    o[i][j] += a[i] * bv[j];
        }
    }

    // Epilogue: ctx layout [B, SEQ, H, DHEAD] == [B, SEQ, D]
    #pragma unroll
    for (int i = 0; i < 4; i++) {
        float inv = 1.f / l_i[i];
        int n = qb * 64 + ty * 4 + i;
        float4 st = make_float4(o[i][0] * inv, o[i][1] * inv,
                                o[i][2] * inv, o[i][3] * inv);
        *(float4*)&g_ctx[(((size_t)bb * SEQ + n) * HEADS + h) * DHEAD + tx * 4] = st;
    }
}

// ---------------------------------------------------------------------------
// Output projection: out[m][e] = sum_d ctx[m][d] * Wo[e][d] + bo[e]
// ---------------------------------------------------------------------------
__global__ __launch_bounds__(256) void proj_out(const float* __restrict__ Wo,
                                                const float* __restrict__ bo,
                                                float* __restrict__ out)
{
    __shared__ float As[16][64];
    __shared__ float Bs[16][64];

    const int tid = threadIdx.x;
    const int tx  = tid & 15;
    const int ty  = tid >> 4;

    const int lr = tid >> 2;
    const int lc = (tid & 3) << 2;
    const float* Arow = g_ctx + (size_t)(blockIdx.y * 64 + lr) * DMODEL + lc;
    const float* Brow = Wo    + (size_t)(blockIdx.x * 64 + lr) * DMODEL + lc;

    float acc[4][4] = {};

    for (int k0 = 0; k0 < DMODEL; k0 += 16) {
        float4 a4 = *(const float4*)(Arow + k0);
        float4 b4 = *(const float4*)(Brow + k0);
        As[lc + 0][lr] = a4.x; As[lc + 1][lr] = a4.y;
        As[lc + 2][lr] = a4.z; As[lc + 3][lr] = a4.w;
        Bs[lc + 0][lr] = b4.x; Bs[lc + 1][lr] = b4.y;
        Bs[lc + 2][lr] = b4.z; Bs[lc + 3][lr] = b4.w;
        __syncthreads();

        #pragma unroll
        for (int kk = 0; kk < 16; kk++) {
            float a[4], b[4];
            #pragma unroll
            for (int i = 0; i < 4; i++) a[i] = As[kk][ty * 4 + i];
            #pragma unroll
            for (int j = 0; j < 4; j++) b[j] = Bs[kk][tx * 4 + j];
            #pragma unroll
            for (int i = 0; i < 4; i++)
                #pragma unroll
                for (int j = 0; j < 4; j++)
                    acc[i][j] += a[i] * b[j];
        }
        __syncthreads();
    }

    const int e0 = blockIdx.x * 64 + tx * 4;
    float4 bias = *(const float4*)(bo + e0);
    #pragma unroll
    for (int i = 0; i < 4; i++) {
        int m = blockIdx.y * 64 + ty * 4 + i;
        float4 v = make_float4(acc[i][0] + bias.x, acc[i][1] + bias.y,
                               acc[i][2] + bias.z, acc[i][3] + bias.w);
        *(float4*)&out[(size_t)m * DMODEL + e0] = v;
    }
}

// ---------------------------------------------------------------------------
extern "C" void kernel_launch(void* const* d_in, const int* in_sizes, int n_in,
                              void* d_out, int out_size)
{
    (void)in_sizes; (void)n_in; (void)out_size;
    const float* x  = (const float*)d_in[0];
    const float* Wq = (const float*)d_in[1];
    const float* Wk = (const float*)d_in[2];
    const float* Wv = (const float*)d_in[3];
    const float* Wo = (const float*)d_in[4];
    const float* bo = (const float*)d_in[5];
    float* out = (float*)d_out;

    cudaFuncSetAttribute(attn_kernel, cudaFuncAttributeMaxDynamicSharedMemorySize,
                         ATTN_SMEM);

    // QKV projections: grid (E/64, M/64, 3)
    proj_qkv<<<dim3(DMODEL / 64, MTOT / 64, 3), 256>>>(x, Wq, Wk, Wv);

    // Attention: grid (SEQ/64, H, B)
    attn_kernel<<<dim3(SEQ / 64, HEADS, BATCH), 256, ATTN_SMEM>>>();

    // Output projection
    proj_out<<<dim3(DMODEL / 64, MTOT / 64), 256>>>(Wo, bo, out);
}

// round 2
// speedup vs baseline: 1.3788x; 1.3788x over previous
#include <cuda_runtime.h>
#include <math.h>

// Problem constants
constexpr int BATCH = 2;
constexpr int SEQ   = 2048;
constexpr int DMODEL= 1024;
constexpr int HEADS = 16;
constexpr int DHEAD = 64;
constexpr int MTOT  = BATCH * SEQ;           // 4096
constexpr float SCALE = 0.0220970869120796f; // 1/sqrt(2048)

// Scratch (allocation-free rule: __device__ globals)
__device__ float g_q[BATCH * HEADS * SEQ * DHEAD];
__device__ float g_k[BATCH * HEADS * SEQ * DHEAD];
__device__ float g_v[BATCH * HEADS * SEQ * DHEAD];
__device__ float g_ctx[BATCH * SEQ * DMODEL];

// ---------------------------------------------------------------------------
// QKV projection: C[m][e] = sum_d X[m][d] * W[e][d]  (NT gemm)
// 128x128 tile, BK=16, 256 threads, 8x8 per thread (split-tile: frags at
// tx*4 and tx*4+64 -> conflict-free LDS.128). Register prefetch pipeline.
// Epilogue scatters into [B, H, SEQ, DHEAD]; head = blockIdx.x*2 + ci.
// ---------------------------------------------------------------------------
__global__ __launch_bounds__(256, 2) void proj_qkv(const float* __restrict__ x,
                                                   const float* __restrict__ Wq,
                                                   const float* __restrict__ Wk,
                                                   const float* __restrict__ Wv)
{
    const float* W   = (blockIdx.z == 0) ? Wq : (blockIdx.z == 1 ? Wk : Wv);
    float*       dst = (blockIdx.z == 0) ? g_q : (blockIdx.z == 1 ? g_k : g_v);

    __shared__ float As[16][132];
    __shared__ float Bs[16][132];

    const int tid = threadIdx.x;
    const int tx  = tid & 15;
    const int ty  = tid >> 4;

    // loader mapping: each thread owns row lm, k-chunk lk (8 floats = 2 float4)
    const int lm = tid >> 1;
    const int lk = (tid & 1) << 3;
    const float* Ap = x + (size_t)(blockIdx.y * 128 + lm) * DMODEL + lk;
    const float* Bp = W + (size_t)(blockIdx.x * 128 + lm) * DMODEL + lk;

    float acc[2][2][4][4] = {};  // [ri][ci][i][j]

    float4 pa0 = *(const float4*)(Ap);
    float4 pa1 = *(const float4*)(Ap + 4);
    float4 pb0 = *(const float4*)(Bp);
    float4 pb1 = *(const float4*)(Bp + 4);

    for (int k0 = 0; k0 < DMODEL; k0 += 16) {
        As[lk + 0][lm] = pa0.x; As[lk + 1][lm] = pa0.y;
        As[lk + 2][lm] = pa0.z; As[lk + 3][lm] = pa0.w;
        As[lk + 4][lm] = pa1.x; As[lk + 5][lm] = pa1.y;
        As[lk + 6][lm] = pa1.z; As[lk + 7][lm] = pa1.w;
        Bs[lk + 0][lm] = pb0.x; Bs[lk + 1][lm] = pb0.y;
        Bs[lk + 2][lm] = pb0.z; Bs[lk + 3][lm] = pb0.w;
        Bs[lk + 4][lm] = pb1.x; Bs[lk + 5][lm] = pb1.y;
        Bs[lk + 6][lm] = pb1.z; Bs[lk + 7][lm] = pb1.w;
        __syncthreads();

        if (k0 + 16 < DMODEL) {
            pa0 = *(const float4*)(Ap + k0 + 16);
            pa1 = *(const float4*)(Ap + k0 + 20);
            pb0 = *(const float4*)(Bp + k0 + 16);
            pb1 = *(const float4*)(Bp + k0 + 20);
        }

        #pragma unroll
        for (int kk = 0; kk < 16; kk++) {
            float4 a0 = *(const float4*)&As[kk][ty * 4];
            float4 a1 = *(const float4*)&As[kk][ty * 4 + 64];
            float4 b0 = *(const float4*)&Bs[kk][tx * 4];
            float4 b1 = *(const float4*)&Bs[kk][tx * 4 + 64];
            const float a[2][4] = {{a0.x, a0.y, a0.z, a0.w},
                                   {a1.x, a1.y, a1.z, a1.w}};
            const float b[2][4] = {{b0.x, b0.y, b0.z, b0.w},
                                   {b1.x, b1.y, b1.z, b1.w}};
            #pragma unroll
            for (int ri = 0; ri < 2; ri++)
                #pragma unroll
                for (int i = 0; i < 4; i++)
                    #pragma unroll
                    for (int ci = 0; ci < 2; ci++)
                        #pragma unroll
                        for (int j = 0; j < 4; j++)
                            acc[ri][ci][i][j] += a[ri][i] * b[ci][j];
        }
        __syncthreads();
    }

    #pragma unroll
    for (int ri = 0; ri < 2; ri++)
        #pragma unroll
        for (int ci = 0; ci < 2; ci++) {
            const int h = blockIdx.x * 2 + ci;
            #pragma unroll
            for (int i = 0; i < 4; i++) {
                int m  = blockIdx.y * 128 + ri * 64 + ty * 4 + i;
                int bi = m >> 11;
                int n  = m & (SEQ - 1);
                float4 v = make_float4(acc[ri][ci][i][0], acc[ri][ci][i][1],
                                       acc[ri][ci][i][2], acc[ri][ci][i][3]);
                *(float4*)&dst[(((size_t)bi * HEADS + h) * SEQ + n) * DHEAD + tx * 4] = v;
            }
        }
}

// ---------------------------------------------------------------------------
// Causal flash attention: 128 queries x 64-key tiles, online softmax.
// 256 threads; per-thread 8q x 4k split-tile (rows ty*4 and ty*4+64).
// ---------------------------------------------------------------------------
constexpr int QS = 132;  // Qt/Pt row stride (pad, 16B aligned)
constexpr int KS = 68;   // Kt/Vs row stride
constexpr int ATTN_SMEM = 64 * (QS + KS + KS + QS) * (int)sizeof(float); // 102400 B

__global__ __launch_bounds__(256, 2) void attn_kernel()
{
    extern __shared__ float sm[];
    float (*Qt)[QS] = (float(*)[QS])(sm);                       // [d][q] 64x128
    float (*Kt)[KS] = (float(*)[KS])(sm + 64 * QS);             // [d][k] 64x64
    float (*Vs)[KS] = (float(*)[KS])(sm + 64 * QS + 64 * KS);   // [k][dh]
    float (*Pt)[QS] = (float(*)[QS])(sm + 64 * QS + 2 * 64 * KS); // [k][q]

    const int qb = blockIdx.x;
    const int h  = blockIdx.y;
    const int bb = blockIdx.z;

    const size_t hoff = ((size_t)bb * HEADS + h) * SEQ * DHEAD;
    const float* Qg = g_q + hoff;
    const float* Kg = g_k + hoff;
    const float* Vg = g_v + hoff;

    const int tid = threadIdx.x;
    const int tx  = tid & 15;
    const int ty  = tid >> 4;

    // Load Q tile transposed: Qt[d][q], q in [0,128)
    #pragma unroll
    for (int p = 0; p < 8; p++) {
        int f = p * 256 + tid;
        int r = f >> 4;            // local q
        int c = (f & 15) << 2;     // d
        float4 v = *(const float4*)(Qg + (size_t)(qb * 128 + r) * DHEAD + c);
        Qt[c + 0][r] = v.x; Qt[c + 1][r] = v.y;
        Qt[c + 2][r] = v.z; Qt[c + 3][r] = v.w;
    }

    float m_i[2][4], l_i[2][4], o[2][4][4];
    #pragma unroll
    for (int ri = 0; ri < 2; ri++)
        #pragma unroll
        for (int i = 0; i < 4; i++) {
            m_i[ri][i] = -INFINITY; l_i[ri][i] = 0.f;
            #pragma unroll
            for (int j = 0; j < 4; j++) o[ri][i][j] = 0.f;
        }

    const int ktmax = 2 * qb + 1;
    for (int kt = 0; kt <= ktmax; kt++) {
        __syncthreads();  // previous iter done with Kt/Vs/Pt

        #pragma unroll
        for (int p = 0; p < 4; p++) {
            int f = p * 256 + tid;
            int r = f >> 4;
            int c = (f & 15) << 2;
            float4 kv = *(const float4*)(Kg + (size_t)(kt * 64 + r) * DHEAD + c);
            Kt[c + 0][r] = kv.x; Kt[c + 1][r] = kv.y;
            Kt[c + 2][r] = kv.z; Kt[c + 3][r] = kv.w;
            float4 vv = *(const float4*)(Vg + (size_t)(kt * 64 + r) * DHEAD + c);
            *(float4*)&Vs[r][c] = vv;
        }
        __syncthreads();

        // S = Q @ K^T
        float s[2][4][4] = {};
        #pragma unroll 8
        for (int d = 0; d < 64; d++) {
            float4 a0 = *(const float4*)&Qt[d][ty * 4];
            float4 a1 = *(const float4*)&Qt[d][ty * 4 + 64];
            float4 b  = *(const float4*)&Kt[d][tx * 4];
            const float a[2][4] = {{a0.x, a0.y, a0.z, a0.w},
                                   {a1.x, a1.y, a1.z, a1.w}};
            const float bv[4] = {b.x, b.y, b.z, b.w};
            #pragma unroll
            for (int ri = 0; ri < 2; ri++)
                #pragma unroll
                for (int i = 0; i < 4; i++)
                    #pragma unroll
                    for (int j = 0; j < 4; j++)
                        s[ri][i][j] += a[ri][i] * bv[j];
        }

        const bool need_mask = (kt >= 2 * qb);

        // Online softmax update (row spread over tx lanes 0..15)
        #pragma unroll
        for (int ri = 0; ri < 2; ri++)
            #pragma unroll
            for (int i = 0; i < 4; i++) {
                const int qglob = qb * 128 + ri * 64 + ty * 4 + i;
                float mx = -INFINITY;
                #pragma unroll
                for (int j = 0; j < 4; j++) {
                    float v = s[ri][i][j] * SCALE;
                    if (need_mask && (kt * 64 + tx * 4 + j) > qglob) v = -INFINITY;
                    s[ri][i][j] = v;
                    mx = fmaxf(mx, v);
                }
                #pragma unroll
                for (int off = 8; off > 0; off >>= 1)
                    mx = fmaxf(mx, __shfl_xor_sync(0xffffffffu, mx, off));

                float mnew  = fmaxf(m_i[ri][i], mx);
                float alpha = __expf(m_i[ri][i] - mnew);
                float rsum  = 0.f;
                #pragma unroll
                for (int j = 0; j < 4; j++) {
                    float p = __expf(s[ri][i][j] - mnew);
                    s[ri][i][j] = p;
                    rsum += p;
                }
                #pragma unroll
                for (int off = 8; off > 0; off >>= 1)
                    rsum += __shfl_xor_sync(0xffffffffu, rsum, off);

                l_i[ri][i] = l_i[ri][i] * alpha + rsum;
                m_i[ri][i] = mnew;
                #pragma unroll
                for (int j = 0; j < 4; j++) o[ri][i][j] *= alpha;
            }

        // Stage P transposed: Pt[k][q]
        #pragma unroll
        for (int ri = 0; ri < 2; ri++)
            #pragma unroll
            for (int i = 0; i < 4; i++)
                #pragma unroll
                for (int j = 0; j < 4; j++)
                    Pt[tx * 4 + j][ri * 64 + ty * 4 + i] = s[ri][i][j];
        __syncthreads();

        // O += P @ V
        #pragma unroll 8
        for (int k = 0; k < 64; k++) {
            float4 a0 = *(const float4*)&Pt[k][ty * 4];
            float4 a1 = *(const float4*)&Pt[k][ty * 4 + 64];
            float4 b  = *(const float4*)&Vs[k][tx * 4];
            const float a[2][4] = {{a0.x, a0.y, a0.z, a0.w},
                                   {a1.x, a1.y, a1.z, a1.w}};
            const float bv[4] = {b.x, b.y, b.z, b.w};
            #pragma unroll
            for (int ri = 0; ri < 2; ri++)
                #pragma unroll
                for (int i = 0; i < 4; i++)
                    #pragma unroll
                    for (int j = 0; j < 4; j++)
                        o[ri][i][j] += a[ri][i] * bv[j];
        }
    }

    // Epilogue: ctx layout [B, SEQ, H, DHEAD] == [B, SEQ, D]
    #pragma unroll
    for (int ri = 0; ri < 2; ri++)
        #pragma unroll
        for (int i = 0; i < 4; i++) {
            float inv = 1.f / l_i[ri][i];
            int q = qb * 128 + ri * 64 + ty * 4 + i;
            float4 st = make_float4(o[ri][i][0] * inv, o[ri][i][1] * inv,
                                    o[ri][i][2] * inv, o[ri][i][3] * inv);
            *(float4*)&g_ctx[(((size_t)bb * SEQ + q) * HEADS + h) * DHEAD + tx * 4] = st;
        }
}

// ---------------------------------------------------------------------------
// Output projection: out[m][e] = sum_d ctx[m][d] * Wo[e][d] + bo[e]
// Same 128x128x16 split-tile GEMM.
// ---------------------------------------------------------------------------
__global__ __launch_bounds__(256, 2) void proj_out(const float* __restrict__ Wo,
                                                   const float* __restrict__ bo,
                                                   float* __restrict__ out)
{
    __shared__ float As[16][132];
    __shared__ float Bs[16][132];

    const int tid = threadIdx.x;
    const int tx  = tid & 15;
    const int ty  = tid >> 4;

    const int lm = tid >> 1;
    const int lk = (tid & 1) << 3;
    const float* Ap = g_ctx + (size_t)(blockIdx.y * 128 + lm) * DMODEL + lk;
    const float* Bp = Wo    + (size_t)(blockIdx.x * 128 + lm) * DMODEL + lk;

    float acc[2][2][4][4] = {};

    float4 pa0 = *(const float4*)(Ap);
    float4 pa1 = *(const float4*)(Ap + 4);
    float4 pb0 = *(const float4*)(Bp);
    float4 pb1 = *(const float4*)(Bp + 4);

    for (int k0 = 0; k0 < DMODEL; k0 += 16) {
        As[lk + 0][lm] = pa0.x; As[lk + 1][lm] = pa0.y;
        As[lk + 2][lm] = pa0.z; As[lk + 3][lm] = pa0.w;
        As[lk + 4][lm] = pa1.x; As[lk + 5][lm] = pa1.y;
        As[lk + 6][lm] = pa1.z; As[lk + 7][lm] = pa1.w;
        Bs[lk + 0][lm] = pb0.x; Bs[lk + 1][lm] = pb0.y;
        Bs[lk + 2][lm] = pb0.z; Bs[lk + 3][lm] = pb0.w;
        Bs[lk + 4][lm] = pb1.x; Bs[lk + 5][lm] = pb1.y;
        Bs[lk + 6][lm] = pb1.z; Bs[lk + 7][lm] = pb1.w;
        __syncthreads();

        if (k0 + 16 < DMODEL) {
            pa0 = *(const float4*)(Ap + k0 + 16);
            pa1 = *(const float4*)(Ap + k0 + 20);
            pb0 = *(const float4*)(Bp + k0 + 16);
            pb1 = *(const float4*)(Bp + k0 + 20);
        }

        #pragma unroll
        for (int kk = 0; kk < 16; kk++) {
            float4 a0 = *(const float4*)&As[kk][ty * 4];
            float4 a1 = *(const float4*)&As[kk][ty * 4 + 64];
            float4 b0 = *(const float4*)&Bs[kk][tx * 4];
            float4 b1 = *(const float4*)&Bs[kk][tx * 4 + 64];
            const float a[2][4] = {{a0.x, a0.y, a0.z, a0.w},
                                   {a1.x, a1.y, a1.z, a1.w}};
            const float b[2][4] = {{b0.x, b0.y, b0.z, b0.w},
                                   {b1.x, b1.y, b1.z, b1.w}};
            #pragma unroll
            for (int ri = 0; ri < 2; ri++)
                #pragma unroll
                for (int i = 0; i < 4; i++)
                    #pragma unroll
                    for (int ci = 0; ci < 2; ci++)
                        #pragma unroll
                        for (int j = 0; j < 4; j++)
                            acc[ri][ci][i][j] += a[ri][i] * b[ci][j];
        }
        __syncthreads();
    }

    #pragma unroll
    for (int ri = 0; ri < 2; ri++)
        #pragma unroll
        for (int ci = 0; ci < 2; ci++) {
            const int e0 = blockIdx.x * 128 + ci * 64 + tx * 4;
            float4 bias = *(const float4*)(bo + e0);
            #pragma unroll
            for (int i = 0; i < 4; i++) {
                int m = blockIdx.y * 128 + ri * 64 + ty * 4 + i;
                float4 v = make_float4(acc[ri][ci][i][0] + bias.x,
                                       acc[ri][ci][i][1] + bias.y,
                                       acc[ri][ci][i][2] + bias.z,
                                       acc[ri][ci][i][3] + bias.w);
                *(float4*)&out[(size_t)m * DMODEL + e0] = v;
            }
        }
}

// ---------------------------------------------------------------------------
extern "C" void kernel_launch(void* const* d_in, const int* in_sizes, int n_in,
                              void* d_out, int out_size)
{
    (void)in_sizes; (void)n_in; (void)out_size;
    const float* x  = (const float*)d_in[0];
    const float* Wq = (const float*)d_in[1];
    const float* Wk = (const float*)d_in[2];
    const float* Wv = (const float*)d_in[3];
    const float* Wo = (const float*)d_in[4];
    const float* bo = (const float*)d_in[5];
    float* out = (float*)d_out;

    cudaFuncSetAttribute(attn_kernel, cudaFuncAttributeMaxDynamicSharedMemorySize,
                         ATTN_SMEM);

    // QKV projections: grid (E/128, M/128, 3)
    proj_qkv<<<dim3(DMODEL / 128, MTOT / 128, 3), 256>>>(x, Wq, Wk, Wv);

    // Attention: grid (SEQ/128, H, B)
    attn_kernel<<<dim3(SEQ / 128, HEADS, BATCH), 256, ATTN_SMEM>>>();

    // Output projection
    proj_out<<<dim3(DMODEL / 128, MTOT / 128), 256>>>(Wo, bo, out);
}

// round 4
// speedup vs baseline: 1.7218x; 1.2488x over previous
#include <cuda_runtime.h>
#include <cuda_bf16.h>
#include <math.h>
#include <stdint.h>

// Problem constants
constexpr int BATCH = 2;
constexpr int SEQ   = 2048;
constexpr int DMODEL= 1024;
constexpr int HEADS = 16;
constexpr int DHEAD = 64;
constexpr int MTOT  = BATCH * SEQ;           // 4096
constexpr float SCALE = 0.0220970869120796f; // 1/sqrt(2048)

// Scratch (allocation-free rule: __device__ globals)
__device__ float g_q[BATCH * HEADS * SEQ * DHEAD];
__device__ float g_k[BATCH * HEADS * SEQ * DHEAD];
__device__ float g_v[BATCH * HEADS * SEQ * DHEAD];
__device__ float g_ctx[BATCH * SEQ * DMODEL];

// bf16 hi/lo split operands
__device__ __nv_bfloat16 g_xhi[MTOT * DMODEL];
__device__ __nv_bfloat16 g_xlo[MTOT * DMODEL];
__device__ __nv_bfloat16 g_whi[4 * DMODEL * DMODEL];
__device__ __nv_bfloat16 g_wlo[4 * DMODEL * DMODEL];
__device__ __nv_bfloat16 g_chi[MTOT * DMODEL];
__device__ __nv_bfloat16 g_clo[MTOT * DMODEL];

// ---------------------------------------------------------------------------
// Portable tensor-core helpers (sm_80+ ISA, works on plain sm_103 target)
// ---------------------------------------------------------------------------
__device__ __forceinline__ uint32_t smem_u32(const void* p) {
    uint32_t a;
    asm("{ .reg .u64 t; cvta.to.shared.u64 t, %1; cvt.u32.u64 %0, t; }"
        : "=r"(a) : "l"(p));
    return a;
}
__device__ __forceinline__ void ldsm_x4(uint32_t r[4], uint32_t a) {
    asm volatile("ldmatrix.sync.aligned.m8n8.x4.shared.b16 {%0,%1,%2,%3}, [%4];"
                 : "=r"(r[0]), "=r"(r[1]), "=r"(r[2]), "=r"(r[3]) : "r"(a));
}
__device__ __forceinline__ void ldsm_x2(uint32_t r[2], uint32_t a) {
    asm volatile("ldmatrix.sync.aligned.m8n8.x2.shared.b16 {%0,%1}, [%2];"
                 : "=r"(r[0]), "=r"(r[1]) : "r"(a));
}
__device__ __forceinline__ void mma_bf16(float d[4], const uint32_t a[4],
                                         const uint32_t b[2]) {
    asm volatile(
        "mma.sync.aligned.m16n8k16.row.col.f32.bf16.bf16.f32 "
        "{%0,%1,%2,%3}, {%4,%5,%6,%7}, {%8,%9}, {%0,%1,%2,%3};"
        : "+f"(d[0]), "+f"(d[1]), "+f"(d[2]), "+f"(d[3])
        : "r"(a[0]), "r"(a[1]), "r"(a[2]), "r"(a[3]), "r"(b[0]), "r"(b[1]));
}
__device__ __forceinline__ void cp_async16(uint32_t dst, const void* src) {
    asm volatile("cp.async.cg.shared.global [%0], [%1], 16;"
                 :: "r"(dst), "l"(src) : "memory");
}
#define CP_COMMIT() asm volatile("cp.async.commit_group;" ::: "memory")
#define CP_WAIT(n)  asm volatile("cp.async.wait_group %0;" :: "n"(n) : "memory")

// ---------------------------------------------------------------------------
// fp32 -> bf16 hi/lo split
// ---------------------------------------------------------------------------
__global__ __launch_bounds__(256) void precvt(const float* __restrict__ src,
                                              __nv_bfloat16* __restrict__ hi,
                                              __nv_bfloat16* __restrict__ lo,
                                              int n4)
{
    int i = blockIdx.x * 256 + threadIdx.x;
    if (i >= n4) return;
    float4 v = ((const float4*)src)[i];
    __nv_bfloat16 h0 = __float2bfloat16(v.x);
    __nv_bfloat16 h1 = __float2bfloat16(v.y);
    __nv_bfloat16 h2 = __float2bfloat16(v.z);
    __nv_bfloat16 h3 = __float2bfloat16(v.w);
    __nv_bfloat16 l0 = __float2bfloat16(v.x - __bfloat162float(h0));
    __nv_bfloat16 l1 = __float2bfloat16(v.y - __bfloat162float(h1));
    __nv_bfloat16 l2 = __float2bfloat16(v.z - __bfloat162float(h2));
    __nv_bfloat16 l3 = __float2bfloat16(v.w - __bfloat162float(h3));
    ((__nv_bfloat162*)hi)[2 * i]     = __nv_bfloat162(h0, h1);
    ((__nv_bfloat162*)hi)[2 * i + 1] = __nv_bfloat162(h2, h3);
    ((__nv_bfloat162*)lo)[2 * i]     = __nv_bfloat162(l0, l1);
    ((__nv_bfloat162*)lo)[2 * i + 1] = __nv_bfloat162(l2, l3);
}

// ---------------------------------------------------------------------------
// Split-bf16 mma.sync GEMM: C[m][e] = sum_d A[m][d] * B[e][d]
// CTA 128x128, 8 warps (warp tile 64x32), K slabs of 64, cp.async double buf.
// smem per buffer: Ahi/Alo/Bhi/Blo each [128][72] bf16 (stride pad ->
// conflict-free STS + ldmatrix).
// is_out==0: A=x(hi/lo), B=W[z], scatter into g_q/g_k/g_v head-major
// is_out==1: A=ctx(hi/lo), B=Wo, out = C + bo
// ---------------------------------------------------------------------------
constexpr int LDS_STRIDE = 72;                       // bf16 elements
constexpr int ARR = 128 * LDS_STRIDE * 2;            // 18432 B per array
constexpr int STAGE = 4 * ARR;                       // 73728 B per buffer
constexpr int GEMM_SMEM = 2 * STAGE;                 // 147456 B

__global__ __launch_bounds__(256, 1)
void gemm_mma(int is_out, const float* __restrict__ bo, float* __restrict__ outp)
{
    extern __shared__ char smc[];
    const uint32_t sbase = smem_u32(smc);

    const int tid  = threadIdx.x;
    const int wid  = tid >> 5;
    const int lane = tid & 31;
    const int wy   = wid >> 2;        // 0..1 -> m offset wy*64
    const int wx   = wid & 3;         // 0..3 -> n offset wx*32

    const int m0 = blockIdx.y * 128;
    const int e0 = blockIdx.x * 128;
    const int z  = blockIdx.z;

    const __nv_bfloat16* Ahi = is_out ? g_chi : g_xhi;
    const __nv_bfloat16* Alo = is_out ? g_clo : g_xlo;
    const int wsel = is_out ? 3 : z;
    const __nv_bfloat16* Bhi = g_whi + (size_t)wsel * DMODEL * DMODEL;
    const __nv_bfloat16* Blo = g_wlo + (size_t)wsel * DMODEL * DMODEL;

    // staging mapping: thread -> (row, 32-col half), 4 x 16B per array
    const int srow = tid >> 1;
    const int scol = (tid & 1) * 32;

    auto stage = [&](int c, int buf) {
        const int k0 = c << 6;
        const uint32_t b = sbase + buf * STAGE;
        const uint32_t soff = (uint32_t)(srow * LDS_STRIDE + scol) * 2;
        const __nv_bfloat16* gAh = Ahi + (size_t)(m0 + srow) * DMODEL + k0 + scol;
        const __nv_bfloat16* gAl = Alo + (size_t)(m0 + srow) * DMODEL + k0 + scol;
        const __nv_bfloat16* gBh = Bhi + (size_t)(e0 + srow) * DMODEL + k0 + scol;
        const __nv_bfloat16* gBl = Blo + (size_t)(e0 + srow) * DMODEL + k0 + scol;
        #pragma unroll
        for (int i = 0; i < 4; i++) {
            cp_async16(b + 0 * ARR + soff + i * 16, gAh + i * 8);
            cp_async16(b + 1 * ARR + soff + i * 16, gAl + i * 8);
            cp_async16(b + 2 * ARR + soff + i * 16, gBh + i * 8);
            cp_async16(b + 3 * ARR + soff + i * 16, gBl + i * 8);
        }
    };

    // ldmatrix per-lane address components
    const int arow  = (lane & 7) + ((lane >> 3) & 1) * 8;  // A: row within 16
    const int akoff = (lane >> 4) * 8;                     // A: k half
    const int brow  = lane & 7;                            // B: row within 8
    const int bkoff = ((lane >> 3) & 1) * 8;               // B: k half

    float acc[4][4][4] = {};

    stage(0, 0);
    CP_COMMIT();

    for (int c = 0; c < 16; c++) {
        if (c + 1 < 16) {
            stage(c + 1, (c + 1) & 1);
            CP_COMMIT();
            CP_WAIT(1);
        } else {
            CP_WAIT(0);
        }
        __syncthreads();

        const uint32_t b    = sbase + (c & 1) * STAGE;
        const uint32_t aHiB = b + 0 * ARR;
        const uint32_t aLoB = b + 1 * ARR;
        const uint32_t bHiB = b + 2 * ARR;
        const uint32_t bLoB = b + 3 * ARR;

        #pragma unroll
        for (int ks = 0; ks < 4; ks++) {
            const int k0 = ks * 16;
            uint32_t bh[4][2], bl[4][2];
            #pragma unroll
            for (int fn = 0; fn < 4; fn++) {
                const uint32_t off =
                    (uint32_t)((wx * 32 + fn * 8 + brow) * LDS_STRIDE + k0 + bkoff) * 2;
                ldsm_x2(bh[fn], bHiB + off);
                ldsm_x2(bl[fn], bLoB + off);
            }
            #pragma unroll
            for (int fm = 0; fm < 4; fm++) {
                const uint32_t off =
                    (uint32_t)((wy * 64 + fm * 16 + arow) * LDS_STRIDE + k0 + akoff) * 2;
                uint32_t ah[4], al[4];
                ldsm_x4(ah, aHiB + off);
                ldsm_x4(al, aLoB + off);
                #pragma unroll
                for (int fn = 0; fn < 4; fn++) {
                    mma_bf16(acc[fm][fn], ah, bh[fn]);
                    mma_bf16(acc[fm][fn], al, bh[fn]);
                    mma_bf16(acc[fm][fn], ah, bl[fn]);
                }
            }
        }
        __syncthreads();
    }

    // Epilogue: direct STG from D fragments.
    const int r0 = lane >> 2;
    const int c0 = (lane & 3) * 2;
    #pragma unroll
    for (int fm = 0; fm < 4; fm++)
        #pragma unroll
        for (int fn = 0; fn < 4; fn++) {
            const int m = m0 + wy * 64 + fm * 16 + r0;
            const int e = e0 + wx * 32 + fn * 8 + c0;
            if (is_out) {
                const float b0v = bo[e], b1v = bo[e + 1];
                float2 v0 = make_float2(acc[fm][fn][0] + b0v, acc[fm][fn][1] + b1v);
                float2 v1 = make_float2(acc[fm][fn][2] + b0v, acc[fm][fn][3] + b1v);
                *(float2*)&outp[(size_t)m * DMODEL + e]       = v0;
                *(float2*)&outp[(size_t)(m + 8) * DMODEL + e] = v1;
            } else {
                float* dst = (z == 0) ? g_q : (z == 1) ? g_k : g_v;
                const int h = e >> 6, dh = e & 63;
                const int bi = m >> 11, n = m & (SEQ - 1);
                float2 v0 = make_float2(acc[fm][fn][0], acc[fm][fn][1]);
                float2 v1 = make_float2(acc[fm][fn][2], acc[fm][fn][3]);
                *(float2*)&dst[(((size_t)bi * HEADS + h) * SEQ + n) * DHEAD + dh] = v0;
                *(float2*)&dst[(((size_t)bi * HEADS + h) * SEQ + n + 8) * DHEAD + dh] = v1;
            }
        }
}

// ---------------------------------------------------------------------------
// Causal flash attention (fp32 CUDA-core, same as round 2): 128q x 64k tiles.
// ---------------------------------------------------------------------------
constexpr int QS = 132;
constexpr int KS = 68;
constexpr int ATTN_SMEM = 64 * (QS + KS + KS + QS) * (int)sizeof(float);

__global__ __launch_bounds__(256, 2) void attn_kernel()
{
    extern __shared__ float sm[];
    float (*Qt)[QS] = (float(*)[QS])(sm);
    float (*Kt)[KS] = (float(*)[KS])(sm + 64 * QS);
    float (*Vs)[KS] = (float(*)[KS])(sm + 64 * QS + 64 * KS);
    float (*Pt)[QS] = (float(*)[QS])(sm + 64 * QS + 2 * 64 * KS);

    const int qb = blockIdx.x;
    const int h  = blockIdx.y;
    const int bb = blockIdx.z;

    const size_t hoff = ((size_t)bb * HEADS + h) * SEQ * DHEAD;
    const float* Qg = g_q + hoff;
    const float* Kg = g_k + hoff;
    const float* Vg = g_v + hoff;

    const int tid = threadIdx.x;
    const int tx  = tid & 15;
    const int ty  = tid >> 4;

    #pragma unroll
    for (int p = 0; p < 8; p++) {
        int f = p * 256 + tid;
        int r = f >> 4;
        int c = (f & 15) << 2;
        float4 v = *(const float4*)(Qg + (size_t)(qb * 128 + r) * DHEAD + c);
        Qt[c + 0][r] = v.x; Qt[c + 1][r] = v.y;
        Qt[c + 2][r] = v.z; Qt[c + 3][r] = v.w;
    }

    float m_i[2][4], l_i[2][4], o[2][4][4];
    #pragma unroll
    for (int ri = 0; ri < 2; ri++)
        #pragma unroll
        for (int i = 0; i < 4; i++) {
            m_i[ri][i] = -INFINITY; l_i[ri][i] = 0.f;
            #pragma unroll
            for (int j = 0; j < 4; j++) o[ri][i][j] = 0.f;
        }

    const int ktmax = 2 * qb + 1;
    for (int kt = 0; kt <= ktmax; kt++) {
        __syncthreads();
        #pragma unroll
        for (int p = 0; p < 4; p++) {
            int f = p * 256 + tid;
            int r = f >> 4;
            int c = (f & 15) << 2;
            float4 kv = *(const float4*)(Kg + (size_t)(kt * 64 + r) * DHEAD + c);
            Kt[c + 0][r] = kv.x; Kt[c + 1][r] = kv.y;
            Kt[c + 2][r] = kv.z; Kt[c + 3][r] = kv.w;
            float4 vv = *(const float4*)(Vg + (size_t)(kt * 64 + r) * DHEAD + c);
            *(float4*)&Vs[r][c] = vv;
        }
        __syncthreads();

        float s[2][4][4] = {};
        #pragma unroll 8
        for (int d = 0; d < 64; d++) {
            float4 a0 = *(const float4*)&Qt[d][ty * 4];
            float4 a1 = *(const float4*)&Qt[d][ty * 4 + 64];
            float4 b  = *(const float4*)&Kt[d][tx * 4];
            const float a[2][4] = {{a0.x, a0.y, a0.z, a0.w},
                                   {a1.x, a1.y, a1.z, a1.w}};
            const float bv[4] = {b.x, b.y, b.z, b.w};
            #pragma unroll
            for (int ri = 0; ri < 2; ri++)
                #pragma unroll
                for (int i = 0; i < 4; i++)
                    #pragma unroll
                    for (int j = 0; j < 4; j++)
                        s[ri][i][j] += a[ri][i] * bv[j];
        }

        const bool need_mask = (kt >= 2 * qb);

        #pragma unroll
        for (int ri = 0; ri < 2; ri++)
            #pragma unroll
            for (int i = 0; i < 4; i++) {
                const int qglob = qb * 128 + ri * 64 + ty * 4 + i;
                float mx = -INFINITY;
                #pragma unroll
                for (int j = 0; j < 4; j++) {
                    float v = s[ri][i][j] * SCALE;
                    if (need_mask && (kt * 64 + tx * 4 + j) > qglob) v = -INFINITY;
                    s[ri][i][j] = v;
                    mx = fmaxf(mx, v);
                }
                #pragma unroll
                for (int off = 8; off > 0; off >>= 1)
                    mx = fmaxf(mx, __shfl_xor_sync(0xffffffffu, mx, off));

                float mnew  = fmaxf(m_i[ri][i], mx);
                float alpha = __expf(m_i[ri][i] - mnew);
                float rsum  = 0.f;
                #pragma unroll
                for (int j = 0; j < 4; j++) {
                    float pj = __expf(s[ri][i][j] - mnew);
                    s[ri][i][j] = pj;
                    rsum += pj;
                }
                #pragma unroll
                for (int off = 8; off > 0; off >>= 1)
                    rsum += __shfl_xor_sync(0xffffffffu, rsum, off);

                l_i[ri][i] = l_i[ri][i] * alpha + rsum;
                m_i[ri][i] = mnew;
                #pragma unroll
                for (int j = 0; j < 4; j++) o[ri][i][j] *= alpha;
            }

        #pragma unroll
        for (int ri = 0; ri < 2; ri++)
            #pragma unroll
            for (int i = 0; i < 4; i++)
                #pragma unroll
                for (int j = 0; j < 4; j++)
                    Pt[tx * 4 + j][ri * 64 + ty * 4 + i] = s[ri][i][j];
        __syncthreads();

        #pragma unroll 8
        for (int k = 0; k < 64; k++) {
            float4 a0 = *(const float4*)&Pt[k][ty * 4];
            float4 a1 = *(const float4*)&Pt[k][ty * 4 + 64];
            float4 b  = *(const float4*)&Vs[k][tx * 4];
            const float a[2][4] = {{a0.x, a0.y, a0.z, a0.w},
                                   {a1.x, a1.y, a1.z, a1.w}};
            const float bv[4] = {b.x, b.y, b.z, b.w};
            #pragma unroll
            for (int ri = 0; ri < 2; ri++)
                #pragma unroll
                for (int i = 0; i < 4; i++)
                    #pragma unroll
                    for (int j = 0; j < 4; j++)
                        o[ri][i][j] += a[ri][i] * bv[j];
        }
    }

    #pragma unroll
    for (int ri = 0; ri < 2; ri++)
        #pragma unroll
        for (int i = 0; i < 4; i++) {
            float inv = 1.f / l_i[ri][i];
            int q = qb * 128 + ri * 64 + ty * 4 + i;
            float4 st = make_float4(o[ri][i][0] * inv, o[ri][i][1] * inv,
                                    o[ri][i][2] * inv, o[ri][i][3] * inv);
            *(float4*)&g_ctx[(((size_t)bb * SEQ + q) * HEADS + h) * DHEAD + tx * 4] = st;
        }
}

// ---------------------------------------------------------------------------
extern "C" void kernel_launch(void* const* d_in, const int* in_sizes, int n_in,
                              void* d_out, int out_size)
{
    (void)in_sizes; (void)n_in; (void)out_size;
    const float* x  = (const float*)d_in[0];
    const float* Wq = (const float*)d_in[1];
    const float* Wk = (const float*)d_in[2];
    const float* Wv = (const float*)d_in[3];
    const float* Wo = (const float*)d_in[4];
    const float* bo = (const float*)d_in[5];
    float* out = (float*)d_out;

    cudaFuncSetAttribute(attn_kernel, cudaFuncAttributeMaxDynamicSharedMemorySize,
                         ATTN_SMEM);
    cudaFuncSetAttribute(gemm_mma, cudaFuncAttributeMaxDynamicSharedMemorySize,
                         GEMM_SMEM);

    __nv_bfloat16 *xhi, *xlo, *whi, *wlo, *chi, *clo;
    cudaGetSymbolAddress((void**)&xhi, g_xhi);
    cudaGetSymbolAddress((void**)&xlo, g_xlo);
    cudaGetSymbolAddress((void**)&whi, g_whi);
    cudaGetSymbolAddress((void**)&wlo, g_wlo);
    cudaGetSymbolAddress((void**)&chi, g_chi);
    cudaGetSymbolAddress((void**)&clo, g_clo);
    float* ctx;
    cudaGetSymbolAddress((void**)&ctx, g_ctx);

    const int NX4 = MTOT * DMODEL / 4;      // 1048576
    const int NW4 = DMODEL * DMODEL / 4;    // 262144

    precvt<<<NX4 / 256, 256>>>(x, xhi, xlo, NX4);
    precvt<<<NW4 / 256, 256>>>(Wq, whi + 0 * (size_t)DMODEL * DMODEL,
                               wlo + 0 * (size_t)DMODEL * DMODEL, NW4);
    precvt<<<NW4 / 256, 256>>>(Wk, whi + 1 * (size_t)DMODEL * DMODEL,
                               wlo + 1 * (size_t)DMODEL * DMODEL, NW4);
    precvt<<<NW4 / 256, 256>>>(Wv, whi + 2 * (size_t)DMODEL * DMODEL,
                               wlo + 2 * (size_t)DMODEL * DMODEL, NW4);
    precvt<<<NW4 / 256, 256>>>(Wo, whi + 3 * (size_t)DMODEL * DMODEL,
                               wlo + 3 * (size_t)DMODEL * DMODEL, NW4);

    // QKV projections on tensor cores (mma.sync): grid (E/128, M/128, 3)
    gemm_mma<<<dim3(DMODEL / 128, MTOT / 128, 3), 256, GEMM_SMEM>>>(0, nullptr, nullptr);

    // Attention (fp32 CUDA-core)
    attn_kernel<<<dim3(SEQ / 128, HEADS, BATCH), 256, ATTN_SMEM>>>();

    // ctx -> bf16 hi/lo, then output projection on tensor cores
    precvt<<<NX4 / 256, 256>>>(ctx, chi, clo, NX4);
    gemm_mma<<<dim3(DMODEL / 128, MTOT / 128, 1), 256, GEMM_SMEM>>>(1, bo, out);
}

// round 5
// speedup vs baseline: 2.7793x; 1.6142x over previous
#include <cuda_runtime.h>
#include <cuda_bf16.h>
#include <math.h>
#include <stdint.h>

// Problem constants
constexpr int BATCH = 2;
constexpr int SEQ   = 2048;
constexpr int DMODEL= 1024;
constexpr int HEADS = 16;
constexpr int DHEAD = 64;
constexpr int MTOT  = BATCH * SEQ;           // 4096
constexpr float SCALE = 0.0220970869120796f; // 1/sqrt(2048)

// Scratch (allocation-free rule: __device__ globals). All bf16 hi/lo split.
__device__ __nv_bfloat16 g_xhi[MTOT * DMODEL];
__device__ __nv_bfloat16 g_xlo[MTOT * DMODEL];
__device__ __nv_bfloat16 g_whi[4 * DMODEL * DMODEL];
__device__ __nv_bfloat16 g_wlo[4 * DMODEL * DMODEL];
__device__ __nv_bfloat16 g_qhi[BATCH * HEADS * SEQ * DHEAD];
__device__ __nv_bfloat16 g_qlo[BATCH * HEADS * SEQ * DHEAD];
__device__ __nv_bfloat16 g_khi[BATCH * HEADS * SEQ * DHEAD];
__device__ __nv_bfloat16 g_klo[BATCH * HEADS * SEQ * DHEAD];
__device__ __nv_bfloat16 g_vhi[BATCH * HEADS * SEQ * DHEAD];
__device__ __nv_bfloat16 g_vlo[BATCH * HEADS * SEQ * DHEAD];
__device__ __nv_bfloat16 g_chi[MTOT * DMODEL];
__device__ __nv_bfloat16 g_clo[MTOT * DMODEL];

// ---------------------------------------------------------------------------
// Portable tensor-core helpers (sm_80+ ISA, works on plain sm_103 target)
// ---------------------------------------------------------------------------
__device__ __forceinline__ uint32_t smem_u32(const void* p) {
    uint32_t a;
    asm("{ .reg .u64 t; cvta.to.shared.u64 t, %1; cvt.u32.u64 %0, t; }"
        : "=r"(a) : "l"(p));
    return a;
}
__device__ __forceinline__ void ldsm_x4(uint32_t r[4], uint32_t a) {
    asm volatile("ldmatrix.sync.aligned.m8n8.x4.shared.b16 {%0,%1,%2,%3}, [%4];"
                 : "=r"(r[0]), "=r"(r[1]), "=r"(r[2]), "=r"(r[3]) : "r"(a));
}
__device__ __forceinline__ void ldsm_x2(uint32_t r[2], uint32_t a) {
    asm volatile("ldmatrix.sync.aligned.m8n8.x2.shared.b16 {%0,%1}, [%2];"
                 : "=r"(r[0]), "=r"(r[1]) : "r"(a));
}
__device__ __forceinline__ void ldsm_x2t(uint32_t r[2], uint32_t a) {
    asm volatile("ldmatrix.sync.aligned.m8n8.x2.trans.shared.b16 {%0,%1}, [%2];"
                 : "=r"(r[0]), "=r"(r[1]) : "r"(a));
}
__device__ __forceinline__ void mma_bf16(float d[4], const uint32_t a[4],
                                         const uint32_t b[2]) {
    asm volatile(
        "mma.sync.aligned.m16n8k16.row.col.f32.bf16.bf16.f32 "
        "{%0,%1,%2,%3}, {%4,%5,%6,%7}, {%8,%9}, {%0,%1,%2,%3};"
        : "+f"(d[0]), "+f"(d[1]), "+f"(d[2]), "+f"(d[3])
        : "r"(a[0]), "r"(a[1]), "r"(a[2]), "r"(a[3]), "r"(b[0]), "r"(b[1]));
}
__device__ __forceinline__ void cp_async16(uint32_t dst, const void* src) {
    asm volatile("cp.async.cg.shared.global [%0], [%1], 16;"
                 :: "r"(dst), "l"(src) : "memory");
}
#define CP_COMMIT() asm volatile("cp.async.commit_group;" ::: "memory")
#define CP_WAIT(n)  asm volatile("cp.async.wait_group %0;" :: "n"(n) : "memory")

__device__ __forceinline__ uint32_t pack_bf2(float a, float b) {
    __nv_bfloat162 t(__float2bfloat16(a), __float2bfloat16(b));
    return *(uint32_t*)&t;
}
__device__ __forceinline__ void split_store(__nv_bfloat16* hi, __nv_bfloat16* lo,
                                            size_t idx, float a, float b) {
    __nv_bfloat16 h0 = __float2bfloat16(a), h1 = __float2bfloat16(b);
    __nv_bfloat162 hv(h0, h1);
    __nv_bfloat162 lv(__float2bfloat16(a - __bfloat162float(h0)),
                      __float2bfloat16(b - __bfloat162float(h1)));
    *(__nv_bfloat162*)&hi[idx] = hv;
    *(__nv_bfloat162*)&lo[idx] = lv;
}

// ---------------------------------------------------------------------------
// fp32 -> bf16 hi/lo split (x / ctx / weights)
// ---------------------------------------------------------------------------
__global__ __launch_bounds__(256) void precvt(const float* __restrict__ src,
                                              __nv_bfloat16* __restrict__ hi,
                                              __nv_bfloat16* __restrict__ lo,
                                              int n4)
{
    int i = blockIdx.x * 256 + threadIdx.x;
    if (i >= n4) return;
    float4 v = ((const float4*)src)[i];
    __nv_bfloat16 h0 = __float2bfloat16(v.x);
    __nv_bfloat16 h1 = __float2bfloat16(v.y);
    __nv_bfloat16 h2 = __float2bfloat16(v.z);
    __nv_bfloat16 h3 = __float2bfloat16(v.w);
    ((__nv_bfloat162*)hi)[2 * i]     = __nv_bfloat162(h0, h1);
    ((__nv_bfloat162*)hi)[2 * i + 1] = __nv_bfloat162(h2, h3);
    ((__nv_bfloat162*)lo)[2 * i] =
        __nv_bfloat162(__float2bfloat16(v.x - __bfloat162float(h0)),
                       __float2bfloat16(v.y - __bfloat162float(h1)));
    ((__nv_bfloat162*)lo)[2 * i + 1] =
        __nv_bfloat162(__float2bfloat16(v.z - __bfloat162float(h2)),
                       __float2bfloat16(v.w - __bfloat162float(h3)));
}

__global__ __launch_bounds__(256) void precvt_w(const float* __restrict__ w0,
                                                const float* __restrict__ w1,
                                                const float* __restrict__ w2,
                                                const float* __restrict__ w3,
                                                int n4)
{
    const int z = blockIdx.y;
    const float* src = (z == 0) ? w0 : (z == 1) ? w1 : (z == 2) ? w2 : w3;
    __nv_bfloat16* hi = g_whi + (size_t)z * DMODEL * DMODEL;
    __nv_bfloat16* lo = g_wlo + (size_t)z * DMODEL * DMODEL;
    int i = blockIdx.x * 256 + threadIdx.x;
    if (i >= n4) return;
    float4 v = ((const float4*)src)[i];
    __nv_bfloat16 h0 = __float2bfloat16(v.x);
    __nv_bfloat16 h1 = __float2bfloat16(v.y);
    __nv_bfloat16 h2 = __float2bfloat16(v.z);
    __nv_bfloat16 h3 = __float2bfloat16(v.w);
    ((__nv_bfloat162*)hi)[2 * i]     = __nv_bfloat162(h0, h1);
    ((__nv_bfloat162*)hi)[2 * i + 1] = __nv_bfloat162(h2, h3);
    ((__nv_bfloat162*)lo)[2 * i] =
        __nv_bfloat162(__float2bfloat16(v.x - __bfloat162float(h0)),
                       __float2bfloat16(v.y - __bfloat162float(h1)));
    ((__nv_bfloat162*)lo)[2 * i + 1] =
        __nv_bfloat162(__float2bfloat16(v.z - __bfloat162float(h2)),
                       __float2bfloat16(v.w - __bfloat162float(h3)));
}

// ---------------------------------------------------------------------------
// Split-bf16 mma.sync GEMM (as round 4). is_out==0 -> write q/k/v hi/lo bf16;
// is_out==1 -> fp32 out + bias.
// ---------------------------------------------------------------------------
constexpr int LDS_STRIDE = 72;
constexpr int ARR = 128 * LDS_STRIDE * 2;            // 18432 B
constexpr int STAGE = 4 * ARR;                       // 73728 B
constexpr int GEMM_SMEM = 2 * STAGE;                 // 147456 B

__global__ __launch_bounds__(256, 1)
void gemm_mma(int is_out, const float* __restrict__ bo, float* __restrict__ outp)
{
    extern __shared__ char smc[];
    const uint32_t sbase = smem_u32(smc);

    const int tid  = threadIdx.x;
    const int wid  = tid >> 5;
    const int lane = tid & 31;
    const int wy   = wid >> 2;
    const int wx   = wid & 3;

    const int m0 = blockIdx.y * 128;
    const int e0 = blockIdx.x * 128;
    const int z  = blockIdx.z;

    const __nv_bfloat16* Ahi = is_out ? g_chi : g_xhi;
    const __nv_bfloat16* Alo = is_out ? g_clo : g_xlo;
    const int wsel = is_out ? 3 : z;
    const __nv_bfloat16* Bhi = g_whi + (size_t)wsel * DMODEL * DMODEL;
    const __nv_bfloat16* Blo = g_wlo + (size_t)wsel * DMODEL * DMODEL;

    const int srow = tid >> 1;
    const int scol = (tid & 1) * 32;

    auto stage = [&](int c, int buf) {
        const int k0 = c << 6;
        const uint32_t b = sbase + buf * STAGE;
        const uint32_t soff = (uint32_t)(srow * LDS_STRIDE + scol) * 2;
        const __nv_bfloat16* gAh = Ahi + (size_t)(m0 + srow) * DMODEL + k0 + scol;
        const __nv_bfloat16* gAl = Alo + (size_t)(m0 + srow) * DMODEL + k0 + scol;
        const __nv_bfloat16* gBh = Bhi + (size_t)(e0 + srow) * DMODEL + k0 + scol;
        const __nv_bfloat16* gBl = Blo + (size_t)(e0 + srow) * DMODEL + k0 + scol;
        #pragma unroll
        for (int i = 0; i < 4; i++) {
            cp_async16(b + 0 * ARR + soff + i * 16, gAh + i * 8);
            cp_async16(b + 1 * ARR + soff + i * 16, gAl + i * 8);
            cp_async16(b + 2 * ARR + soff + i * 16, gBh + i * 8);
            cp_async16(b + 3 * ARR + soff + i * 16, gBl + i * 8);
        }
    };

    const int arow  = (lane & 7) + ((lane >> 3) & 1) * 8;
    const int akoff = (lane >> 4) * 8;
    const int brow  = lane & 7;
    const int bkoff = ((lane >> 3) & 1) * 8;

    float acc[4][4][4] = {};

    stage(0, 0);
    CP_COMMIT();

    for (int c = 0; c < 16; c++) {
        if (c + 1 < 16) {
            stage(c + 1, (c + 1) & 1);
            CP_COMMIT();
            CP_WAIT(1);
        } else {
            CP_WAIT(0);
        }
        __syncthreads();

        const uint32_t b    = sbase + (c & 1) * STAGE;
        const uint32_t aHiB = b + 0 * ARR;
        const uint32_t aLoB = b + 1 * ARR;
        const uint32_t bHiB = b + 2 * ARR;
        const uint32_t bLoB = b + 3 * ARR;

        #pragma unroll
        for (int ks = 0; ks < 4; ks++) {
            const int k0 = ks * 16;
            uint32_t bh[4][2], bl[4][2];
            #pragma unroll
            for (int fn = 0; fn < 4; fn++) {
                const uint32_t off =
                    (uint32_t)((wx * 32 + fn * 8 + brow) * LDS_STRIDE + k0 + bkoff) * 2;
                ldsm_x2(bh[fn], bHiB + off);
                ldsm_x2(bl[fn], bLoB + off);
            }
            #pragma unroll
            for (int fm = 0; fm < 4; fm++) {
                const uint32_t off =
                    (uint32_t)((wy * 64 + fm * 16 + arow) * LDS_STRIDE + k0 + akoff) * 2;
                uint32_t ah[4], al[4];
                ldsm_x4(ah, aHiB + off);
                ldsm_x4(al, aLoB + off);
                #pragma unroll
                for (int fn = 0; fn < 4; fn++) {
                    mma_bf16(acc[fm][fn], ah, bh[fn]);
                    mma_bf16(acc[fm][fn], al, bh[fn]);
                    mma_bf16(acc[fm][fn], ah, bl[fn]);
                }
            }
        }
        __syncthreads();
    }

    const int r0 = lane >> 2;
    const int c0 = (lane & 3) * 2;
    #pragma unroll
    for (int fm = 0; fm < 4; fm++)
        #pragma unroll
        for (int fn = 0; fn < 4; fn++) {
            const int m = m0 + wy * 64 + fm * 16 + r0;
            const int e = e0 + wx * 32 + fn * 8 + c0;
            if (is_out) {
                const float b0v = bo[e], b1v = bo[e + 1];
                float2 v0 = make_float2(acc[fm][fn][0] + b0v, acc[fm][fn][1] + b1v);
                float2 v1 = make_float2(acc[fm][fn][2] + b0v, acc[fm][fn][3] + b1v);
                *(float2*)&outp[(size_t)m * DMODEL + e]       = v0;
                *(float2*)&outp[(size_t)(m + 8) * DMODEL + e] = v1;
            } else {
                __nv_bfloat16* dhi = (z == 0) ? g_qhi : (z == 1) ? g_khi : g_vhi;
                __nv_bfloat16* dlo = (z == 0) ? g_qlo : (z == 1) ? g_klo : g_vlo;
                const int h = e >> 6, dh = e & 63;
                const int bi = m >> 11, n = m & (SEQ - 1);
                size_t i0 = (((size_t)bi * HEADS + h) * SEQ + n) * DHEAD + dh;
                size_t i1 = (((size_t)bi * HEADS + h) * SEQ + n + 8) * DHEAD + dh;
                split_store(dhi, dlo, i0, acc[fm][fn][0], acc[fm][fn][1]);
                split_store(dhi, dlo, i1, acc[fm][fn][2], acc[fm][fn][3]);
            }
        }
}

// ---------------------------------------------------------------------------
// FlashAttention-2 with mma.sync split-bf16.
// CTA = 128 queries (8 warps; warp owns 16 rows). K/V tiles of 64 keys,
// cp.async double-buffered. Softmax in registers; P reused from S acc frags.
// ---------------------------------------------------------------------------
constexpr int QSTR = 72;                       // bf16 elems per row
constexpr int ATT_Q   = 128 * QSTR * 2;        // 18432 B per Q array
constexpr int ATT_KV1 = 64 * QSTR * 2;         // 9216 B per K/V array
constexpr int ATT_BUF = 4 * ATT_KV1;           // 36864 B per buffer
constexpr int ATTN_SMEM = 2 * ATT_Q + 2 * ATT_BUF;  // 110592 B

__global__ __launch_bounds__(256, 1) void attn_mma()
{
    extern __shared__ char smc[];
    const uint32_t sb  = smem_u32(smc);
    const uint32_t qhB = sb;
    const uint32_t qlB = sb + ATT_Q;

    const int tid  = threadIdx.x;
    const int wid  = tid >> 5;
    const int lane = tid & 31;
    const int qb = blockIdx.x;
    const int h  = blockIdx.y;
    const int bb = blockIdx.z;

    const size_t hoff = ((size_t)bb * HEADS + h) * SEQ * DHEAD;
    const __nv_bfloat16* Qh = g_qhi + hoff + (size_t)qb * 128 * DHEAD;
    const __nv_bfloat16* Ql = g_qlo + hoff + (size_t)qb * 128 * DHEAD;
    const __nv_bfloat16* Kh = g_khi + hoff;
    const __nv_bfloat16* Kl = g_klo + hoff;
    const __nv_bfloat16* Vh = g_vhi + hoff;
    const __nv_bfloat16* Vl = g_vlo + hoff;

    auto stage_kv = [&](int kt, int buf) {
        const uint32_t base = sb + 2 * ATT_Q + buf * ATT_BUF;
        const size_t goff = (size_t)kt * 64 * DHEAD;
        #pragma unroll
        for (int i = 0; i < 2; i++) {
            int c = i * 256 + tid;
            int r = c >> 3, col = (c & 7) * 8;
            uint32_t so = (uint32_t)(r * QSTR + col) * 2;
            size_t go = goff + (size_t)r * DHEAD + col;
            cp_async16(base + 0 * ATT_KV1 + so, Kh + go);
            cp_async16(base + 1 * ATT_KV1 + so, Kl + go);
            cp_async16(base + 2 * ATT_KV1 + so, Vh + go);
            cp_async16(base + 3 * ATT_KV1 + so, Vl + go);
        }
    };

    // stage Q + first KV tile
    #pragma unroll
    for (int i = 0; i < 4; i++) {
        int c = i * 256 + tid;
        int r = c >> 3, col = (c & 7) * 8;
        uint32_t so = (uint32_t)(r * QSTR + col) * 2;
        cp_async16(qhB + so, Qh + (size_t)r * DHEAD + col);
        cp_async16(qlB + so, Ql + (size_t)r * DHEAD + col);
    }
    stage_kv(0, 0);
    CP_COMMIT();
    CP_WAIT(0);
    __syncthreads();

    // preload Q fragments (reused across all key tiles)
    const int arow  = (lane & 7) + ((lane >> 3) & 1) * 8;
    const int akoff = (lane >> 4) * 8;
    uint32_t qfh[4][4], qfl[4][4];
    #pragma unroll
    for (int ks = 0; ks < 4; ks++) {
        uint32_t off = (uint32_t)((wid * 16 + arow) * QSTR + ks * 16 + akoff) * 2;
        ldsm_x4(qfh[ks], qhB + off);
        ldsm_x4(qfl[ks], qlB + off);
    }

    const int g  = lane >> 2;
    const int tg = lane & 3;
    const int rowbase = qb * 128 + wid * 16;
    const int brow = lane & 7;
    const int bk8  = ((lane >> 3) & 1) * 8;
    const int vrowl = (lane & 7) + ((lane >> 3) & 1) * 8;

    float o[8][4] = {};
    float mrow0 = -INFINITY, mrow1 = -INFINITY;
    float lrow0 = 0.f, lrow1 = 0.f;

    const int ktmax = 2 * qb + 1;
    for (int kt = 0; kt <= ktmax; kt++) {
        __syncthreads();  // all warps done reading buffer (kt+1)&1 from kt-1
        if (kt < ktmax) {
            stage_kv(kt + 1, (kt + 1) & 1);
            CP_COMMIT();
            CP_WAIT(1);
        } else {
            CP_WAIT(0);
        }
        __syncthreads();

        const uint32_t kB = sb + 2 * ATT_Q + (kt & 1) * ATT_BUF;

        // S = Q @ K^T (3-term split)
        float s[8][4] = {};
        #pragma unroll
        for (int fn = 0; fn < 8; fn++) {
            #pragma unroll
            for (int ks = 0; ks < 4; ks++) {
                uint32_t off = (uint32_t)((fn * 8 + brow) * QSTR + ks * 16 + bk8) * 2;
                uint32_t bh[2], bl[2];
                ldsm_x2(bh, kB + off);
                ldsm_x2(bl, kB + ATT_KV1 + off);
                mma_bf16(s[fn], qfh[ks], bh);
                mma_bf16(s[fn], qfl[ks], bh);
                mma_bf16(s[fn], qfh[ks], bl);
            }
        }

        // scale + causal mask
        const bool needmask = (kt * 64 + 63 > rowbase);
        const int r0g = rowbase + g, r1g = r0g + 8;
        #pragma unroll
        for (int fn = 0; fn < 8; fn++) {
            const int cbase = kt * 64 + fn * 8 + tg * 2;
            float v0 = s[fn][0] * SCALE, v1 = s[fn][1] * SCALE;
            float v2 = s[fn][2] * SCALE, v3 = s[fn][3] * SCALE;
            if (needmask) {
                if (cbase     > r0g) v0 = -INFINITY;
                if (cbase + 1 > r0g) v1 = -INFINITY;
                if (cbase     > r1g) v2 = -INFINITY;
                if (cbase + 1 > r1g) v3 = -INFINITY;
            }
            s[fn][0] = v0; s[fn][1] = v1; s[fn][2] = v2; s[fn][3] = v3;
        }

        // row max (quad reduce)
        float mx0 = -INFINITY, mx1 = -INFINITY;
        #pragma unroll
        for (int fn = 0; fn < 8; fn++) {
            mx0 = fmaxf(mx0, fmaxf(s[fn][0], s[fn][1]));
            mx1 = fmaxf(mx1, fmaxf(s[fn][2], s[fn][3]));
        }
        mx0 = fmaxf(mx0, __shfl_xor_sync(0xffffffffu, mx0, 1));
        mx0 = fmaxf(mx0, __shfl_xor_sync(0xffffffffu, mx0, 2));
        mx1 = fmaxf(mx1, __shfl_xor_sync(0xffffffffu, mx1, 1));
        mx1 = fmaxf(mx1, __shfl_xor_sync(0xffffffffu, mx1, 2));

        const float mn0 = fmaxf(mrow0, mx0);
        const float mn1 = fmaxf(mrow1, mx1);
        const float al0 = __expf(mrow0 - mn0);
        const float al1 = __expf(mrow1 - mn1);

        float rs0 = 0.f, rs1 = 0.f;
        #pragma unroll
        for (int fn = 0; fn < 8; fn++) {
            float p0 = __expf(s[fn][0] - mn0);
            float p1 = __expf(s[fn][1] - mn0);
            float p2 = __expf(s[fn][2] - mn1);
            float p3 = __expf(s[fn][3] - mn1);
            s[fn][0] = p0; s[fn][1] = p1; s[fn][2] = p2; s[fn][3] = p3;
            rs0 += p0 + p1;
            rs1 += p2 + p3;
        }
        rs0 += __shfl_xor_sync(0xffffffffu, rs0, 1);
        rs0 += __shfl_xor_sync(0xffffffffu, rs0, 2);
        rs1 += __shfl_xor_sync(0xffffffffu, rs1, 1);
        rs1 += __shfl_xor_sync(0xffffffffu, rs1, 2);

        lrow0 = lrow0 * al0 + rs0;
        lrow1 = lrow1 * al1 + rs1;
        mrow0 = mn0; mrow1 = mn1;

        #pragma unroll
        for (int fn = 0; fn < 8; fn++) {
            o[fn][0] *= al0; o[fn][1] *= al0;
            o[fn][2] *= al1; o[fn][3] *= al1;
        }

        // O += P @ V  (P from S frags, V via ldmatrix.trans)
        const uint32_t vB = kB + 2 * ATT_KV1;
        #pragma unroll
        for (int kg = 0; kg < 4; kg++) {
            uint32_t ph[4], pl[4];
            #pragma unroll
            for (int half = 0; half < 2; half++) {
                const int f = 2 * kg + half;
                float a0 = s[f][0], a1 = s[f][1], a2 = s[f][2], a3 = s[f][3];
                __nv_bfloat16 h0 = __float2bfloat16(a0), h1 = __float2bfloat16(a1);
                __nv_bfloat16 h2 = __float2bfloat16(a2), h3 = __float2bfloat16(a3);
                __nv_bfloat162 t0(h0, h1), t1(h2, h3);
                ph[2 * half]     = *(uint32_t*)&t0;
                ph[2 * half + 1] = *(uint32_t*)&t1;
                __nv_bfloat162 u0(__float2bfloat16(a0 - __bfloat162float(h0)),
                                  __float2bfloat16(a1 - __bfloat162float(h1)));
                __nv_bfloat162 u1(__float2bfloat16(a2 - __bfloat162float(h2)),
                                  __float2bfloat16(a3 - __bfloat162float(h3)));
                pl[2 * half]     = *(uint32_t*)&u0;
                pl[2 * half + 1] = *(uint32_t*)&u1;
            }
            // fix operand order: ph[0..3] currently = {f0:(r,c),(r+8,c), f1:(r,c),(r+8,c)}
            // A layout wants {a0=f0(r), a1=f0(r+8), a2=f1(r), a3=f1(r+8)} -- already matches.
            const int vrow = kg * 16 + vrowl;
            #pragma unroll
            for (int fn = 0; fn < 8; fn++) {
                uint32_t off = (uint32_t)(vrow * QSTR + fn * 8) * 2;
                uint32_t vh2[2], vl2[2];
                ldsm_x2t(vh2, vB + off);
                ldsm_x2t(vl2, vB + ATT_KV1 + off);
                mma_bf16(o[fn], ph, vh2);
                mma_bf16(o[fn], pl, vh2);
                mma_bf16(o[fn], ph, vl2);
            }
        }
    }

    // epilogue: ctx = O / l, write bf16 hi/lo into chi/clo ([b][n][h*64+dh])
    const float inv0 = 1.f / lrow0;
    const float inv1 = 1.f / lrow1;
    const int q0 = rowbase + g;
    const int q1 = q0 + 8;
    #pragma unroll
    for (int fn = 0; fn < 8; fn++) {
        const int e = h * 64 + fn * 8 + tg * 2;
        size_t i0 = (size_t)(bb * SEQ + q0) * DMODEL + e;
        size_t i1 = (size_t)(bb * SEQ + q1) * DMODEL + e;
        split_store(g_chi, g_clo, i0, o[fn][0] * inv0, o[fn][1] * inv0);
        split_store(g_chi, g_clo, i1, o[fn][2] * inv1, o[fn][3] * inv1);
    }
}

// ---------------------------------------------------------------------------
extern "C" void kernel_launch(void* const* d_in, const int* in_sizes, int n_in,
                              void* d_out, int out_size)
{
    (void)in_sizes; (void)n_in; (void)out_size;
    const float* x  = (const float*)d_in[0];
    const float* Wq = (const float*)d_in[1];
    const float* Wk = (const float*)d_in[2];
    const float* Wv = (const float*)d_in[3];
    const float* Wo = (const float*)d_in[4];
    const float* bo = (const float*)d_in[5];
    float* out = (float*)d_out;

    cudaFuncSetAttribute(gemm_mma, cudaFuncAttributeMaxDynamicSharedMemorySize,
                         GEMM_SMEM);
    cudaFuncSetAttribute(attn_mma, cudaFuncAttributeMaxDynamicSharedMemorySize,
                         ATTN_SMEM);

    __nv_bfloat16 *xhi, *xlo;
    cudaGetSymbolAddress((void**)&xhi, g_xhi);
    cudaGetSymbolAddress((void**)&xlo, g_xlo);

    const int NX4 = MTOT * DMODEL / 4;
    const int NW4 = DMODEL * DMODEL / 4;

    precvt<<<NX4 / 256, 256>>>(x, xhi, xlo, NX4);
    precvt_w<<<dim3(NW4 / 256, 4), 256>>>(Wq, Wk, Wv, Wo, NW4);

    // QKV projections (writes q/k/v bf16 hi/lo head-major)
    gemm_mma<<<dim3(DMODEL / 128, MTOT / 128, 3), 256, GEMM_SMEM>>>(0, nullptr, nullptr);

    // attention (writes ctx bf16 hi/lo)
    attn_mma<<<dim3(SEQ / 128, HEADS, BATCH), 256, ATTN_SMEM>>>();

    // output projection
    gemm_mma<<<dim3(DMODEL / 128, MTOT / 128, 1), 256, GEMM_SMEM>>>(1, bo, out);
}

// round 6
// speedup vs baseline: 3.3653x; 1.2108x over previous
#include <cuda_runtime.h>
#include <cuda_bf16.h>
#include <math.h>
#include <stdint.h>

// Problem constants
constexpr int BATCH = 2;
constexpr int SEQ   = 2048;
constexpr int DMODEL= 1024;
constexpr int HEADS = 16;
constexpr int DHEAD = 64;
constexpr int MTOT  = BATCH * SEQ;           // 4096
constexpr float SCALE = 0.0220970869120796f; // 1/sqrt(2048)

// Scratch (allocation-free rule: __device__ globals). All bf16 hi/lo split.
__device__ __nv_bfloat16 g_xhi[MTOT * DMODEL];
__device__ __nv_bfloat16 g_xlo[MTOT * DMODEL];
__device__ __nv_bfloat16 g_whi[4 * DMODEL * DMODEL];
__device__ __nv_bfloat16 g_wlo[4 * DMODEL * DMODEL];
__device__ __nv_bfloat16 g_qhi[BATCH * HEADS * SEQ * DHEAD];
__device__ __nv_bfloat16 g_qlo[BATCH * HEADS * SEQ * DHEAD];
__device__ __nv_bfloat16 g_khi[BATCH * HEADS * SEQ * DHEAD];
__device__ __nv_bfloat16 g_klo[BATCH * HEADS * SEQ * DHEAD];
__device__ __nv_bfloat16 g_vhi[BATCH * HEADS * SEQ * DHEAD];
__device__ __nv_bfloat16 g_vlo[BATCH * HEADS * SEQ * DHEAD];
__device__ __nv_bfloat16 g_chi[MTOT * DMODEL];
__device__ __nv_bfloat16 g_clo[MTOT * DMODEL];

// ---------------------------------------------------------------------------
// Portable tensor-core helpers (sm_80+ ISA)
// ---------------------------------------------------------------------------
__device__ __forceinline__ uint32_t smem_u32(const void* p) {
    uint32_t a;
    asm("{ .reg .u64 t; cvta.to.shared.u64 t, %1; cvt.u32.u64 %0, t; }"
        : "=r"(a) : "l"(p));
    return a;
}
__device__ __forceinline__ void ldsm_x4(uint32_t r[4], uint32_t a) {
    asm volatile("ldmatrix.sync.aligned.m8n8.x4.shared.b16 {%0,%1,%2,%3}, [%4];"
                 : "=r"(r[0]), "=r"(r[1]), "=r"(r[2]), "=r"(r[3]) : "r"(a));
}
__device__ __forceinline__ void ldsm_x4t(uint32_t r[4], uint32_t a) {
    asm volatile("ldmatrix.sync.aligned.m8n8.x4.trans.shared.b16 {%0,%1,%2,%3}, [%4];"
                 : "=r"(r[0]), "=r"(r[1]), "=r"(r[2]), "=r"(r[3]) : "r"(a));
}
__device__ __forceinline__ void mma_bf16(float d[4], const uint32_t a[4],
                                         const uint32_t b[2]) {
    asm volatile(
        "mma.sync.aligned.m16n8k16.row.col.f32.bf16.bf16.f32 "
        "{%0,%1,%2,%3}, {%4,%5,%6,%7}, {%8,%9}, {%0,%1,%2,%3};"
        : "+f"(d[0]), "+f"(d[1]), "+f"(d[2]), "+f"(d[3])
        : "r"(a[0]), "r"(a[1]), "r"(a[2]), "r"(a[3]), "r"(b[0]), "r"(b[1]));
}
__device__ __forceinline__ void cp_async16(uint32_t dst, const void* src) {
    asm volatile("cp.async.cg.shared.global [%0], [%1], 16;"
                 :: "r"(dst), "l"(src) : "memory");
}
#define CP_COMMIT() asm volatile("cp.async.commit_group;" ::: "memory")
#define CP_WAIT(n)  asm volatile("cp.async.wait_group %0;" :: "n"(n) : "memory")

__device__ __forceinline__ void split_store(__nv_bfloat16* hi, __nv_bfloat16* lo,
                                            size_t idx, float a, float b) {
    __nv_bfloat16 h0 = __float2bfloat16(a), h1 = __float2bfloat16(b);
    __nv_bfloat162 hv(h0, h1);
    __nv_bfloat162 lv(__float2bfloat16(a - __bfloat162float(h0)),
                      __float2bfloat16(b - __bfloat162float(h1)));
    *(__nv_bfloat162*)&hi[idx] = hv;
    *(__nv_bfloat162*)&lo[idx] = lv;
}

// ---------------------------------------------------------------------------
// fp32 -> bf16 hi/lo split
// ---------------------------------------------------------------------------
__global__ __launch_bounds__(256) void precvt(const float* __restrict__ src,
                                              __nv_bfloat16* __restrict__ hi,
                                              __nv_bfloat16* __restrict__ lo,
                                              int n4)
{
    int i = blockIdx.x * 256 + threadIdx.x;
    if (i >= n4) return;
    float4 v = ((const float4*)src)[i];
    __nv_bfloat16 h0 = __float2bfloat16(v.x);
    __nv_bfloat16 h1 = __float2bfloat16(v.y);
    __nv_bfloat16 h2 = __float2bfloat16(v.z);
    __nv_bfloat16 h3 = __float2bfloat16(v.w);
    ((__nv_bfloat162*)hi)[2 * i]     = __nv_bfloat162(h0, h1);
    ((__nv_bfloat162*)hi)[2 * i + 1] = __nv_bfloat162(h2, h3);
    ((__nv_bfloat162*)lo)[2 * i] =
        __nv_bfloat162(__float2bfloat16(v.x - __bfloat162float(h0)),
                       __float2bfloat16(v.y - __bfloat162float(h1)));
    ((__nv_bfloat162*)lo)[2 * i + 1] =
        __nv_bfloat162(__float2bfloat16(v.z - __bfloat162float(h2)),
                       __float2bfloat16(v.w - __bfloat162float(h3)));
}

__global__ __launch_bounds__(256) void precvt_w(const float* __restrict__ w0,
                                                const float* __restrict__ w1,
                                                const float* __restrict__ w2,
                                                const float* __restrict__ w3,
                                                int n4)
{
    const int z = blockIdx.y;
    const float* src = (z == 0) ? w0 : (z == 1) ? w1 : (z == 2) ? w2 : w3;
    __nv_bfloat16* hi = g_whi + (size_t)z * DMODEL * DMODEL;
    __nv_bfloat16* lo = g_wlo + (size_t)z * DMODEL * DMODEL;
    int i = blockIdx.x * 256 + threadIdx.x;
    if (i >= n4) return;
    float4 v = ((const float4*)src)[i];
    __nv_bfloat16 h0 = __float2bfloat16(v.x);
    __nv_bfloat16 h1 = __float2bfloat16(v.y);
    __nv_bfloat16 h2 = __float2bfloat16(v.z);
    __nv_bfloat16 h3 = __float2bfloat16(v.w);
    ((__nv_bfloat162*)hi)[2 * i]     = __nv_bfloat162(h0, h1);
    ((__nv_bfloat162*)hi)[2 * i + 1] = __nv_bfloat162(h2, h3);
    ((__nv_bfloat162*)lo)[2 * i] =
        __nv_bfloat162(__float2bfloat16(v.x - __bfloat162float(h0)),
                       __float2bfloat16(v.y - __bfloat162float(h1)));
    ((__nv_bfloat162*)lo)[2 * i + 1] =
        __nv_bfloat162(__float2bfloat16(v.z - __bfloat162float(h2)),
                       __float2bfloat16(v.w - __bfloat162float(h3)));
}

// ---------------------------------------------------------------------------
// Split-bf16 mma.sync GEMM: C[m][e] = sum_d A[m][d] * B[e][d]
// CTA 128x128, 8 warps (warp 64x32). K slabs of 32, double-buffered cp.async.
// smem 80KB -> 2 CTAs/SM.
// ---------------------------------------------------------------------------
constexpr int GSTR = 40;                             // bf16 elems per row
constexpr int ARR = 128 * GSTR * 2;                  // 10240 B
constexpr int STAGE = 4 * ARR;                       // 40960 B
constexpr int GEMM_SMEM = 2 * STAGE;                 // 81920 B

__global__ __launch_bounds__(256, 2)
void gemm_mma(int is_out, const float* __restrict__ bo, float* __restrict__ outp)
{
    extern __shared__ char smc[];
    const uint32_t sbase = smem_u32(smc);

    const int tid  = threadIdx.x;
    const int wid  = tid >> 5;
    const int lane = tid & 31;
    const int wy   = wid >> 2;
    const int wx   = wid & 3;

    const int m0 = blockIdx.y * 128;
    const int e0 = blockIdx.x * 128;
    const int z  = blockIdx.z;

    const __nv_bfloat16* Ahi = is_out ? g_chi : g_xhi;
    const __nv_bfloat16* Alo = is_out ? g_clo : g_xlo;
    const int wsel = is_out ? 3 : z;
    const __nv_bfloat16* Bhi = g_whi + (size_t)wsel * DMODEL * DMODEL;
    const __nv_bfloat16* Blo = g_wlo + (size_t)wsel * DMODEL * DMODEL;

    auto stage = [&](int c, int buf) {
        const int k0 = c << 5;
        const uint32_t b = sbase + buf * STAGE;
        #pragma unroll
        for (int i = 0; i < 2; i++) {
            const int idx = i * 256 + tid;
            const int row = idx >> 2;
            const int col = (idx & 3) * 8;
            const uint32_t so = (uint32_t)(row * GSTR + col) * 2;
            const size_t gA = (size_t)(m0 + row) * DMODEL + k0 + col;
            const size_t gB = (size_t)(e0 + row) * DMODEL + k0 + col;
            cp_async16(b + 0 * ARR + so, Ahi + gA);
            cp_async16(b + 1 * ARR + so, Alo + gA);
            cp_async16(b + 2 * ARR + so, Bhi + gB);
            cp_async16(b + 3 * ARR + so, Blo + gB);
        }
    };

    // ldmatrix lane addressing
    const int arow  = (lane & 7) + ((lane >> 3) & 1) * 8;  // A x4
    const int akoff = (lane >> 4) * 8;
    const int browp = ((lane >> 4) & 1) * 8 + (lane & 7);  // B x4 pair
    const int bkoff = ((lane >> 3) & 1) * 8;

    float acc[4][4][4] = {};

    stage(0, 0);
    CP_COMMIT();

    for (int c = 0; c < 32; c++) {
        if (c + 1 < 32) {
            stage(c + 1, (c + 1) & 1);
            CP_COMMIT();
            CP_WAIT(1);
        } else {
            CP_WAIT(0);
        }
        __syncthreads();

        const uint32_t b    = sbase + (c & 1) * STAGE;
        const uint32_t aHiB = b + 0 * ARR;
        const uint32_t aLoB = b + 1 * ARR;
        const uint32_t bHiB = b + 2 * ARR;
        const uint32_t bLoB = b + 3 * ARR;

        #pragma unroll
        for (int ks = 0; ks < 2; ks++) {
            const int k0 = ks * 16;
            uint32_t bh[2][4], bl[2][4];   // [pair][4 regs = 2 frags]
            #pragma unroll
            for (int fp = 0; fp < 2; fp++) {
                const uint32_t off =
                    (uint32_t)((wx * 32 + fp * 16 + browp) * GSTR + k0 + bkoff) * 2;
                ldsm_x4(bh[fp], bHiB + off);
                ldsm_x4(bl[fp], bLoB + off);
            }
            #pragma unroll
            for (int fm = 0; fm < 4; fm++) {
                const uint32_t off =
                    (uint32_t)((wy * 64 + fm * 16 + arow) * GSTR + k0 + akoff) * 2;
                uint32_t ah[4], al[4];
                ldsm_x4(ah, aHiB + off);
                ldsm_x4(al, aLoB + off);
                #pragma unroll
                for (int fp = 0; fp < 2; fp++)
                    #pragma unroll
                    for (int hf = 0; hf < 2; hf++) {
                        const int fn = fp * 2 + hf;
                        mma_bf16(acc[fm][fn], ah, &bh[fp][hf * 2]);
                        mma_bf16(acc[fm][fn], al, &bh[fp][hf * 2]);
                        mma_bf16(acc[fm][fn], ah, &bl[fp][hf * 2]);
                    }
            }
        }
        __syncthreads();
    }

    const int r0 = lane >> 2;
    const int c0 = (lane & 3) * 2;
    #pragma unroll
    for (int fm = 0; fm < 4; fm++)
        #pragma unroll
        for (int fn = 0; fn < 4; fn++) {
            const int m = m0 + wy * 64 + fm * 16 + r0;
            const int e = e0 + wx * 32 + fn * 8 + c0;
            if (is_out) {
                const float b0v = bo[e], b1v = bo[e + 1];
                float2 v0 = make_float2(acc[fm][fn][0] + b0v, acc[fm][fn][1] + b1v);
                float2 v1 = make_float2(acc[fm][fn][2] + b0v, acc[fm][fn][3] + b1v);
                *(float2*)&outp[(size_t)m * DMODEL + e]       = v0;
                *(float2*)&outp[(size_t)(m + 8) * DMODEL + e] = v1;
            } else {
                __nv_bfloat16* dhi = (z == 0) ? g_qhi : (z == 1) ? g_khi : g_vhi;
                __nv_bfloat16* dlo = (z == 0) ? g_qlo : (z == 1) ? g_klo : g_vlo;
                const int h = e >> 6, dh = e & 63;
                const int bi = m >> 11, n = m & (SEQ - 1);
                size_t i0 = (((size_t)bi * HEADS + h) * SEQ + n) * DHEAD + dh;
                size_t i1 = (((size_t)bi * HEADS + h) * SEQ + n + 8) * DHEAD + dh;
                split_store(dhi, dlo, i0, acc[fm][fn][0], acc[fm][fn][1]);
                split_store(dhi, dlo, i1, acc[fm][fn][2], acc[fm][fn][3]);
            }
        }
}

// ---------------------------------------------------------------------------
// FlashAttention-2 with mma.sync split-bf16. CTA = 128 q (8 warps x 16 rows),
// 64-key double-buffered tiles. Q frags reloaded per tile (reg budget -> occ 2).
// ---------------------------------------------------------------------------
constexpr int QSTR = 72;
constexpr int ATT_Q   = 128 * QSTR * 2;        // 18432 B per Q array
constexpr int ATT_KV1 = 64 * QSTR * 2;         // 9216 B per K/V array
constexpr int ATT_BUF = 4 * ATT_KV1;           // 36864 B
constexpr int ATTN_SMEM = 2 * ATT_Q + 2 * ATT_BUF;  // 110592 B

__global__ __launch_bounds__(256, 2) void attn_mma()
{
    extern __shared__ char smc[];
    const uint32_t sb  = smem_u32(smc);
    const uint32_t qhB = sb;
    const uint32_t qlB = sb + ATT_Q;

    const int tid  = threadIdx.x;
    const int wid  = tid >> 5;
    const int lane = tid & 31;
    const int qb = blockIdx.x;
    const int h  = blockIdx.y;
    const int bb = blockIdx.z;

    const size_t hoff = ((size_t)bb * HEADS + h) * SEQ * DHEAD;
    const __nv_bfloat16* Qh = g_qhi + hoff + (size_t)qb * 128 * DHEAD;
    const __nv_bfloat16* Ql = g_qlo + hoff + (size_t)qb * 128 * DHEAD;
    const __nv_bfloat16* Kh = g_khi + hoff;
    const __nv_bfloat16* Kl = g_klo + hoff;
    const __nv_bfloat16* Vh = g_vhi + hoff;
    const __nv_bfloat16* Vl = g_vlo + hoff;

    auto stage_kv = [&](int kt, int buf) {
        const uint32_t base = sb + 2 * ATT_Q + buf * ATT_BUF;
        const size_t goff = (size_t)kt * 64 * DHEAD;
        #pragma unroll
        for (int i = 0; i < 2; i++) {
            int c = i * 256 + tid;
            int r = c >> 3, col = (c & 7) * 8;
            uint32_t so = (uint32_t)(r * QSTR + col) * 2;
            size_t go = goff + (size_t)r * DHEAD + col;
            cp_async16(base + 0 * ATT_KV1 + so, Kh + go);
            cp_async16(base + 1 * ATT_KV1 + so, Kl + go);
            cp_async16(base + 2 * ATT_KV1 + so, Vh + go);
            cp_async16(base + 3 * ATT_KV1 + so, Vl + go);
        }
    };

    #pragma unroll
    for (int i = 0; i < 4; i++) {
        int c = i * 256 + tid;
        int r = c >> 3, col = (c & 7) * 8;
        uint32_t so = (uint32_t)(r * QSTR + col) * 2;
        cp_async16(qhB + so, Qh + (size_t)r * DHEAD + col);
        cp_async16(qlB + so, Ql + (size_t)r * DHEAD + col);
    }
    stage_kv(0, 0);
    CP_COMMIT();
    CP_WAIT(0);
    __syncthreads();

    const int arow  = (lane & 7) + ((lane >> 3) & 1) * 8;
    const int akoff = (lane >> 4) * 8;
    const int browp = ((lane >> 4) & 1) * 8 + (lane & 7);
    const int bkoff = ((lane >> 3) & 1) * 8;
    const int vrowl = (lane & 7) + ((lane >> 3) & 1) * 8;
    const int vcolp = ((lane >> 4) & 1) * 8;

    const int g  = lane >> 2;
    const int tg = lane & 3;
    const int rowbase = qb * 128 + wid * 16;

    float o[8][4] = {};
    float mrow0 = -INFINITY, mrow1 = -INFINITY;
    float lrow0 = 0.f, lrow1 = 0.f;

    const int ktmax = 2 * qb + 1;
    for (int kt = 0; kt <= ktmax; kt++) {
        __syncthreads();
        if (kt < ktmax) {
            stage_kv(kt + 1, (kt + 1) & 1);
            CP_COMMIT();
            CP_WAIT(1);
        } else {
            CP_WAIT(0);
        }
        __syncthreads();

        const uint32_t kB = sb + 2 * ATT_Q + (kt & 1) * ATT_BUF;

        // S = Q @ K^T (3-term split)
        float s[8][4] = {};
        #pragma unroll
        for (int ks = 0; ks < 4; ks++) {
            uint32_t qoff = (uint32_t)((wid * 16 + arow) * QSTR + ks * 16 + akoff) * 2;
            uint32_t qh4[4], ql4[4];
            ldsm_x4(qh4, qhB + qoff);
            ldsm_x4(ql4, qlB + qoff);
            #pragma unroll
            for (int fp = 0; fp < 4; fp++) {
                uint32_t off =
                    (uint32_t)((fp * 16 + browp) * QSTR + ks * 16 + bkoff) * 2;
                uint32_t bh4[4], bl4[4];
                ldsm_x4(bh4, kB + off);
                ldsm_x4(bl4, kB + ATT_KV1 + off);
                #pragma unroll
                for (int hf = 0; hf < 2; hf++) {
                    const int fn = fp * 2 + hf;
                    mma_bf16(s[fn], qh4, &bh4[hf * 2]);
                    mma_bf16(s[fn], ql4, &bh4[hf * 2]);
                    mma_bf16(s[fn], qh4, &bl4[hf * 2]);
                }
            }
        }

        // scale + causal mask
        const bool needmask = (kt * 64 + 63 > rowbase);
        const int r0g = rowbase + g, r1g = r0g + 8;
        #pragma unroll
        for (int fn = 0; fn < 8; fn++) {
            const int cbase = kt * 64 + fn * 8 + tg * 2;
            float v0 = s[fn][0] * SCALE, v1 = s[fn][1] * SCALE;
            float v2 = s[fn][2] * SCALE, v3 = s[fn][3] * SCALE;
            if (needmask) {
                if (cbase     > r0g) v0 = -INFINITY;
                if (cbase + 1 > r0g) v1 = -INFINITY;
                if (cbase     > r1g) v2 = -INFINITY;
                if (cbase + 1 > r1g) v3 = -INFINITY;
            }
            s[fn][0] = v0; s[fn][1] = v1; s[fn][2] = v2; s[fn][3] = v3;
        }

        float mx0 = -INFINITY, mx1 = -INFINITY;
        #pragma unroll
        for (int fn = 0; fn < 8; fn++) {
            mx0 = fmaxf(mx0, fmaxf(s[fn][0], s[fn][1]));
            mx1 = fmaxf(mx1, fmaxf(s[fn][2], s[fn][3]));
        }
        mx0 = fmaxf(mx0, __shfl_xor_sync(0xffffffffu, mx0, 1));
        mx0 = fmaxf(mx0, __shfl_xor_sync(0xffffffffu, mx0, 2));
        mx1 = fmaxf(mx1, __shfl_xor_sync(0xffffffffu, mx1, 1));
        mx1 = fmaxf(mx1, __shfl_xor_sync(0xffffffffu, mx1, 2));

        const float mn0 = fmaxf(mrow0, mx0);
        const float mn1 = fmaxf(mrow1, mx1);
        const float al0 = __expf(mrow0 - mn0);
        const float al1 = __expf(mrow1 - mn1);

        float rs0 = 0.f, rs1 = 0.f;
        #pragma unroll
        for (int fn = 0; fn < 8; fn++) {
            float p0 = __expf(s[fn][0] - mn0);
            float p1 = __expf(s[fn][1] - mn0);
            float p2 = __expf(s[fn][2] - mn1);
            float p3 = __expf(s[fn][3] - mn1);
            s[fn][0] = p0; s[fn][1] = p1; s[fn][2] = p2; s[fn][3] = p3;
            rs0 += p0 + p1;
            rs1 += p2 + p3;
        }
        rs0 += __shfl_xor_sync(0xffffffffu, rs0, 1);
        rs0 += __shfl_xor_sync(0xffffffffu, rs0, 2);
        rs1 += __shfl_xor_sync(0xffffffffu, rs1, 1);
        rs1 += __shfl_xor_sync(0xffffffffu, rs1, 2);

        lrow0 = lrow0 * al0 + rs0;
        lrow1 = lrow1 * al1 + rs1;
        mrow0 = mn0; mrow1 = mn1;

        #pragma unroll
        for (int fn = 0; fn < 8; fn++) {
            o[fn][0] *= al0; o[fn][1] *= al0;
            o[fn][2] *= al1; o[fn][3] *= al1;
        }

        // O += P @ V
        const uint32_t vB = kB + 2 * ATT_KV1;
        #pragma unroll
        for (int kg = 0; kg < 4; kg++) {
            uint32_t ph[4], pl[4];
            #pragma unroll
            for (int half = 0; half < 2; half++) {
                const int f = 2 * kg + half;
                float a0 = s[f][0], a1 = s[f][1], a2 = s[f][2], a3 = s[f][3];
                __nv_bfloat16 h0 = __float2bfloat16(a0), h1 = __float2bfloat16(a1);
                __nv_bfloat16 h2 = __float2bfloat16(a2), h3 = __float2bfloat16(a3);
                __nv_bfloat162 t0(h0, h1), t1(h2, h3);
                ph[2 * half]     = *(uint32_t*)&t0;
                ph[2 * half + 1] = *(uint32_t*)&t1;
                __nv_bfloat162 u0(__float2bfloat16(a0 - __bfloat162float(h0)),
                                  __float2bfloat16(a1 - __bfloat162float(h1)));
                __nv_bfloat162 u1(__float2bfloat16(a2 - __bfloat162float(h2)),
                                  __float2bfloat16(a3 - __bfloat162float(h3)));
                pl[2 * half]     = *(uint32_t*)&u0;
                pl[2 * half + 1] = *(uint32_t*)&u1;
            }
            const int vrow = kg * 16 + vrowl;
            #pragma unroll
            for (int fp = 0; fp < 4; fp++) {
                uint32_t off = (uint32_t)(vrow * QSTR + fp * 16 + vcolp) * 2;
                uint32_t vh4[4], vl4[4];
                ldsm_x4t(vh4, vB + off);
                ldsm_x4t(vl4, vB + ATT_KV1 + off);
                #pragma unroll
                for (int hf = 0; hf < 2; hf++) {
                    const int fn = fp * 2 + hf;
                    mma_bf16(o[fn], ph, &vh4[hf * 2]);
                    mma_bf16(o[fn], pl, &vh4[hf * 2]);
                    mma_bf16(o[fn], ph, &vl4[hf * 2]);
                }
            }
        }
    }

    const float inv0 = 1.f / lrow0;
    const float inv1 = 1.f / lrow1;
    const int q0 = rowbase + g;
    const int q1 = q0 + 8;
    #pragma unroll
    for (int fn = 0; fn < 8; fn++) {
        const int e = h * 64 + fn * 8 + tg * 2;
        size_t i0 = (size_t)(bb * SEQ + q0) * DMODEL + e;
        size_t i1 = (size_t)(bb * SEQ + q1) * DMODEL + e;
        split_store(g_chi, g_clo, i0, o[fn][0] * inv0, o[fn][1] * inv0);
        split_store(g_chi, g_clo, i1, o[fn][2] * inv1, o[fn][3] * inv1);
    }
}

// ---------------------------------------------------------------------------
extern "C" void kernel_launch(void* const* d_in, const int* in_sizes, int n_in,
                              void* d_out, int out_size)
{
    (void)in_sizes; (void)n_in; (void)out_size;
    const float* x  = (const float*)d_in[0];
    const float* Wq = (const float*)d_in[1];
    const float* Wk = (const float*)d_in[2];
    const float* Wv = (const float*)d_in[3];
    const float* Wo = (const float*)d_in[4];
    const float* bo = (const float*)d_in[5];
    float* out = (float*)d_out;

    cudaFuncSetAttribute(gemm_mma, cudaFuncAttributeMaxDynamicSharedMemorySize,
                         GEMM_SMEM);
    cudaFuncSetAttribute(attn_mma, cudaFuncAttributeMaxDynamicSharedMemorySize,
                         ATTN_SMEM);

    __nv_bfloat16 *xhi, *xlo;
    cudaGetSymbolAddress((void**)&xhi, g_xhi);
    cudaGetSymbolAddress((void**)&xlo, g_xlo);

    const int NX4 = MTOT * DMODEL / 4;
    const int NW4 = DMODEL * DMODEL / 4;

    precvt<<<NX4 / 256, 256>>>(x, xhi, xlo, NX4);
    precvt_w<<<dim3(NW4 / 256, 4), 256>>>(Wq, Wk, Wv, Wo, NW4);

    gemm_mma<<<dim3(DMODEL / 128, MTOT / 128, 3), 256, GEMM_SMEM>>>(0, nullptr, nullptr);
    attn_mma<<<dim3(SEQ / 128, HEADS, BATCH), 256, ATTN_SMEM>>>();
    gemm_mma<<<dim3(DMODEL / 128, MTOT / 128, 1), 256, GEMM_SMEM>>>(1, bo, out);
}

// round 7
// speedup vs baseline: 3.7537x; 1.1154x over previous
#include <cuda_runtime.h>
#include <cuda_bf16.h>
#include <math.h>
#include <stdint.h>

// Problem constants
constexpr int BATCH = 2;
constexpr int SEQ   = 2048;
constexpr int DMODEL= 1024;
constexpr int HEADS = 16;
constexpr int DHEAD = 64;
constexpr int MTOT  = BATCH * SEQ;           // 4096
constexpr float SCALE = 0.0220970869120796f; // 1/sqrt(2048)

// Scratch (allocation-free rule: __device__ globals). bf16 split where needed.
__device__ __nv_bfloat16 g_xhi[MTOT * DMODEL];
__device__ __nv_bfloat16 g_xlo[MTOT * DMODEL];
__device__ __nv_bfloat16 g_whi[4 * DMODEL * DMODEL];
__device__ __nv_bfloat16 g_wlo[4 * DMODEL * DMODEL];
__device__ __nv_bfloat16 g_qhi[BATCH * HEADS * SEQ * DHEAD];   // hi only
__device__ __nv_bfloat16 g_khi[BATCH * HEADS * SEQ * DHEAD];   // hi only
__device__ __nv_bfloat16 g_vhi[BATCH * HEADS * SEQ * DHEAD];
__device__ __nv_bfloat16 g_vlo[BATCH * HEADS * SEQ * DHEAD];
__device__ __nv_bfloat16 g_chi[MTOT * DMODEL];
__device__ __nv_bfloat16 g_clo[MTOT * DMODEL];

// ---------------------------------------------------------------------------
// Portable tensor-core helpers (sm_80+ ISA)
// ---------------------------------------------------------------------------
__device__ __forceinline__ uint32_t smem_u32(const void* p) {
    uint32_t a;
    asm("{ .reg .u64 t; cvta.to.shared.u64 t, %1; cvt.u32.u64 %0, t; }"
        : "=r"(a) : "l"(p));
    return a;
}
__device__ __forceinline__ void ldsm_x4(uint32_t r[4], uint32_t a) {
    asm volatile("ldmatrix.sync.aligned.m8n8.x4.shared.b16 {%0,%1,%2,%3}, [%4];"
                 : "=r"(r[0]), "=r"(r[1]), "=r"(r[2]), "=r"(r[3]) : "r"(a));
}
__device__ __forceinline__ void ldsm_x4t(uint32_t r[4], uint32_t a) {
    asm volatile("ldmatrix.sync.aligned.m8n8.x4.trans.shared.b16 {%0,%1,%2,%3}, [%4];"
                 : "=r"(r[0]), "=r"(r[1]), "=r"(r[2]), "=r"(r[3]) : "r"(a));
}
__device__ __forceinline__ void mma_bf16(float d[4], const uint32_t a[4],
                                         const uint32_t b[2]) {
    asm volatile(
        "mma.sync.aligned.m16n8k16.row.col.f32.bf16.bf16.f32 "
        "{%0,%1,%2,%3}, {%4,%5,%6,%7}, {%8,%9}, {%0,%1,%2,%3};"
        : "+f"(d[0]), "+f"(d[1]), "+f"(d[2]), "+f"(d[3])
        : "r"(a[0]), "r"(a[1]), "r"(a[2]), "r"(a[3]), "r"(b[0]), "r"(b[1]));
}
__device__ __forceinline__ void cp_async16(uint32_t dst, const void* src) {
    asm volatile("cp.async.cg.shared.global [%0], [%1], 16;"
                 :: "r"(dst), "l"(src) : "memory");
}
#define CP_COMMIT() asm volatile("cp.async.commit_group;" ::: "memory")
#define CP_WAIT(n)  asm volatile("cp.async.wait_group %0;" :: "n"(n) : "memory")

__device__ __forceinline__ void split_store(__nv_bfloat16* hi, __nv_bfloat16* lo,
                                            size_t idx, float a, float b) {
    __nv_bfloat16 h0 = __float2bfloat16(a), h1 = __float2bfloat16(b);
    __nv_bfloat162 hv(h0, h1);
    __nv_bfloat162 lv(__float2bfloat16(a - __bfloat162float(h0)),
                      __float2bfloat16(b - __bfloat162float(h1)));
    *(__nv_bfloat162*)&hi[idx] = hv;
    *(__nv_bfloat162*)&lo[idx] = lv;
}
__device__ __forceinline__ void hi_store(__nv_bfloat16* hi, size_t idx,
                                         float a, float b) {
    __nv_bfloat162 hv(__float2bfloat16(a), __float2bfloat16(b));
    *(__nv_bfloat162*)&hi[idx] = hv;
}

// ---------------------------------------------------------------------------
// fp32 -> bf16 hi/lo split
// ---------------------------------------------------------------------------
__global__ __launch_bounds__(256) void precvt(const float* __restrict__ src,
                                              __nv_bfloat16* __restrict__ hi,
                                              __nv_bfloat16* __restrict__ lo,
                                              int n4)
{
    int i = blockIdx.x * 256 + threadIdx.x;
    if (i >= n4) return;
    float4 v = ((const float4*)src)[i];
    __nv_bfloat16 h0 = __float2bfloat16(v.x);
    __nv_bfloat16 h1 = __float2bfloat16(v.y);
    __nv_bfloat16 h2 = __float2bfloat16(v.z);
    __nv_bfloat16 h3 = __float2bfloat16(v.w);
    ((__nv_bfloat162*)hi)[2 * i]     = __nv_bfloat162(h0, h1);
    ((__nv_bfloat162*)hi)[2 * i + 1] = __nv_bfloat162(h2, h3);
    ((__nv_bfloat162*)lo)[2 * i] =
        __nv_bfloat162(__float2bfloat16(v.x - __bfloat162float(h0)),
                       __float2bfloat16(v.y - __bfloat162float(h1)));
    ((__nv_bfloat162*)lo)[2 * i + 1] =
        __nv_bfloat162(__float2bfloat16(v.z - __bfloat162float(h2)),
                       __float2bfloat16(v.w - __bfloat162float(h3)));
}

__global__ __launch_bounds__(256) void precvt_w(const float* __restrict__ w0,
                                                const float* __restrict__ w1,
                                                const float* __restrict__ w2,
                                                const float* __restrict__ w3,
                                                int n4)
{
    const int z = blockIdx.y;
    const float* src = (z == 0) ? w0 : (z == 1) ? w1 : (z == 2) ? w2 : w3;
    __nv_bfloat16* hi = g_whi + (size_t)z * DMODEL * DMODEL;
    __nv_bfloat16* lo = g_wlo + (size_t)z * DMODEL * DMODEL;
    int i = blockIdx.x * 256 + threadIdx.x;
    if (i >= n4) return;
    float4 v = ((const float4*)src)[i];
    __nv_bfloat16 h0 = __float2bfloat16(v.x);
    __nv_bfloat16 h1 = __float2bfloat16(v.y);
    __nv_bfloat16 h2 = __float2bfloat16(v.z);
    __nv_bfloat16 h3 = __float2bfloat16(v.w);
    ((__nv_bfloat162*)hi)[2 * i]     = __nv_bfloat162(h0, h1);
    ((__nv_bfloat162*)hi)[2 * i + 1] = __nv_bfloat162(h2, h3);
    ((__nv_bfloat162*)lo)[2 * i] =
        __nv_bfloat162(__float2bfloat16(v.x - __bfloat162float(h0)),
                       __float2bfloat16(v.y - __bfloat162float(h1)));
    ((__nv_bfloat162*)lo)[2 * i + 1] =
        __nv_bfloat162(__float2bfloat16(v.z - __bfloat162float(h2)),
                       __float2bfloat16(v.w - __bfloat162float(h3)));
}

// ---------------------------------------------------------------------------
// Split-bf16 mma.sync GEMM: C[m][e] = sum_d A[m][d] * B[e][d]
// CTA 128x128, 8 warps, K slabs of 32, double-buffered cp.async, 2 CTAs/SM.
// ---------------------------------------------------------------------------
constexpr int GSTR = 40;
constexpr int ARR = 128 * GSTR * 2;                  // 10240 B
constexpr int STAGE = 4 * ARR;                       // 40960 B
constexpr int GEMM_SMEM = 2 * STAGE;                 // 81920 B

__global__ __launch_bounds__(256, 2)
void gemm_mma(int is_out, const float* __restrict__ bo, float* __restrict__ outp)
{
    extern __shared__ char smc[];
    const uint32_t sbase = smem_u32(smc);

    const int tid  = threadIdx.x;
    const int wid  = tid >> 5;
    const int lane = tid & 31;
    const int wy   = wid >> 2;
    const int wx   = wid & 3;

    const int m0 = blockIdx.y * 128;
    const int e0 = blockIdx.x * 128;
    const int z  = blockIdx.z;

    const __nv_bfloat16* Ahi = is_out ? g_chi : g_xhi;
    const __nv_bfloat16* Alo = is_out ? g_clo : g_xlo;
    const int wsel = is_out ? 3 : z;
    const __nv_bfloat16* Bhi = g_whi + (size_t)wsel * DMODEL * DMODEL;
    const __nv_bfloat16* Blo = g_wlo + (size_t)wsel * DMODEL * DMODEL;

    auto stage = [&](int c, int buf) {
        const int k0 = c << 5;
        const uint32_t b = sbase + buf * STAGE;
        #pragma unroll
        for (int i = 0; i < 2; i++) {
            const int idx = i * 256 + tid;
            const int row = idx >> 2;
            const int col = (idx & 3) * 8;
            const uint32_t so = (uint32_t)(row * GSTR + col) * 2;
            const size_t gA = (size_t)(m0 + row) * DMODEL + k0 + col;
            const size_t gB = (size_t)(e0 + row) * DMODEL + k0 + col;
            cp_async16(b + 0 * ARR + so, Ahi + gA);
            cp_async16(b + 1 * ARR + so, Alo + gA);
            cp_async16(b + 2 * ARR + so, Bhi + gB);
            cp_async16(b + 3 * ARR + so, Blo + gB);
        }
    };

    const int arow  = (lane & 7) + ((lane >> 3) & 1) * 8;
    const int akoff = (lane >> 4) * 8;
    const int browp = ((lane >> 4) & 1) * 8 + (lane & 7);
    const int bkoff = ((lane >> 3) & 1) * 8;

    float acc[4][4][4] = {};

    stage(0, 0);
    CP_COMMIT();

    for (int c = 0; c < 32; c++) {
        if (c + 1 < 32) {
            stage(c + 1, (c + 1) & 1);
            CP_COMMIT();
            CP_WAIT(1);
        } else {
            CP_WAIT(0);
        }
        __syncthreads();

        const uint32_t b    = sbase + (c & 1) * STAGE;
        const uint32_t aHiB = b + 0 * ARR;
        const uint32_t aLoB = b + 1 * ARR;
        const uint32_t bHiB = b + 2 * ARR;
        const uint32_t bLoB = b + 3 * ARR;

        #pragma unroll
        for (int ks = 0; ks < 2; ks++) {
            const int k0 = ks * 16;
            uint32_t bh[2][4], bl[2][4];
            #pragma unroll
            for (int fp = 0; fp < 2; fp++) {
                const uint32_t off =
                    (uint32_t)((wx * 32 + fp * 16 + browp) * GSTR + k0 + bkoff) * 2;
                ldsm_x4(bh[fp], bHiB + off);
                ldsm_x4(bl[fp], bLoB + off);
            }
            #pragma unroll
            for (int fm = 0; fm < 4; fm++) {
                const uint32_t off =
                    (uint32_t)((wy * 64 + fm * 16 + arow) * GSTR + k0 + akoff) * 2;
                uint32_t ah[4], al[4];
                ldsm_x4(ah, aHiB + off);
                ldsm_x4(al, aLoB + off);
                #pragma unroll
                for (int fp = 0; fp < 2; fp++)
                    #pragma unroll
                    for (int hf = 0; hf < 2; hf++) {
                        const int fn = fp * 2 + hf;
                        mma_bf16(acc[fm][fn], ah, &bh[fp][hf * 2]);
                        mma_bf16(acc[fm][fn], al, &bh[fp][hf * 2]);
                        mma_bf16(acc[fm][fn], ah, &bl[fp][hf * 2]);
                    }
            }
        }
        __syncthreads();
    }

    const int r0 = lane >> 2;
    const int c0 = (lane & 3) * 2;
    #pragma unroll
    for (int fm = 0; fm < 4; fm++)
        #pragma unroll
        for (int fn = 0; fn < 4; fn++) {
            const int m = m0 + wy * 64 + fm * 16 + r0;
            const int e = e0 + wx * 32 + fn * 8 + c0;
            if (is_out) {
                const float b0v = bo[e], b1v = bo[e + 1];
                float2 v0 = make_float2(acc[fm][fn][0] + b0v, acc[fm][fn][1] + b1v);
                float2 v1 = make_float2(acc[fm][fn][2] + b0v, acc[fm][fn][3] + b1v);
                *(float2*)&outp[(size_t)m * DMODEL + e]       = v0;
                *(float2*)&outp[(size_t)(m + 8) * DMODEL + e] = v1;
            } else {
                const int h = e >> 6, dh = e & 63;
                const int bi = m >> 11, n = m & (SEQ - 1);
                size_t i0 = (((size_t)bi * HEADS + h) * SEQ + n) * DHEAD + dh;
                size_t i1 = (((size_t)bi * HEADS + h) * SEQ + n + 8) * DHEAD + dh;
                if (z == 2) {
                    split_store(g_vhi, g_vlo, i0, acc[fm][fn][0], acc[fm][fn][1]);
                    split_store(g_vhi, g_vlo, i1, acc[fm][fn][2], acc[fm][fn][3]);
                } else {
                    __nv_bfloat16* dhi = (z == 0) ? g_qhi : g_khi;
                    hi_store(dhi, i0, acc[fm][fn][0], acc[fm][fn][1]);
                    hi_store(dhi, i1, acc[fm][fn][2], acc[fm][fn][3]);
                }
            }
        }
}

// ---------------------------------------------------------------------------
// FlashAttention-2 mma.sync. QK^T hi-only (1 term); PV 3-term split.
// CTA = 128 q (8 warps x 16 rows), 64-key double-buffered tiles.
// Biggest qb scheduled first (reverse map) to trim causal tail.
// ---------------------------------------------------------------------------
constexpr int QSTR = 72;
constexpr int ATT_Q   = 128 * QSTR * 2;        // 18432 B (Q hi)
constexpr int ATT_KV1 = 64 * QSTR * 2;         // 9216 B per array
constexpr int ATT_BUF = 3 * ATT_KV1;           // 27648 B (Kh, Vh, Vl)
constexpr int ATTN_SMEM = ATT_Q + 2 * ATT_BUF; // 73728 B

__global__ __launch_bounds__(256, 2) void attn_mma()
{
    extern __shared__ char smc[];
    const uint32_t sb  = smem_u32(smc);
    const uint32_t qhB = sb;

    const int tid  = threadIdx.x;
    const int wid  = tid >> 5;
    const int lane = tid & 31;
    const int qb = gridDim.x - 1 - blockIdx.x;   // biggest first
    const int h  = blockIdx.y;
    const int bb = blockIdx.z;

    const size_t hoff = ((size_t)bb * HEADS + h) * SEQ * DHEAD;
    const __nv_bfloat16* Qh = g_qhi + hoff + (size_t)qb * 128 * DHEAD;
    const __nv_bfloat16* Kh = g_khi + hoff;
    const __nv_bfloat16* Vh = g_vhi + hoff;
    const __nv_bfloat16* Vl = g_vlo + hoff;

    auto stage_kv = [&](int kt, int buf) {
        const uint32_t base = sb + ATT_Q + buf * ATT_BUF;
        const size_t goff = (size_t)kt * 64 * DHEAD;
        #pragma unroll
        for (int i = 0; i < 2; i++) {
            int c = i * 256 + tid;
            int r = c >> 3, col = (c & 7) * 8;
            uint32_t so = (uint32_t)(r * QSTR + col) * 2;
            size_t go = goff + (size_t)r * DHEAD + col;
            cp_async16(base + 0 * ATT_KV1 + so, Kh + go);
            cp_async16(base + 1 * ATT_KV1 + so, Vh + go);
            cp_async16(base + 2 * ATT_KV1 + so, Vl + go);
        }
    };

    #pragma unroll
    for (int i = 0; i < 4; i++) {
        int c = i * 256 + tid;
        int r = c >> 3, col = (c & 7) * 8;
        uint32_t so = (uint32_t)(r * QSTR + col) * 2;
        cp_async16(qhB + so, Qh + (size_t)r * DHEAD + col);
    }
    stage_kv(0, 0);
    CP_COMMIT();
    CP_WAIT(0);
    __syncthreads();

    const int arow  = (lane & 7) + ((lane >> 3) & 1) * 8;
    const int akoff = (lane >> 4) * 8;
    const int browp = ((lane >> 4) & 1) * 8 + (lane & 7);
    const int bkoff = ((lane >> 3) & 1) * 8;
    const int vrowl = (lane & 7) + ((lane >> 3) & 1) * 8;
    const int vcolp = ((lane >> 4) & 1) * 8;

    const int g  = lane >> 2;
    const int tg = lane & 3;
    const int rowbase = qb * 128 + wid * 16;

    float o[8][4] = {};
    float mrow0 = -INFINITY, mrow1 = -INFINITY;
    float lrow0 = 0.f, lrow1 = 0.f;

    const int ktmax = 2 * qb + 1;
    for (int kt = 0; kt <= ktmax; kt++) {
        __syncthreads();
        if (kt < ktmax) {
            stage_kv(kt + 1, (kt + 1) & 1);
            CP_COMMIT();
            CP_WAIT(1);
        } else {
            CP_WAIT(0);
        }
        __syncthreads();

        const uint32_t kB = sb + ATT_Q + (kt & 1) * ATT_BUF;

        // S = Qhi @ Khi^T (hi-only)
        float s[8][4] = {};
        #pragma unroll
        for (int ks = 0; ks < 4; ks++) {
            uint32_t qoff = (uint32_t)((wid * 16 + arow) * QSTR + ks * 16 + akoff) * 2;
            uint32_t qh4[4];
            ldsm_x4(qh4, qhB + qoff);
            #pragma unroll
            for (int fp = 0; fp < 4; fp++) {
                uint32_t off =
                    (uint32_t)((fp * 16 + browp) * QSTR + ks * 16 + bkoff) * 2;
                uint32_t bh4[4];
                ldsm_x4(bh4, kB + off);
                mma_bf16(s[fp * 2 + 0], qh4, &bh4[0]);
                mma_bf16(s[fp * 2 + 1], qh4, &bh4[2]);
            }
        }

        // scale + causal mask
        const bool needmask = (kt * 64 + 63 > rowbase);
        const int r0g = rowbase + g, r1g = r0g + 8;
        #pragma unroll
        for (int fn = 0; fn < 8; fn++) {
            const int cbase = kt * 64 + fn * 8 + tg * 2;
            float v0 = s[fn][0] * SCALE, v1 = s[fn][1] * SCALE;
            float v2 = s[fn][2] * SCALE, v3 = s[fn][3] * SCALE;
            if (needmask) {
                if (cbase     > r0g) v0 = -INFINITY;
                if (cbase + 1 > r0g) v1 = -INFINITY;
                if (cbase     > r1g) v2 = -INFINITY;
                if (cbase + 1 > r1g) v3 = -INFINITY;
            }
            s[fn][0] = v0; s[fn][1] = v1; s[fn][2] = v2; s[fn][3] = v3;
        }

        float mx0 = -INFINITY, mx1 = -INFINITY;
        #pragma unroll
        for (int fn = 0; fn < 8; fn++) {
            mx0 = fmaxf(mx0, fmaxf(s[fn][0], s[fn][1]));
            mx1 = fmaxf(mx1, fmaxf(s[fn][2], s[fn][3]));
        }
        mx0 = fmaxf(mx0, __shfl_xor_sync(0xffffffffu, mx0, 1));
        mx0 = fmaxf(mx0, __shfl_xor_sync(0xffffffffu, mx0, 2));
        mx1 = fmaxf(mx1, __shfl_xor_sync(0xffffffffu, mx1, 1));
        mx1 = fmaxf(mx1, __shfl_xor_sync(0xffffffffu, mx1, 2));

        const float mn0 = fmaxf(mrow0, mx0);
        const float mn1 = fmaxf(mrow1, mx1);
        const float al0 = __expf(mrow0 - mn0);
        const float al1 = __expf(mrow1 - mn1);

        float rs0 = 0.f, rs1 = 0.f;
        #pragma unroll
        for (int fn = 0; fn < 8; fn++) {
            float p0 = __expf(s[fn][0] - mn0);
            float p1 = __expf(s[fn][1] - mn0);
            float p2 = __expf(s[fn][2] - mn1);
            float p3 = __expf(s[fn][3] - mn1);
            s[fn][0] = p0; s[fn][1] = p1; s[fn][2] = p2; s[fn][3] = p3;
            rs0 += p0 + p1;
            rs1 += p2 + p3;
        }
        rs0 += __shfl_xor_sync(0xffffffffu, rs0, 1);
        rs0 += __shfl_xor_sync(0xffffffffu, rs0, 2);
        rs1 += __shfl_xor_sync(0xffffffffu, rs1, 1);
        rs1 += __shfl_xor_sync(0xffffffffu, rs1, 2);

        lrow0 = lrow0 * al0 + rs0;
        lrow1 = lrow1 * al1 + rs1;
        mrow0 = mn0; mrow1 = mn1;

        #pragma unroll
        for (int fn = 0; fn < 8; fn++) {
            o[fn][0] *= al0; o[fn][1] *= al0;
            o[fn][2] *= al1; o[fn][3] *= al1;
        }

        // O += P @ V (P split hi/lo, V split hi/lo, 3 terms)
        const uint32_t vB = kB + 1 * ATT_KV1;
        #pragma unroll
        for (int kg = 0; kg < 4; kg++) {
            uint32_t ph[4], pl[4];
            #pragma unroll
            for (int half = 0; half < 2; half++) {
                const int f = 2 * kg + half;
                float a0 = s[f][0], a1 = s[f][1], a2 = s[f][2], a3 = s[f][3];
                __nv_bfloat16 h0 = __float2bfloat16(a0), h1 = __float2bfloat16(a1);
                __nv_bfloat16 h2 = __float2bfloat16(a2), h3 = __float2bfloat16(a3);
                __nv_bfloat162 t0(h0, h1), t1(h2, h3);
                ph[2 * half]     = *(uint32_t*)&t0;
                ph[2 * half + 1] = *(uint32_t*)&t1;
                __nv_bfloat162 u0(__float2bfloat16(a0 - __bfloat162float(h0)),
                                  __float2bfloat16(a1 - __bfloat162float(h1)));
                __nv_bfloat162 u1(__float2bfloat16(a2 - __bfloat162float(h2)),
                                  __float2bfloat16(a3 - __bfloat162float(h3)));
                pl[2 * half]     = *(uint32_t*)&u0;
                pl[2 * half + 1] = *(uint32_t*)&u1;
            }
            const int vrow = kg * 16 + vrowl;
            #pragma unroll
            for (int fp = 0; fp < 4; fp++) {
                uint32_t off = (uint32_t)(vrow * QSTR + fp * 16 + vcolp) * 2;
                uint32_t vh4[4], vl4[4];
                ldsm_x4t(vh4, vB + off);
                ldsm_x4t(vl4, vB + ATT_KV1 + off);
                #pragma unroll
                for (int hf = 0; hf < 2; hf++) {
                    const int fn = fp * 2 + hf;
                    mma_bf16(o[fn], ph, &vh4[hf * 2]);
                    mma_bf16(o[fn], pl, &vh4[hf * 2]);
                    mma_bf16(o[fn], ph, &vl4[hf * 2]);
                }
            }
        }
    }

    const float inv0 = 1.f / lrow0;
    const float inv1 = 1.f / lrow1;
    const int q0 = rowbase + g;
    const int q1 = q0 + 8;
    #pragma unroll
    for (int fn = 0; fn < 8; fn++) {
        const int e = h * 64 + fn * 8 + tg * 2;
        size_t i0 = (size_t)(bb * SEQ + q0) * DMODEL + e;
        size_t i1 = (size_t)(bb * SEQ + q1) * DMODEL + e;
        split_store(g_chi, g_clo, i0, o[fn][0] * inv0, o[fn][1] * inv0);
        split_store(g_chi, g_clo, i1, o[fn][2] * inv1, o[fn][3] * inv1);
    }
}

// ---------------------------------------------------------------------------
extern "C" void kernel_launch(void* const* d_in, const int* in_sizes, int n_in,
                              void* d_out, int out_size)
{
    (void)in_sizes; (void)n_in; (void)out_size;
    const float* x  = (const float*)d_in[0];
    const float* Wq = (const float*)d_in[1];
    const float* Wk = (const float*)d_in[2];
    const float* Wv = (const float*)d_in[3];
    const float* Wo = (const float*)d_in[4];
    const float* bo = (const float*)d_in[5];
    float* out = (float*)d_out;

    cudaFuncSetAttribute(gemm_mma, cudaFuncAttributeMaxDynamicSharedMemorySize,
                         GEMM_SMEM);
    cudaFuncSetAttribute(attn_mma, cudaFuncAttributeMaxDynamicSharedMemorySize,
                         ATTN_SMEM);

    __nv_bfloat16 *xhi, *xlo;
    cudaGetSymbolAddress((void**)&xhi, g_xhi);
    cudaGetSymbolAddress((void**)&xlo, g_xlo);

    const int NX4 = MTOT * DMODEL / 4;
    const int NW4 = DMODEL * DMODEL / 4;

    precvt<<<NX4 / 256, 256>>>(x, xhi, xlo, NX4);
    precvt_w<<<dim3(NW4 / 256, 4), 256>>>(Wq, Wk, Wv, Wo, NW4);

    gemm_mma<<<dim3(DMODEL / 128, MTOT / 128, 3), 256, GEMM_SMEM>>>(0, nullptr, nullptr);
    attn_mma<<<dim3(SEQ / 128, HEADS, BATCH), 256, ATTN_SMEM>>>();
    gemm_mma<<<dim3(DMODEL / 128, MTOT / 128, 1), 256, GEMM_SMEM>>>(1, bo, out);
}

// round 8
// speedup vs baseline: 4.5735x; 1.2184x over previous
#include <cuda_runtime.h>
#include <cuda_bf16.h>
#include <math.h>
#include <stdint.h>

// Problem constants
constexpr int BATCH = 2;
constexpr int SEQ   = 2048;
constexpr int DMODEL= 1024;
constexpr int HEADS = 16;
constexpr int DHEAD = 64;
constexpr int MTOT  = BATCH * SEQ;           // 4096
constexpr float SCALE = 0.0220970869120796f; // 1/sqrt(2048)

// Scratch (allocation-free rule: __device__ globals). bf16 split where needed.
__device__ __nv_bfloat16 g_xhi[MTOT * DMODEL];
__device__ __nv_bfloat16 g_xlo[MTOT * DMODEL];
__device__ __nv_bfloat16 g_whi[4 * DMODEL * DMODEL];
__device__ __nv_bfloat16 g_wlo[4 * DMODEL * DMODEL];
__device__ __nv_bfloat16 g_qhi[BATCH * HEADS * SEQ * DHEAD];   // hi only
__device__ __nv_bfloat16 g_khi[BATCH * HEADS * SEQ * DHEAD];   // hi only
__device__ __nv_bfloat16 g_vhi[BATCH * HEADS * SEQ * DHEAD];
__device__ __nv_bfloat16 g_vlo[BATCH * HEADS * SEQ * DHEAD];
__device__ __nv_bfloat16 g_chi[MTOT * DMODEL];
__device__ __nv_bfloat16 g_clo[MTOT * DMODEL];

// ---------------------------------------------------------------------------
// Portable tensor-core helpers (sm_80+ ISA)
// ---------------------------------------------------------------------------
__device__ __forceinline__ uint32_t smem_u32(const void* p) {
    uint32_t a;
    asm("{ .reg .u64 t; cvta.to.shared.u64 t, %1; cvt.u32.u64 %0, t; }"
        : "=r"(a) : "l"(p));
    return a;
}
__device__ __forceinline__ void ldsm_x4(uint32_t r[4], uint32_t a) {
    asm volatile("ldmatrix.sync.aligned.m8n8.x4.shared.b16 {%0,%1,%2,%3}, [%4];"
                 : "=r"(r[0]), "=r"(r[1]), "=r"(r[2]), "=r"(r[3]) : "r"(a));
}
__device__ __forceinline__ void ldsm_x4t(uint32_t r[4], uint32_t a) {
    asm volatile("ldmatrix.sync.aligned.m8n8.x4.trans.shared.b16 {%0,%1,%2,%3}, [%4];"
                 : "=r"(r[0]), "=r"(r[1]), "=r"(r[2]), "=r"(r[3]) : "r"(a));
}
__device__ __forceinline__ void mma_bf16(float d[4], const uint32_t a[4],
                                         const uint32_t b[2]) {
    asm volatile(
        "mma.sync.aligned.m16n8k16.row.col.f32.bf16.bf16.f32 "
        "{%0,%1,%2,%3}, {%4,%5,%6,%7}, {%8,%9}, {%0,%1,%2,%3};"
        : "+f"(d[0]), "+f"(d[1]), "+f"(d[2]), "+f"(d[3])
        : "r"(a[0]), "r"(a[1]), "r"(a[2]), "r"(a[3]), "r"(b[0]), "r"(b[1]));
}
__device__ __forceinline__ void cp_async16(uint32_t dst, const void* src) {
    asm volatile("cp.async.cg.shared.global [%0], [%1], 16;"
                 :: "r"(dst), "l"(src) : "memory");
}
#define CP_COMMIT() asm volatile("cp.async.commit_group;" ::: "memory")
#define CP_WAIT(n)  asm volatile("cp.async.wait_group %0;" :: "n"(n) : "memory")

__device__ __forceinline__ void split_store(__nv_bfloat16* hi, __nv_bfloat16* lo,
                                            size_t idx, float a, float b) {
    __nv_bfloat16 h0 = __float2bfloat16(a), h1 = __float2bfloat16(b);
    __nv_bfloat162 hv(h0, h1);
    __nv_bfloat162 lv(__float2bfloat16(a - __bfloat162float(h0)),
                      __float2bfloat16(b - __bfloat162float(h1)));
    *(__nv_bfloat162*)&hi[idx] = hv;
    *(__nv_bfloat162*)&lo[idx] = lv;
}
__device__ __forceinline__ void hi_store(__nv_bfloat16* hi, size_t idx,
                                         float a, float b) {
    __nv_bfloat162 hv(__float2bfloat16(a), __float2bfloat16(b));
    *(__nv_bfloat162*)&hi[idx] = hv;
}

// ---------------------------------------------------------------------------
// fp32 -> bf16 hi/lo split
// ---------------------------------------------------------------------------
__global__ __launch_bounds__(256) void precvt(const float* __restrict__ src,
                                              __nv_bfloat16* __restrict__ hi,
                                              __nv_bfloat16* __restrict__ lo,
                                              int n4)
{
    int i = blockIdx.x * 256 + threadIdx.x;
    if (i >= n4) return;
    float4 v = ((const float4*)src)[i];
    __nv_bfloat16 h0 = __float2bfloat16(v.x);
    __nv_bfloat16 h1 = __float2bfloat16(v.y);
    __nv_bfloat16 h2 = __float2bfloat16(v.z);
    __nv_bfloat16 h3 = __float2bfloat16(v.w);
    ((__nv_bfloat162*)hi)[2 * i]     = __nv_bfloat162(h0, h1);
    ((__nv_bfloat162*)hi)[2 * i + 1] = __nv_bfloat162(h2, h3);
    ((__nv_bfloat162*)lo)[2 * i] =
        __nv_bfloat162(__float2bfloat16(v.x - __bfloat162float(h0)),
                       __float2bfloat16(v.y - __bfloat162float(h1)));
    ((__nv_bfloat162*)lo)[2 * i + 1] =
        __nv_bfloat162(__float2bfloat16(v.z - __bfloat162float(h2)),
                       __float2bfloat16(v.w - __bfloat162float(h3)));
}

__global__ __launch_bounds__(256) void precvt_w(const float* __restrict__ w0,
                                                const float* __restrict__ w1,
                                                const float* __restrict__ w2,
                                                const float* __restrict__ w3,
                                                int n4)
{
    const int z = blockIdx.y;
    const float* src = (z == 0) ? w0 : (z == 1) ? w1 : (z == 2) ? w2 : w3;
    __nv_bfloat16* hi = g_whi + (size_t)z * DMODEL * DMODEL;
    __nv_bfloat16* lo = g_wlo + (size_t)z * DMODEL * DMODEL;
    int i = blockIdx.x * 256 + threadIdx.x;
    if (i >= n4) return;
    float4 v = ((const float4*)src)[i];
    __nv_bfloat16 h0 = __float2bfloat16(v.x);
    __nv_bfloat16 h1 = __float2bfloat16(v.y);
    __nv_bfloat16 h2 = __float2bfloat16(v.z);
    __nv_bfloat16 h3 = __float2bfloat16(v.w);
    ((__nv_bfloat162*)hi)[2 * i]     = __nv_bfloat162(h0, h1);
    ((__nv_bfloat162*)hi)[2 * i + 1] = __nv_bfloat162(h2, h3);
    if (z >= 2) {   // lo plane only needed for Wv / Wo
        ((__nv_bfloat162*)lo)[2 * i] =
            __nv_bfloat162(__float2bfloat16(v.x - __bfloat162float(h0)),
                           __float2bfloat16(v.y - __bfloat162float(h1)));
        ((__nv_bfloat162*)lo)[2 * i + 1] =
            __nv_bfloat162(__float2bfloat16(v.z - __bfloat162float(h2)),
                           __float2bfloat16(v.w - __bfloat162float(h3)));
    }
}

// ---------------------------------------------------------------------------
// Split-bf16 mma.sync GEMM: C[m][e] = sum_d A[m][d] * B[e][d]
// CTA 128x128, 8 warps, K slabs of 32, double-buffered cp.async, 2 CTAs/SM.
// z 0/1 (Q,K): 1-term hi*hi. z 2 (V) and is_out: 3-term split.
// ---------------------------------------------------------------------------
constexpr int GSTR = 40;
constexpr int ARR = 128 * GSTR * 2;                  // 10240 B
constexpr int STAGE = 4 * ARR;                       // 40960 B
constexpr int GEMM_SMEM = 2 * STAGE;                 // 81920 B

__global__ __launch_bounds__(256, 2)
void gemm_mma(int is_out, const float* __restrict__ bo, float* __restrict__ outp)
{
    extern __shared__ char smc[];
    const uint32_t sbase = smem_u32(smc);

    const int tid  = threadIdx.x;
    const int wid  = tid >> 5;
    const int lane = tid & 31;
    const int wy   = wid >> 2;
    const int wx   = wid & 3;

    const int m0 = blockIdx.y * 128;
    const int e0 = blockIdx.x * 128;
    const int z  = blockIdx.z;
    const bool nt3 = is_out || (z == 2);   // 3-term only for V / out proj

    const __nv_bfloat16* Ahi = is_out ? g_chi : g_xhi;
    const __nv_bfloat16* Alo = is_out ? g_clo : g_xlo;
    const int wsel = is_out ? 3 : z;
    const __nv_bfloat16* Bhi = g_whi + (size_t)wsel * DMODEL * DMODEL;
    const __nv_bfloat16* Blo = g_wlo + (size_t)wsel * DMODEL * DMODEL;

    auto stage = [&](int c, int buf) {
        const int k0 = c << 5;
        const uint32_t b = sbase + buf * STAGE;
        #pragma unroll
        for (int i = 0; i < 2; i++) {
            const int idx = i * 256 + tid;
            const int row = idx >> 2;
            const int col = (idx & 3) * 8;
            const uint32_t so = (uint32_t)(row * GSTR + col) * 2;
            const size_t gA = (size_t)(m0 + row) * DMODEL + k0 + col;
            const size_t gB = (size_t)(e0 + row) * DMODEL + k0 + col;
            cp_async16(b + 0 * ARR + so, Ahi + gA);
            cp_async16(b + 2 * ARR + so, Bhi + gB);
            if (nt3) {
                cp_async16(b + 1 * ARR + so, Alo + gA);
                cp_async16(b + 3 * ARR + so, Blo + gB);
            }
        }
    };

    const int arow  = (lane & 7) + ((lane >> 3) & 1) * 8;
    const int akoff = (lane >> 4) * 8;
    const int browp = ((lane >> 4) & 1) * 8 + (lane & 7);
    const int bkoff = ((lane >> 3) & 1) * 8;

    float acc[4][4][4] = {};

    stage(0, 0);
    CP_COMMIT();

    for (int c = 0; c < 32; c++) {
        if (c + 1 < 32) {
            stage(c + 1, (c + 1) & 1);
            CP_COMMIT();
            CP_WAIT(1);
        } else {
            CP_WAIT(0);
        }
        __syncthreads();

        const uint32_t b    = sbase + (c & 1) * STAGE;
        const uint32_t aHiB = b + 0 * ARR;
        const uint32_t aLoB = b + 1 * ARR;
        const uint32_t bHiB = b + 2 * ARR;
        const uint32_t bLoB = b + 3 * ARR;

        #pragma unroll
        for (int ks = 0; ks < 2; ks++) {
            const int k0 = ks * 16;
            if (nt3) {
                uint32_t bh[2][4], bl[2][4];
                #pragma unroll
                for (int fp = 0; fp < 2; fp++) {
                    const uint32_t off =
                        (uint32_t)((wx * 32 + fp * 16 + browp) * GSTR + k0 + bkoff) * 2;
                    ldsm_x4(bh[fp], bHiB + off);
                    ldsm_x4(bl[fp], bLoB + off);
                }
                #pragma unroll
                for (int fm = 0; fm < 4; fm++) {
                    const uint32_t off =
                        (uint32_t)((wy * 64 + fm * 16 + arow) * GSTR + k0 + akoff) * 2;
                    uint32_t ah[4], al[4];
                    ldsm_x4(ah, aHiB + off);
                    ldsm_x4(al, aLoB + off);
                    #pragma unroll
                    for (int fp = 0; fp < 2; fp++)
                        #pragma unroll
                        for (int hf = 0; hf < 2; hf++) {
                            const int fn = fp * 2 + hf;
                            mma_bf16(acc[fm][fn], ah, &bh[fp][hf * 2]);
                            mma_bf16(acc[fm][fn], al, &bh[fp][hf * 2]);
                            mma_bf16(acc[fm][fn], ah, &bl[fp][hf * 2]);
                        }
                }
            } else {
                uint32_t bh[2][4];
                #pragma unroll
                for (int fp = 0; fp < 2; fp++) {
                    const uint32_t off =
                        (uint32_t)((wx * 32 + fp * 16 + browp) * GSTR + k0 + bkoff) * 2;
                    ldsm_x4(bh[fp], bHiB + off);
                }
                #pragma unroll
                for (int fm = 0; fm < 4; fm++) {
                    const uint32_t off =
                        (uint32_t)((wy * 64 + fm * 16 + arow) * GSTR + k0 + akoff) * 2;
                    uint32_t ah[4];
                    ldsm_x4(ah, aHiB + off);
                    #pragma unroll
                    for (int fp = 0; fp < 2; fp++)
                        #pragma unroll
                        for (int hf = 0; hf < 2; hf++)
                            mma_bf16(acc[fm][fp * 2 + hf], ah, &bh[fp][hf * 2]);
                }
            }
        }
        __syncthreads();
    }

    const int r0 = lane >> 2;
    const int c0 = (lane & 3) * 2;
    #pragma unroll
    for (int fm = 0; fm < 4; fm++)
        #pragma unroll
        for (int fn = 0; fn < 4; fn++) {
            const int m = m0 + wy * 64 + fm * 16 + r0;
            const int e = e0 + wx * 32 + fn * 8 + c0;
            if (is_out) {
                const float b0v = bo[e], b1v = bo[e + 1];
                float2 v0 = make_float2(acc[fm][fn][0] + b0v, acc[fm][fn][1] + b1v);
                float2 v1 = make_float2(acc[fm][fn][2] + b0v, acc[fm][fn][3] + b1v);
                *(float2*)&outp[(size_t)m * DMODEL + e]       = v0;
                *(float2*)&outp[(size_t)(m + 8) * DMODEL + e] = v1;
            } else {
                const int h = e >> 6, dh = e & 63;
                const int bi = m >> 11, n = m & (SEQ - 1);
                size_t i0 = (((size_t)bi * HEADS + h) * SEQ + n) * DHEAD + dh;
                size_t i1 = (((size_t)bi * HEADS + h) * SEQ + n + 8) * DHEAD + dh;
                if (z == 2) {
                    split_store(g_vhi, g_vlo, i0, acc[fm][fn][0], acc[fm][fn][1]);
                    split_store(g_vhi, g_vlo, i1, acc[fm][fn][2], acc[fm][fn][3]);
                } else {
                    __nv_bfloat16* dhi = (z == 0) ? g_qhi : g_khi;
                    hi_store(dhi, i0, acc[fm][fn][0], acc[fm][fn][1]);
                    hi_store(dhi, i1, acc[fm][fn][2], acc[fm][fn][3]);
                }
            }
        }
}

// ---------------------------------------------------------------------------
// FlashAttention-2 mma.sync. QK^T hi-only (1 term); PV 3-term split.
// CTA = 128 q (8 warps x 16 rows), 64-key double-buffered tiles.
// Biggest qb scheduled first (reverse map) to trim causal tail.
// ---------------------------------------------------------------------------
constexpr int QSTR = 72;
constexpr int ATT_Q   = 128 * QSTR * 2;        // 18432 B (Q hi)
constexpr int ATT_KV1 = 64 * QSTR * 2;         // 9216 B per array
constexpr int ATT_BUF = 3 * ATT_KV1;           // 27648 B (Kh, Vh, Vl)
constexpr int ATTN_SMEM = ATT_Q + 2 * ATT_BUF; // 73728 B

__global__ __launch_bounds__(256, 2) void attn_mma()
{
    extern __shared__ char smc[];
    const uint32_t sb  = smem_u32(smc);
    const uint32_t qhB = sb;

    const int tid  = threadIdx.x;
    const int wid  = tid >> 5;
    const int lane = tid & 31;
    const int qb = gridDim.x - 1 - blockIdx.x;   // biggest first
    const int h  = blockIdx.y;
    const int bb = blockIdx.z;

    const size_t hoff = ((size_t)bb * HEADS + h) * SEQ * DHEAD;
    const __nv_bfloat16* Qh = g_qhi + hoff + (size_t)qb * 128 * DHEAD;
    const __nv_bfloat16* Kh = g_khi + hoff;
    const __nv_bfloat16* Vh = g_vhi + hoff;
    const __nv_bfloat16* Vl = g_vlo + hoff;

    auto stage_kv = [&](int kt, int buf) {
        const uint32_t base = sb + ATT_Q + buf * ATT_BUF;
        const size_t goff = (size_t)kt * 64 * DHEAD;
        #pragma unroll
        for (int i = 0; i < 2; i++) {
            int c = i * 256 + tid;
            int r = c >> 3, col = (c & 7) * 8;
            uint32_t so = (uint32_t)(r * QSTR + col) * 2;
            size_t go = goff + (size_t)r * DHEAD + col;
            cp_async16(base + 0 * ATT_KV1 + so, Kh + go);
            cp_async16(base + 1 * ATT_KV1 + so, Vh + go);
            cp_async16(base + 2 * ATT_KV1 + so, Vl + go);
        }
    };

    #pragma unroll
    for (int i = 0; i < 4; i++) {
        int c = i * 256 + tid;
        int r = c >> 3, col = (c & 7) * 8;
        uint32_t so = (uint32_t)(r * QSTR + col) * 2;
        cp_async16(qhB + so, Qh + (size_t)r * DHEAD + col);
    }
    stage_kv(0, 0);
    CP_COMMIT();
    CP_WAIT(0);
    __syncthreads();

    const int arow  = (lane & 7) + ((lane >> 3) & 1) * 8;
    const int akoff = (lane >> 4) * 8;
    const int browp = ((lane >> 4) & 1) * 8 + (lane & 7);
    const int bkoff = ((lane >> 3) & 1) * 8;
    const int vrowl = (lane & 7) + ((lane >> 3) & 1) * 8;
    const int vcolp = ((lane >> 4) & 1) * 8;

    const int g  = lane >> 2;
    const int tg = lane & 3;
    const int rowbase = qb * 128 + wid * 16;

    float o[8][4] = {};
    float mrow0 = -INFINITY, mrow1 = -INFINITY;
    float lrow0 = 0.f, lrow1 = 0.f;

    const int ktmax = 2 * qb + 1;
    for (int kt = 0; kt <= ktmax; kt++) {
        __syncthreads();
        if (kt < ktmax) {
            stage_kv(kt + 1, (kt + 1) & 1);
            CP_COMMIT();
            CP_WAIT(1);
        } else {
            CP_WAIT(0);
        }
        __syncthreads();

        const uint32_t kB = sb + ATT_Q + (kt & 1) * ATT_BUF;

        // S = Qhi @ Khi^T (hi-only)
        float s[8][4] = {};
        #pragma unroll
        for (int ks = 0; ks < 4; ks++) {
            uint32_t qoff = (uint32_t)((wid * 16 + arow) * QSTR + ks * 16 + akoff) * 2;
            uint32_t qh4[4];
            ldsm_x4(qh4, qhB + qoff);
            #pragma unroll
            for (int fp = 0; fp < 4; fp++) {
                uint32_t off =
                    (uint32_t)((fp * 16 + browp) * QSTR + ks * 16 + bkoff) * 2;
                uint32_t bh4[4];
                ldsm_x4(bh4, kB + off);
                mma_bf16(s[fp * 2 + 0], qh4, &bh4[0]);
                mma_bf16(s[fp * 2 + 1], qh4, &bh4[2]);
            }
        }

        // scale + causal mask
        const bool needmask = (kt * 64 + 63 > rowbase);
        const int r0g = rowbase + g, r1g = r0g + 8;
        #pragma unroll
        for (int fn = 0; fn < 8; fn++) {
            const int cbase = kt * 64 + fn * 8 + tg * 2;
            float v0 = s[fn][0] * SCALE, v1 = s[fn][1] * SCALE;
            float v2 = s[fn][2] * SCALE, v3 = s[fn][3] * SCALE;
            if (needmask) {
                if (cbase     > r0g) v0 = -INFINITY;
                if (cbase + 1 > r0g) v1 = -INFINITY;
                if (cbase     > r1g) v2 = -INFINITY;
                if (cbase + 1 > r1g) v3 = -INFINITY;
            }
            s[fn][0] = v0; s[fn][1] = v1; s[fn][2] = v2; s[fn][3] = v3;
        }

        float mx0 = -INFINITY, mx1 = -INFINITY;
        #pragma unroll
        for (int fn = 0; fn < 8; fn++) {
            mx0 = fmaxf(mx0, fmaxf(s[fn][0], s[fn][1]));
            mx1 = fmaxf(mx1, fmaxf(s[fn][2], s[fn][3]));
        }
        mx0 = fmaxf(mx0, __shfl_xor_sync(0xffffffffu, mx0, 1));
        mx0 = fmaxf(mx0, __shfl_xor_sync(0xffffffffu, mx0, 2));
        mx1 = fmaxf(mx1, __shfl_xor_sync(0xffffffffu, mx1, 1));
        mx1 = fmaxf(mx1, __shfl_xor_sync(0xffffffffu, mx1, 2));

        const float mn0 = fmaxf(mrow0, mx0);
        const float mn1 = fmaxf(mrow1, mx1);
        const float al0 = __expf(mrow0 - mn0);
        const float al1 = __expf(mrow1 - mn1);

        float rs0 = 0.f, rs1 = 0.f;
        #pragma unroll
        for (int fn = 0; fn < 8; fn++) {
            float p0 = __expf(s[fn][0] - mn0);
            float p1 = __expf(s[fn][1] - mn0);
            float p2 = __expf(s[fn][2] - mn1);
            float p3 = __expf(s[fn][3] - mn1);
            s[fn][0] = p0; s[fn][1] = p1; s[fn][2] = p2; s[fn][3] = p3;
            rs0 += p0 + p1;
            rs1 += p2 + p3;
        }
        rs0 += __shfl_xor_sync(0xffffffffu, rs0, 1);
        rs0 += __shfl_xor_sync(0xffffffffu, rs0, 2);
        rs1 += __shfl_xor_sync(0xffffffffu, rs1, 1);
        rs1 += __shfl_xor_sync(0xffffffffu, rs1, 2);

        lrow0 = lrow0 * al0 + rs0;
        lrow1 = lrow1 * al1 + rs1;
        mrow0 = mn0; mrow1 = mn1;

        #pragma unroll
        for (int fn = 0; fn < 8; fn++) {
            o[fn][0] *= al0; o[fn][1] *= al0;
            o[fn][2] *= al1; o[fn][3] *= al1;
        }

        // O += P @ V (P split hi/lo, V split hi/lo, 3 terms)
        const uint32_t vB = kB + 1 * ATT_KV1;
        #pragma unroll
        for (int kg = 0; kg < 4; kg++) {
            uint32_t ph[4], pl[4];
            #pragma unroll
            for (int half = 0; half < 2; half++) {
                const int f = 2 * kg + half;
                float a0 = s[f][0], a1 = s[f][1], a2 = s[f][2], a3 = s[f][3];
                __nv_bfloat16 h0 = __float2bfloat16(a0), h1 = __float2bfloat16(a1);
                __nv_bfloat16 h2 = __float2bfloat16(a2), h3 = __float2bfloat16(a3);
                __nv_bfloat162 t0(h0, h1), t1(h2, h3);
                ph[2 * half]     = *(uint32_t*)&t0;
                ph[2 * half + 1] = *(uint32_t*)&t1;
                __nv_bfloat162 u0(__float2bfloat16(a0 - __bfloat162float(h0)),
                                  __float2bfloat16(a1 - __bfloat162float(h1)));
                __nv_bfloat162 u1(__float2bfloat16(a2 - __bfloat162float(h2)),
                                  __float2bfloat16(a3 - __bfloat162float(h3)));
                pl[2 * half]     = *(uint32_t*)&u0;
                pl[2 * half + 1] = *(uint32_t*)&u1;
            }
            const int vrow = kg * 16 + vrowl;
            #pragma unroll
            for (int fp = 0; fp < 4; fp++) {
                uint32_t off = (uint32_t)(vrow * QSTR + fp * 16 + vcolp) * 2;
                uint32_t vh4[4], vl4[4];
                ldsm_x4t(vh4, vB + off);
                ldsm_x4t(vl4, vB + ATT_KV1 + off);
                #pragma unroll
                for (int hf = 0; hf < 2; hf++) {
                    const int fn = fp * 2 + hf;
                    mma_bf16(o[fn], ph, &vh4[hf * 2]);
                    mma_bf16(o[fn], pl, &vh4[hf * 2]);
                    mma_bf16(o[fn], ph, &vl4[hf * 2]);
                }
            }
        }
    }

    const float inv0 = 1.f / lrow0;
    const float inv1 = 1.f / lrow1;
    const int q0 = rowbase + g;
    const int q1 = q0 + 8;
    #pragma unroll
    for (int fn = 0; fn < 8; fn++) {
        const int e = h * 64 + fn * 8 + tg * 2;
        size_t i0 = (size_t)(bb * SEQ + q0) * DMODEL + e;
        size_t i1 = (size_t)(bb * SEQ + q1) * DMODEL + e;
        split_store(g_chi, g_clo, i0, o[fn][0] * inv0, o[fn][1] * inv0);
        split_store(g_chi, g_clo, i1, o[fn][2] * inv1, o[fn][3] * inv1);
    }
}

// ---------------------------------------------------------------------------
extern "C" void kernel_launch(void* const* d_in, const int* in_sizes, int n_in,
                              void* d_out, int out_size)
{
    (void)in_sizes; (void)n_in; (void)out_size;
    const float* x  = (const float*)d_in[0];
    const float* Wq = (const float*)d_in[1];
    const float* Wk = (const float*)d_in[2];
    const float* Wv = (const float*)d_in[3];
    const float* Wo = (const float*)d_in[4];
    const float* bo = (const float*)d_in[5];
    float* out = (float*)d_out;

    cudaFuncSetAttribute(gemm_mma, cudaFuncAttributeMaxDynamicSharedMemorySize,
                         GEMM_SMEM);
    cudaFuncSetAttribute(attn_mma, cudaFuncAttributeMaxDynamicSharedMemorySize,
                         ATTN_SMEM);

    __nv_bfloat16 *xhi, *xlo;
    cudaGetSymbolAddress((void**)&xhi, g_xhi);
    cudaGetSymbolAddress((void**)&xlo, g_xlo);

    const int NX4 = MTOT * DMODEL / 4;
    const int NW4 = DMODEL * DMODEL / 4;

    precvt<<<NX4 / 256, 256>>>(x, xhi, xlo, NX4);
    precvt_w<<<dim3(NW4 / 256, 4), 256>>>(Wq, Wk, Wv, Wo, NW4);

    gemm_mma<<<dim3(DMODEL / 128, MTOT / 128, 3), 256, GEMM_SMEM>>>(0, nullptr, nullptr);
    attn_mma<<<dim3(SEQ / 128, HEADS, BATCH), 256, ATTN_SMEM>>>();
    gemm_mma<<<dim3(DMODEL / 128, MTOT / 128, 1), 256, GEMM_SMEM>>>(1, bo, out);
}

// round 9
// speedup vs baseline: 5.8638x; 1.2821x over previous
#include <cuda_runtime.h>
#include <cuda_bf16.h>
#include <cuda_fp16.h>
#include <math.h>
#include <stdint.h>

// Problem constants
constexpr int BATCH = 2;
constexpr int SEQ   = 2048;
constexpr int DMODEL= 1024;
constexpr int HEADS = 16;
constexpr int DHEAD = 64;
constexpr int MTOT  = BATCH * SEQ;           // 4096
// (1/sqrt(2048)) * log2(e) -- softmax runs in base-2 domain
constexpr float SCALE2 = 0.0318793566f;

// Scratch (allocation-free rule: __device__ globals).
__device__ __nv_bfloat16 g_xhi[MTOT * DMODEL];
__device__ __nv_bfloat16 g_xlo[MTOT * DMODEL];
__device__ __nv_bfloat16 g_whi[4 * DMODEL * DMODEL];
__device__ __nv_bfloat16 g_wlo[4 * DMODEL * DMODEL];
__device__ __half        g_q[BATCH * HEADS * SEQ * DHEAD];   // fp16
__device__ __half        g_k[BATCH * HEADS * SEQ * DHEAD];   // fp16
__device__ __half        g_v[BATCH * HEADS * SEQ * DHEAD];   // fp16 (3-term accurate)
__device__ __nv_bfloat16 g_chi[MTOT * DMODEL];
__device__ __nv_bfloat16 g_clo[MTOT * DMODEL];

// ---------------------------------------------------------------------------
// Portable tensor-core helpers (sm_80+ ISA)
// ---------------------------------------------------------------------------
__device__ __forceinline__ uint32_t smem_u32(const void* p) {
    uint32_t a;
    asm("{ .reg .u64 t; cvta.to.shared.u64 t, %1; cvt.u32.u64 %0, t; }"
        : "=r"(a) : "l"(p));
    return a;
}
__device__ __forceinline__ void ldsm_x4(uint32_t r[4], uint32_t a) {
    asm volatile("ldmatrix.sync.aligned.m8n8.x4.shared.b16 {%0,%1,%2,%3}, [%4];"
                 : "=r"(r[0]), "=r"(r[1]), "=r"(r[2]), "=r"(r[3]) : "r"(a));
}
__device__ __forceinline__ void ldsm_x4t(uint32_t r[4], uint32_t a) {
    asm volatile("ldmatrix.sync.aligned.m8n8.x4.trans.shared.b16 {%0,%1,%2,%3}, [%4];"
                 : "=r"(r[0]), "=r"(r[1]), "=r"(r[2]), "=r"(r[3]) : "r"(a));
}
__device__ __forceinline__ void mma_bf16(float d[4], const uint32_t a[4],
                                         const uint32_t b[2]) {
    asm volatile(
        "mma.sync.aligned.m16n8k16.row.col.f32.bf16.bf16.f32 "
        "{%0,%1,%2,%3}, {%4,%5,%6,%7}, {%8,%9}, {%0,%1,%2,%3};"
        : "+f"(d[0]), "+f"(d[1]), "+f"(d[2]), "+f"(d[3])
        : "r"(a[0]), "r"(a[1]), "r"(a[2]), "r"(a[3]), "r"(b[0]), "r"(b[1]));
}
__device__ __forceinline__ void mma_f16(float d[4], const uint32_t a[4],
                                        const uint32_t b[2]) {
    asm volatile(
        "mma.sync.aligned.m16n8k16.row.col.f32.f16.f16.f32 "
        "{%0,%1,%2,%3}, {%4,%5,%6,%7}, {%8,%9}, {%0,%1,%2,%3};"
        : "+f"(d[0]), "+f"(d[1]), "+f"(d[2]), "+f"(d[3])
        : "r"(a[0]), "r"(a[1]), "r"(a[2]), "r"(a[3]), "r"(b[0]), "r"(b[1]));
}
__device__ __forceinline__ void cp_async16(uint32_t dst, const void* src) {
    asm volatile("cp.async.cg.shared.global [%0], [%1], 16;"
                 :: "r"(dst), "l"(src) : "memory");
}
#define CP_COMMIT() asm volatile("cp.async.commit_group;" ::: "memory")
#define CP_WAIT(n)  asm volatile("cp.async.wait_group %0;" :: "n"(n) : "memory")

__device__ __forceinline__ float ex2f(float x) {
    float r;
    asm("ex2.approx.f32 %0, %1;" : "=f"(r) : "f"(x));
    return r;
}
__device__ __forceinline__ void split_store(__nv_bfloat16* hi, __nv_bfloat16* lo,
                                            size_t idx, float a, float b) {
    __nv_bfloat16 h0 = __float2bfloat16(a), h1 = __float2bfloat16(b);
    __nv_bfloat162 hv(h0, h1);
    __nv_bfloat162 lv(__float2bfloat16(a - __bfloat162float(h0)),
                      __float2bfloat16(b - __bfloat162float(h1)));
    *(__nv_bfloat162*)&hi[idx] = hv;
    *(__nv_bfloat162*)&lo[idx] = lv;
}
__device__ __forceinline__ void h2_store(__half* p, size_t idx, float a, float b) {
    *(__half2*)&p[idx] = __floats2half2_rn(a, b);
}

// ---------------------------------------------------------------------------
// fp32 -> bf16 hi/lo split
// ---------------------------------------------------------------------------
__global__ __launch_bounds__(256) void precvt(const float* __restrict__ src,
                                              __nv_bfloat16* __restrict__ hi,
                                              __nv_bfloat16* __restrict__ lo,
                                              int n4)
{
    int i = blockIdx.x * 256 + threadIdx.x;
    if (i >= n4) return;
    float4 v = ((const float4*)src)[i];
    __nv_bfloat16 h0 = __float2bfloat16(v.x);
    __nv_bfloat16 h1 = __float2bfloat16(v.y);
    __nv_bfloat16 h2 = __float2bfloat16(v.z);
    __nv_bfloat16 h3 = __float2bfloat16(v.w);
    ((__nv_bfloat162*)hi)[2 * i]     = __nv_bfloat162(h0, h1);
    ((__nv_bfloat162*)hi)[2 * i + 1] = __nv_bfloat162(h2, h3);
    ((__nv_bfloat162*)lo)[2 * i] =
        __nv_bfloat162(__float2bfloat16(v.x - __bfloat162float(h0)),
                       __float2bfloat16(v.y - __bfloat162float(h1)));
    ((__nv_bfloat162*)lo)[2 * i + 1] =
        __nv_bfloat162(__float2bfloat16(v.z - __bfloat162float(h2)),
                       __float2bfloat16(v.w - __bfloat162float(h3)));
}

__global__ __launch_bounds__(256) void precvt_w(const float* __restrict__ w0,
                                                const float* __restrict__ w1,
                                                const float* __restrict__ w2,
                                                const float* __restrict__ w3,
                                                int n4)
{
    const int z = blockIdx.y;
    const float* src = (z == 0) ? w0 : (z == 1) ? w1 : (z == 2) ? w2 : w3;
    __nv_bfloat16* hi = g_whi + (size_t)z * DMODEL * DMODEL;
    __nv_bfloat16* lo = g_wlo + (size_t)z * DMODEL * DMODEL;
    int i = blockIdx.x * 256 + threadIdx.x;
    if (i >= n4) return;
    float4 v = ((const float4*)src)[i];
    __nv_bfloat16 h0 = __float2bfloat16(v.x);
    __nv_bfloat16 h1 = __float2bfloat16(v.y);
    __nv_bfloat16 h2 = __float2bfloat16(v.z);
    __nv_bfloat16 h3 = __float2bfloat16(v.w);
    ((__nv_bfloat162*)hi)[2 * i]     = __nv_bfloat162(h0, h1);
    ((__nv_bfloat162*)hi)[2 * i + 1] = __nv_bfloat162(h2, h3);
    if (z >= 2) {   // lo plane only needed for Wv / Wo
        ((__nv_bfloat162*)lo)[2 * i] =
            __nv_bfloat162(__float2bfloat16(v.x - __bfloat162float(h0)),
                           __float2bfloat16(v.y - __bfloat162float(h1)));
        ((__nv_bfloat162*)lo)[2 * i + 1] =
            __nv_bfloat162(__float2bfloat16(v.z - __bfloat162float(h2)),
                           __float2bfloat16(v.w - __bfloat162float(h3)));
    }
}

// ---------------------------------------------------------------------------
// Split-bf16 mma.sync GEMM: C[m][e] = sum_d A[m][d] * B[e][d]
// CTA 128x128, 8 warps, K slabs of 32, double-buffered cp.async, 2 CTAs/SM.
// z 0/1 (Q,K): 1-term hi*hi, fp16 store. z 2 (V): 3-term, fp16 store.
// is_out: 3-term, fp32 out + bias.
// ---------------------------------------------------------------------------
constexpr int GSTR = 40;
constexpr int ARR = 128 * GSTR * 2;                  // 10240 B
constexpr int STAGE = 4 * ARR;                       // 40960 B
constexpr int GEMM_SMEM = 2 * STAGE;                 // 81920 B

__global__ __launch_bounds__(256, 2)
void gemm_mma(int is_out, const float* __restrict__ bo, float* __restrict__ outp)
{
    extern __shared__ char smc[];
    const uint32_t sbase = smem_u32(smc);

    const int tid  = threadIdx.x;
    const int wid  = tid >> 5;
    const int lane = tid & 31;
    const int wy   = wid >> 2;
    const int wx   = wid & 3;

    const int m0 = blockIdx.y * 128;
    const int e0 = blockIdx.x * 128;
    const int z  = blockIdx.z;
    const bool nt3 = is_out || (z == 2);   // 3-term only for V / out proj

    const __nv_bfloat16* Ahi = is_out ? g_chi : g_xhi;
    const __nv_bfloat16* Alo = is_out ? g_clo : g_xlo;
    const int wsel = is_out ? 3 : z;
    const __nv_bfloat16* Bhi = g_whi + (size_t)wsel * DMODEL * DMODEL;
    const __nv_bfloat16* Blo = g_wlo + (size_t)wsel * DMODEL * DMODEL;

    auto stage = [&](int c, int buf) {
        const int k0 = c << 5;
        const uint32_t b = sbase + buf * STAGE;
        #pragma unroll
        for (int i = 0; i < 2; i++) {
            const int idx = i * 256 + tid;
            const int row = idx >> 2;
            const int col = (idx & 3) * 8;
            const uint32_t so = (uint32_t)(row * GSTR + col) * 2;
            const size_t gA = (size_t)(m0 + row) * DMODEL + k0 + col;
            const size_t gB = (size_t)(e0 + row) * DMODEL + k0 + col;
            cp_async16(b + 0 * ARR + so, Ahi + gA);
            cp_async16(b + 2 * ARR + so, Bhi + gB);
            if (nt3) {
                cp_async16(b + 1 * ARR + so, Alo + gA);
                cp_async16(b + 3 * ARR + so, Blo + gB);
            }
        }
    };

    const int arow  = (lane & 7) + ((lane >> 3) & 1) * 8;
    const int akoff = (lane >> 4) * 8;
    const int browp = ((lane >> 4) & 1) * 8 + (lane & 7);
    const int bkoff = ((lane >> 3) & 1) * 8;

    float acc[4][4][4] = {};

    stage(0, 0);
    CP_COMMIT();

    for (int c = 0; c < 32; c++) {
        if (c + 1 < 32) {
            stage(c + 1, (c + 1) & 1);
            CP_COMMIT();
            CP_WAIT(1);
        } else {
            CP_WAIT(0);
        }
        __syncthreads();

        const uint32_t b    = sbase + (c & 1) * STAGE;
        const uint32_t aHiB = b + 0 * ARR;
        const uint32_t aLoB = b + 1 * ARR;
        const uint32_t bHiB = b + 2 * ARR;
        const uint32_t bLoB = b + 3 * ARR;

        #pragma unroll
        for (int ks = 0; ks < 2; ks++) {
            const int k0 = ks * 16;
            if (nt3) {
                uint32_t bh[2][4], bl[2][4];
                #pragma unroll
                for (int fp = 0; fp < 2; fp++) {
                    const uint32_t off =
                        (uint32_t)((wx * 32 + fp * 16 + browp) * GSTR + k0 + bkoff) * 2;
                    ldsm_x4(bh[fp], bHiB + off);
                    ldsm_x4(bl[fp], bLoB + off);
                }
                #pragma unroll
                for (int fm = 0; fm < 4; fm++) {
                    const uint32_t off =
                        (uint32_t)((wy * 64 + fm * 16 + arow) * GSTR + k0 + akoff) * 2;
                    uint32_t ah[4], al[4];
                    ldsm_x4(ah, aHiB + off);
                    ldsm_x4(al, aLoB + off);
                    #pragma unroll
                    for (int fp = 0; fp < 2; fp++)
                        #pragma unroll
                        for (int hf = 0; hf < 2; hf++) {
                            const int fn = fp * 2 + hf;
                            mma_bf16(acc[fm][fn], ah, &bh[fp][hf * 2]);
                            mma_bf16(acc[fm][fn], al, &bh[fp][hf * 2]);
                            mma_bf16(acc[fm][fn], ah, &bl[fp][hf * 2]);
                        }
                }
            } else {
                uint32_t bh[2][4];
                #pragma unroll
                for (int fp = 0; fp < 2; fp++) {
                    const uint32_t off =
                        (uint32_t)((wx * 32 + fp * 16 + browp) * GSTR + k0 + bkoff) * 2;
                    ldsm_x4(bh[fp], bHiB + off);
                }
                #pragma unroll
                for (int fm = 0; fm < 4; fm++) {
                    const uint32_t off =
                        (uint32_t)((wy * 64 + fm * 16 + arow) * GSTR + k0 + akoff) * 2;
                    uint32_t ah[4];
                    ldsm_x4(ah, aHiB + off);
                    #pragma unroll
                    for (int fp = 0; fp < 2; fp++)
                        #pragma unroll
                        for (int hf = 0; hf < 2; hf++)
                            mma_bf16(acc[fm][fp * 2 + hf], ah, &bh[fp][hf * 2]);
                }
            }
        }
        __syncthreads();
    }

    const int r0 = lane >> 2;
    const int c0 = (lane & 3) * 2;
    #pragma unroll
    for (int fm = 0; fm < 4; fm++)
        #pragma unroll
        for (int fn = 0; fn < 4; fn++) {
            const int m = m0 + wy * 64 + fm * 16 + r0;
            const int e = e0 + wx * 32 + fn * 8 + c0;
            if (is_out) {
                const float b0v = bo[e], b1v = bo[e + 1];
                float2 v0 = make_float2(acc[fm][fn][0] + b0v, acc[fm][fn][1] + b1v);
                float2 v1 = make_float2(acc[fm][fn][2] + b0v, acc[fm][fn][3] + b1v);
                *(float2*)&outp[(size_t)m * DMODEL + e]       = v0;
                *(float2*)&outp[(size_t)(m + 8) * DMODEL + e] = v1;
            } else {
                __half* dst = (z == 0) ? g_q : (z == 1) ? g_k : g_v;
                const int h = e >> 6, dh = e & 63;
                const int bi = m >> 11, n = m & (SEQ - 1);
                size_t i0 = (((size_t)bi * HEADS + h) * SEQ + n) * DHEAD + dh;
                size_t i1 = (((size_t)bi * HEADS + h) * SEQ + n + 8) * DHEAD + dh;
                h2_store(dst, i0, acc[fm][fn][0], acc[fm][fn][1]);
                h2_store(dst, i1, acc[fm][fn][2], acc[fm][fn][3]);
            }
        }
}

// ---------------------------------------------------------------------------
// FlashAttention-2 mma.sync, all-fp16 operands.
// QK^T: 1-term fp16. PV: 1-term fp16 (P fp16, V fp16-accurate).
// CTA = 128 q (8 warps x 16 rows), 64-key double-buffered tiles.
// 1-D grid; longest (largest qb) CTAs scheduled first.
// ---------------------------------------------------------------------------
constexpr int QSTR = 72;
constexpr int ATT_Q   = 128 * QSTR * 2;        // 18432 B (Q)
constexpr int ATT_KV1 = 64 * QSTR * 2;         // 9216 B per array
constexpr int ATT_BUF = 2 * ATT_KV1;           // 18432 B (K, V)
constexpr int ATTN_SMEM = ATT_Q + 2 * ATT_BUF; // 55296 B

__global__ __launch_bounds__(256, 2) void attn_mma()
{
    extern __shared__ char smc[];
    const uint32_t sb  = smem_u32(smc);
    const uint32_t qB  = sb;

    const int tid  = threadIdx.x;
    const int wid  = tid >> 5;
    const int lane = tid & 31;
    const int bid  = blockIdx.x;
    const int qb = (SEQ / 128 - 1) - (bid >> 5);   // longest first
    const int hb = bid & 31;
    const int h  = hb & (HEADS - 1);
    const int bb = hb >> 4;

    const size_t hoff = ((size_t)bb * HEADS + h) * SEQ * DHEAD;
    const __half* Qg = g_q + hoff + (size_t)qb * 128 * DHEAD;
    const __half* Kg = g_k + hoff;
    const __half* Vg = g_v + hoff;

    auto stage_kv = [&](int kt, int buf) {
        const uint32_t base = sb + ATT_Q + buf * ATT_BUF;
        const size_t goff = (size_t)kt * 64 * DHEAD;
        #pragma unroll
        for (int i = 0; i < 2; i++) {
            int c = i * 256 + tid;
            int r = c >> 3, col = (c & 7) * 8;
            uint32_t so = (uint32_t)(r * QSTR + col) * 2;
            size_t go = goff + (size_t)r * DHEAD + col;
            cp_async16(base + 0 * ATT_KV1 + so, Kg + go);
            cp_async16(base + 1 * ATT_KV1 + so, Vg + go);
        }
    };

    #pragma unroll
    for (int i = 0; i < 4; i++) {
        int c = i * 256 + tid;
        int r = c >> 3, col = (c & 7) * 8;
        uint32_t so = (uint32_t)(r * QSTR + col) * 2;
        cp_async16(qB + so, Qg + (size_t)r * DHEAD + col);
    }
    stage_kv(0, 0);
    CP_COMMIT();
    CP_WAIT(0);
    __syncthreads();

    const int arow  = (lane & 7) + ((lane >> 3) & 1) * 8;
    const int akoff = (lane >> 4) * 8;
    const int browp = ((lane >> 4) & 1) * 8 + (lane & 7);
    const int bkoff = ((lane >> 3) & 1) * 8;
    const int vrowl = (lane & 7) + ((lane >> 3) & 1) * 8;
    const int vcolp = ((lane >> 4) & 1) * 8;

    const int g  = lane >> 2;
    const int tg = lane & 3;
    const int rowbase = qb * 128 + wid * 16;

    float o[8][4] = {};
    float mrow0 = -INFINITY, mrow1 = -INFINITY;
    float lrow0 = 0.f, lrow1 = 0.f;

    const int ktmax = 2 * qb + 1;
    for (int kt = 0; kt <= ktmax; kt++) {
        __syncthreads();
        if (kt < ktmax) {
            stage_kv(kt + 1, (kt + 1) & 1);
            CP_COMMIT();
            CP_WAIT(1);
        } else {
            CP_WAIT(0);
        }
        __syncthreads();

        const uint32_t kB = sb + ATT_Q + (kt & 1) * ATT_BUF;

        // S = Q @ K^T (fp16, 1 term)
        float s[8][4] = {};
        #pragma unroll
        for (int ks = 0; ks < 4; ks++) {
            uint32_t qoff = (uint32_t)((wid * 16 + arow) * QSTR + ks * 16 + akoff) * 2;
            uint32_t q4[4];
            ldsm_x4(q4, qB + qoff);
            #pragma unroll
            for (int fp = 0; fp < 4; fp++) {
                uint32_t off =
                    (uint32_t)((fp * 16 + browp) * QSTR + ks * 16 + bkoff) * 2;
                uint32_t b4[4];
                ldsm_x4(b4, kB + off);
                mma_f16(s[fp * 2 + 0], q4, &b4[0]);
                mma_f16(s[fp * 2 + 1], q4, &b4[2]);
            }
        }

        // scale (base-2 domain) + causal mask
        const bool needmask = (kt * 64 + 63 > rowbase);
        const int r0g = rowbase + g, r1g = r0g + 8;
        #pragma unroll
        for (int fn = 0; fn < 8; fn++) {
            const int cbase = kt * 64 + fn * 8 + tg * 2;
            float v0 = s[fn][0] * SCALE2, v1 = s[fn][1] * SCALE2;
            float v2 = s[fn][2] * SCALE2, v3 = s[fn][3] * SCALE2;
            if (needmask) {
                if (cbase     > r0g) v0 = -INFINITY;
                if (cbase + 1 > r0g) v1 = -INFINITY;
                if (cbase     > r1g) v2 = -INFINITY;
                if (cbase + 1 > r1g) v3 = -INFINITY;
            }
            s[fn][0] = v0; s[fn][1] = v1; s[fn][2] = v2; s[fn][3] = v3;
        }

        float mx0 = -INFINITY, mx1 = -INFINITY;
        #pragma unroll
        for (int fn = 0; fn < 8; fn++) {
            mx0 = fmaxf(mx0, fmaxf(s[fn][0], s[fn][1]));
            mx1 = fmaxf(mx1, fmaxf(s[fn][2], s[fn][3]));
        }
        mx0 = fmaxf(mx0, __shfl_xor_sync(0xffffffffu, mx0, 1));
        mx0 = fmaxf(mx0, __shfl_xor_sync(0xffffffffu, mx0, 2));
        mx1 = fmaxf(mx1, __shfl_xor_sync(0xffffffffu, mx1, 1));
        mx1 = fmaxf(mx1, __shfl_xor_sync(0xffffffffu, mx1, 2));

        const float mn0 = fmaxf(mrow0, mx0);
        const float mn1 = fmaxf(mrow1, mx1);
        const float al0 = ex2f(mrow0 - mn0);
        const float al1 = ex2f(mrow1 - mn1);

        float rs0 = 0.f, rs1 = 0.f;
        #pragma unroll
        for (int fn = 0; fn < 8; fn++) {
            float p0 = ex2f(s[fn][0] - mn0);
            float p1 = ex2f(s[fn][1] - mn0);
            float p2 = ex2f(s[fn][2] - mn1);
            float p3 = ex2f(s[fn][3] - mn1);
            s[fn][0] = p0; s[fn][1] = p1; s[fn][2] = p2; s[fn][3] = p3;
            rs0 += p0 + p1;
            rs1 += p2 + p3;
        }
        rs0 += __shfl_xor_sync(0xffffffffu, rs0, 1);
        rs0 += __shfl_xor_sync(0xffffffffu, rs0, 2);
        rs1 += __shfl_xor_sync(0xffffffffu, rs1, 1);
        rs1 += __shfl_xor_sync(0xffffffffu, rs1, 2);

        lrow0 = lrow0 * al0 + rs0;
        lrow1 = lrow1 * al1 + rs1;
        mrow0 = mn0; mrow1 = mn1;

        #pragma unroll
        for (int fn = 0; fn < 8; fn++) {
            o[fn][0] *= al0; o[fn][1] *= al0;
            o[fn][2] *= al1; o[fn][3] *= al1;
        }

        // O += P @ V (fp16, 1 term)
        const uint32_t vB = kB + 1 * ATT_KV1;
        #pragma unroll
        for (int kg = 0; kg < 4; kg++) {
            uint32_t ph[4];
            #pragma unroll
            for (int half = 0; half < 2; half++) {
                const int f = 2 * kg + half;
                __half2 t0 = __floats2half2_rn(s[f][0], s[f][1]);
                __half2 t1 = __floats2half2_rn(s[f][2], s[f][3]);
                ph[2 * half]     = *(uint32_t*)&t0;
                ph[2 * half + 1] = *(uint32_t*)&t1;
            }
            const int vrow = kg * 16 + vrowl;
            #pragma unroll
            for (int fp = 0; fp < 4; fp++) {
                uint32_t off = (uint32_t)(vrow * QSTR + fp * 16 + vcolp) * 2;
                uint32_t v4[4];
                ldsm_x4t(v4, vB + off);
                mma_f16(o[fp * 2 + 0], ph, &v4[0]);
                mma_f16(o[fp * 2 + 1], ph, &v4[2]);
            }
        }
    }

    const float inv0 = 1.f / lrow0;
    const float inv1 = 1.f / lrow1;
    const int q0 = rowbase + g;
    const int q1 = q0 + 8;
    #pragma unroll
    for (int fn = 0; fn < 8; fn++) {
        const int e = h * 64 + fn * 8 + tg * 2;
        size_t i0 = (size_t)(bb * SEQ + q0) * DMODEL + e;
        size_t i1 = (size_t)(bb * SEQ + q1) * DMODEL + e;
        split_store(g_chi, g_clo, i0, o[fn][0] * inv0, o[fn][1] * inv0);
        split_store(g_chi, g_clo, i1, o[fn][2] * inv1, o[fn][3] * inv1);
    }
}

// ---------------------------------------------------------------------------
extern "C" void kernel_launch(void* const* d_in, const int* in_sizes, int n_in,
                              void* d_out, int out_size)
{
    (void)in_sizes; (void)n_in; (void)out_size;
    const float* x  = (const float*)d_in[0];
    const float* Wq = (const float*)d_in[1];
    const float* Wk = (const float*)d_in[2];
    const float* Wv = (const float*)d_in[3];
    const float* Wo = (const float*)d_in[4];
    const float* bo = (const float*)d_in[5];
    float* out = (float*)d_out;

    cudaFuncSetAttribute(gemm_mma, cudaFuncAttributeMaxDynamicSharedMemorySize,
                         GEMM_SMEM);
    cudaFuncSetAttribute(attn_mma, cudaFuncAttributeMaxDynamicSharedMemorySize,
                         ATTN_SMEM);

    __nv_bfloat16 *xhi, *xlo;
    cudaGetSymbolAddress((void**)&xhi, g_xhi);
    cudaGetSymbolAddress((void**)&xlo, g_xlo);

    const int NX4 = MTOT * DMODEL / 4;
    const int NW4 = DMODEL * DMODEL / 4;

    precvt<<<NX4 / 256, 256>>>(x, xhi, xlo, NX4);
    precvt_w<<<dim3(NW4 / 256, 4), 256>>>(Wq, Wk, Wv, Wo, NW4);

    gemm_mma<<<dim3(DMODEL / 128, MTOT / 128, 3), 256, GEMM_SMEM>>>(0, nullptr, nullptr);
    attn_mma<<<(SEQ / 128) * HEADS * BATCH, 256, ATTN_SMEM>>>();
    gemm_mma<<<dim3(DMODEL / 128, MTOT / 128, 1), 256, GEMM_SMEM>>>(1, bo, out);
}

// round 10
// speedup vs baseline: 7.2420x; 1.2350x over previous
#include <cuda_runtime.h>
#include <cuda_fp16.h>
#include <math.h>
#include <stdint.h>

// Problem constants
constexpr int BATCH = 2;
constexpr int SEQ   = 2048;
constexpr int DMODEL= 1024;
constexpr int HEADS = 16;
constexpr int DHEAD = 64;
constexpr int MTOT  = BATCH * SEQ;           // 4096
// (1/sqrt(2048)) * log2(e) -- softmax runs in base-2 domain
constexpr float SCALE2 = 0.0318793566f;

// Scratch (allocation-free rule: __device__ globals). All fp16.
__device__ __half g_xh[MTOT * DMODEL];
__device__ __half g_xl[MTOT * DMODEL];
__device__ __half g_w [4 * DMODEL * DMODEL];
__device__ __half g_q [BATCH * HEADS * SEQ * DHEAD];
__device__ __half g_k [BATCH * HEADS * SEQ * DHEAD];
__device__ __half g_v [BATCH * HEADS * SEQ * DHEAD];
__device__ __half g_ch[MTOT * DMODEL];
__device__ __half g_cl[MTOT * DMODEL];

// ---------------------------------------------------------------------------
// Portable tensor-core helpers (sm_80+ ISA)
// ---------------------------------------------------------------------------
__device__ __forceinline__ uint32_t smem_u32(const void* p) {
    uint32_t a;
    asm("{ .reg .u64 t; cvta.to.shared.u64 t, %1; cvt.u32.u64 %0, t; }"
        : "=r"(a) : "l"(p));
    return a;
}
__device__ __forceinline__ void ldsm_x4(uint32_t r[4], uint32_t a) {
    asm volatile("ldmatrix.sync.aligned.m8n8.x4.shared.b16 {%0,%1,%2,%3}, [%4];"
                 : "=r"(r[0]), "=r"(r[1]), "=r"(r[2]), "=r"(r[3]) : "r"(a));
}
__device__ __forceinline__ void ldsm_x4t(uint32_t r[4], uint32_t a) {
    asm volatile("ldmatrix.sync.aligned.m8n8.x4.trans.shared.b16 {%0,%1,%2,%3}, [%4];"
                 : "=r"(r[0]), "=r"(r[1]), "=r"(r[2]), "=r"(r[3]) : "r"(a));
}
__device__ __forceinline__ void mma_f16(float d[4], const uint32_t a[4],
                                        const uint32_t b[2]) {
    asm volatile(
        "mma.sync.aligned.m16n8k16.row.col.f32.f16.f16.f32 "
        "{%0,%1,%2,%3}, {%4,%5,%6,%7}, {%8,%9}, {%0,%1,%2,%3};"
        : "+f"(d[0]), "+f"(d[1]), "+f"(d[2]), "+f"(d[3])
        : "r"(a[0]), "r"(a[1]), "r"(a[2]), "r"(a[3]), "r"(b[0]), "r"(b[1]));
}
__device__ __forceinline__ void cp_async16(uint32_t dst, const void* src) {
    asm volatile("cp.async.cg.shared.global [%0], [%1], 16;"
                 :: "r"(dst), "l"(src) : "memory");
}
#define CP_COMMIT() asm volatile("cp.async.commit_group;" ::: "memory")
#define CP_WAIT(n)  asm volatile("cp.async.wait_group %0;" :: "n"(n) : "memory")

__device__ __forceinline__ float ex2f(float x) {
    float r;
    asm("ex2.approx.f32 %0, %1;" : "=f"(r) : "f"(x));
    return r;
}
__device__ __forceinline__ void h2_store(__half* p, size_t idx, float a, float b) {
    *(__half2*)&p[idx] = __floats2half2_rn(a, b);
}
__device__ __forceinline__ void h_split_store(__half* hi, __half* lo, size_t idx,
                                              float a, float b) {
    __half h0 = __float2half_rn(a), h1 = __float2half_rn(b);
    __half2 hv(h0, h1);
    __half2 lv(__float2half_rn(a - __half2float(h0)),
               __float2half_rn(b - __half2float(h1)));
    *(__half2*)&hi[idx] = hv;
    *(__half2*)&lo[idx] = lv;
}

// ---------------------------------------------------------------------------
// fp32 -> fp16 hi/lo split (x); fp32 -> fp16 (weights)
// ---------------------------------------------------------------------------
__global__ __launch_bounds__(256) void precvt_x(const float* __restrict__ src,
                                                int n4)
{
    int i = blockIdx.x * 256 + threadIdx.x;
    if (i >= n4) return;
    float4 v = ((const float4*)src)[i];
    __half h0 = __float2half_rn(v.x), h1 = __float2half_rn(v.y);
    __half h2 = __float2half_rn(v.z), h3 = __float2half_rn(v.w);
    ((__half2*)g_xh)[2 * i]     = __half2(h0, h1);
    ((__half2*)g_xh)[2 * i + 1] = __half2(h2, h3);
    ((__half2*)g_xl)[2 * i] =
        __half2(__float2half_rn(v.x - __half2float(h0)),
                __float2half_rn(v.y - __half2float(h1)));
    ((__half2*)g_xl)[2 * i + 1] =
        __half2(__float2half_rn(v.z - __half2float(h2)),
                __float2half_rn(v.w - __half2float(h3)));
}

__global__ __launch_bounds__(256) void precvt_w(const float* __restrict__ w0,
                                                const float* __restrict__ w1,
                                                const float* __restrict__ w2,
                                                const float* __restrict__ w3,
                                                int n4)
{
    const int z = blockIdx.y;
    const float* src = (z == 0) ? w0 : (z == 1) ? w1 : (z == 2) ? w2 : w3;
    __half* dst = g_w + (size_t)z * DMODEL * DMODEL;
    int i = blockIdx.x * 256 + threadIdx.x;
    if (i >= n4) return;
    float4 v = ((const float4*)src)[i];
    ((__half2*)dst)[2 * i]     = __floats2half2_rn(v.x, v.y);
    ((__half2*)dst)[2 * i + 1] = __floats2half2_rn(v.z, v.w);
}

// ---------------------------------------------------------------------------
// fp16 mma.sync GEMM: C[m][e] = sum_d A[m][d] * B[e][d]
// CTA 128x128, 8 warps, K slabs of 64, double-buffered cp.async, 2 CTAs/SM.
// z 0/1 (Q,K): 1-term (xh*W). z 2 (V) + is_out: 2-term ((xh+xl)*W).
// ---------------------------------------------------------------------------
constexpr int GSTR = 72;
constexpr int GARR = 128 * GSTR * 2;                 // 18432 B
constexpr int GBUF = 3 * GARR;                       // 55296 B per buffer
constexpr int GEMM_SMEM = 2 * GBUF;                  // 110592 B

__global__ __launch_bounds__(256, 2)
void gemm_mma(int is_out, const float* __restrict__ bo, float* __restrict__ outp)
{
    extern __shared__ char smc[];
    const uint32_t sbase = smem_u32(smc);

    const int tid  = threadIdx.x;
    const int wid  = tid >> 5;
    const int lane = tid & 31;
    const int wy   = wid >> 2;
    const int wx   = wid & 3;

    const int m0 = blockIdx.y * 128;
    const int e0 = blockIdx.x * 128;
    const int z  = blockIdx.z;
    const bool two = is_out || (z == 2);   // 2-term for V / out proj

    const __half* Ah = is_out ? g_ch : g_xh;
    const __half* Al = is_out ? g_cl : g_xl;
    const int wsel = is_out ? 3 : z;
    const __half* Bw = g_w + (size_t)wsel * DMODEL * DMODEL;

    auto stage = [&](int c, int buf) {
        const int k0 = c << 6;
        const uint32_t b = sbase + buf * GBUF;
        #pragma unroll
        for (int i = 0; i < 4; i++) {
            const int idx = i * 256 + tid;
            const int row = idx >> 3;
            const int col = (idx & 7) * 8;
            const uint32_t so = (uint32_t)(row * GSTR + col) * 2;
            const size_t gA = (size_t)(m0 + row) * DMODEL + k0 + col;
            const size_t gB = (size_t)(e0 + row) * DMODEL + k0 + col;
            cp_async16(b + 0 * GARR + so, Ah + gA);
            cp_async16(b + 2 * GARR + so, Bw + gB);
            if (two) cp_async16(b + 1 * GARR + so, Al + gA);
        }
    };

    const int arow  = (lane & 7) + ((lane >> 3) & 1) * 8;
    const int akoff = (lane >> 4) * 8;
    const int browp = ((lane >> 4) & 1) * 8 + (lane & 7);
    const int bkoff = ((lane >> 3) & 1) * 8;

    float acc[4][4][4] = {};

    stage(0, 0);
    CP_COMMIT();

    for (int c = 0; c < 16; c++) {
        if (c + 1 < 16) {
            stage(c + 1, (c + 1) & 1);
            CP_COMMIT();
            CP_WAIT(1);
        } else {
            CP_WAIT(0);
        }
        __syncthreads();

        const uint32_t b   = sbase + (c & 1) * GBUF;
        const uint32_t aHB = b + 0 * GARR;
        const uint32_t aLB = b + 1 * GARR;
        const uint32_t bB  = b + 2 * GARR;

        #pragma unroll
        for (int ks = 0; ks < 4; ks++) {
            const int k0 = ks * 16;
            uint32_t bh[2][4];
            #pragma unroll
            for (int fp = 0; fp < 2; fp++) {
                const uint32_t off =
                    (uint32_t)((wx * 32 + fp * 16 + browp) * GSTR + k0 + bkoff) * 2;
                ldsm_x4(bh[fp], bB + off);
            }
            #pragma unroll
            for (int fm = 0; fm < 4; fm++) {
                const uint32_t off =
                    (uint32_t)((wy * 64 + fm * 16 + arow) * GSTR + k0 + akoff) * 2;
                uint32_t ah[4];
                ldsm_x4(ah, aHB + off);
                if (two) {
                    uint32_t al[4];
                    ldsm_x4(al, aLB + off);
                    #pragma unroll
                    for (int fp = 0; fp < 2; fp++)
                        #pragma unroll
                        for (int hf = 0; hf < 2; hf++) {
                            const int fn = fp * 2 + hf;
                            mma_f16(acc[fm][fn], ah, &bh[fp][hf * 2]);
                            mma_f16(acc[fm][fn], al, &bh[fp][hf * 2]);
                        }
                } else {
                    #pragma unroll
                    for (int fp = 0; fp < 2; fp++)
                        #pragma unroll
                        for (int hf = 0; hf < 2; hf++)
                            mma_f16(acc[fm][fp * 2 + hf], ah, &bh[fp][hf * 2]);
                }
            }
        }
        __syncthreads();
    }

    const int r0 = lane >> 2;
    const int c0 = (lane & 3) * 2;
    #pragma unroll
    for (int fm = 0; fm < 4; fm++)
        #pragma unroll
        for (int fn = 0; fn < 4; fn++) {
            const int m = m0 + wy * 64 + fm * 16 + r0;
            const int e = e0 + wx * 32 + fn * 8 + c0;
            if (is_out) {
                const float b0v = bo[e], b1v = bo[e + 1];
                float2 v0 = make_float2(acc[fm][fn][0] + b0v, acc[fm][fn][1] + b1v);
                float2 v1 = make_float2(acc[fm][fn][2] + b0v, acc[fm][fn][3] + b1v);
                *(float2*)&outp[(size_t)m * DMODEL + e]       = v0;
                *(float2*)&outp[(size_t)(m + 8) * DMODEL + e] = v1;
            } else {
                __half* dst = (z == 0) ? g_q : (z == 1) ? g_k : g_v;
                const int h = e >> 6, dh = e & 63;
                const int bi = m >> 11, n = m & (SEQ - 1);
                size_t i0 = (((size_t)bi * HEADS + h) * SEQ + n) * DHEAD + dh;
                size_t i1 = (((size_t)bi * HEADS + h) * SEQ + n + 8) * DHEAD + dh;
                h2_store(dst, i0, acc[fm][fn][0], acc[fm][fn][1]);
                h2_store(dst, i1, acc[fm][fn][2], acc[fm][fn][3]);
            }
        }
}

// ---------------------------------------------------------------------------
// FlashAttention-2 mma.sync, all-fp16 operands (unchanged from round 9,
// except ctx is stored as fp16 hi/lo).
// ---------------------------------------------------------------------------
constexpr int QSTR = 72;
constexpr int ATT_Q   = 128 * QSTR * 2;        // 18432 B (Q)
constexpr int ATT_KV1 = 64 * QSTR * 2;         // 9216 B per array
constexpr int ATT_BUF = 2 * ATT_KV1;           // 18432 B (K, V)
constexpr int ATTN_SMEM = ATT_Q + 2 * ATT_BUF; // 55296 B

__global__ __launch_bounds__(256, 2) void attn_mma()
{
    extern __shared__ char smc[];
    const uint32_t sb  = smem_u32(smc);
    const uint32_t qB  = sb;

    const int tid  = threadIdx.x;
    const int wid  = tid >> 5;
    const int lane = tid & 31;
    const int bid  = blockIdx.x;
    const int qb = (SEQ / 128 - 1) - (bid >> 5);   // longest first
    const int hb = bid & 31;
    const int h  = hb & (HEADS - 1);
    const int bb = hb >> 4;

    const size_t hoff = ((size_t)bb * HEADS + h) * SEQ * DHEAD;
    const __half* Qg = g_q + hoff + (size_t)qb * 128 * DHEAD;
    const __half* Kg = g_k + hoff;
    const __half* Vg = g_v + hoff;

    auto stage_kv = [&](int kt, int buf) {
        const uint32_t base = sb + ATT_Q + buf * ATT_BUF;
        const size_t goff = (size_t)kt * 64 * DHEAD;
        #pragma unroll
        for (int i = 0; i < 2; i++) {
            int c = i * 256 + tid;
            int r = c >> 3, col = (c & 7) * 8;
            uint32_t so = (uint32_t)(r * QSTR + col) * 2;
            size_t go = goff + (size_t)r * DHEAD + col;
            cp_async16(base + 0 * ATT_KV1 + so, Kg + go);
            cp_async16(base + 1 * ATT_KV1 + so, Vg + go);
        }
    };

    #pragma unroll
    for (int i = 0; i < 4; i++) {
        int c = i * 256 + tid;
        int r = c >> 3, col = (c & 7) * 8;
        uint32_t so = (uint32_t)(r * QSTR + col) * 2;
        cp_async16(qB + so, Qg + (size_t)r * DHEAD + col);
    }
    stage_kv(0, 0);
    CP_COMMIT();
    CP_WAIT(0);
    __syncthreads();

    const int arow  = (lane & 7) + ((lane >> 3) & 1) * 8;
    const int akoff = (lane >> 4) * 8;
    const int browp = ((lane >> 4) & 1) * 8 + (lane & 7);
    const int bkoff = ((lane >> 3) & 1) * 8;
    const int vrowl = (lane & 7) + ((lane >> 3) & 1) * 8;
    const int vcolp = ((lane >> 4) & 1) * 8;

    const int g  = lane >> 2;
    const int tg = lane & 3;
    const int rowbase = qb * 128 + wid * 16;

    float o[8][4] = {};
    float mrow0 = -INFINITY, mrow1 = -INFINITY;
    float lrow0 = 0.f, lrow1 = 0.f;

    const int ktmax = 2 * qb + 1;
    for (int kt = 0; kt <= ktmax; kt++) {
        __syncthreads();
        if (kt < ktmax) {
            stage_kv(kt + 1, (kt + 1) & 1);
            CP_COMMIT();
            CP_WAIT(1);
        } else {
            CP_WAIT(0);
        }
        __syncthreads();

        const uint32_t kB = sb + ATT_Q + (kt & 1) * ATT_BUF;

        // S = Q @ K^T (fp16, 1 term)
        float s[8][4] = {};
        #pragma unroll
        for (int ks = 0; ks < 4; ks++) {
            uint32_t qoff = (uint32_t)((wid * 16 + arow) * QSTR + ks * 16 + akoff) * 2;
            uint32_t q4[4];
            ldsm_x4(q4, qB + qoff);
            #pragma unroll
            for (int fp = 0; fp < 4; fp++) {
                uint32_t off =
                    (uint32_t)((fp * 16 + browp) * QSTR + ks * 16 + bkoff) * 2;
                uint32_t b4[4];
                ldsm_x4(b4, kB + off);
                mma_f16(s[fp * 2 + 0], q4, &b4[0]);
                mma_f16(s[fp * 2 + 1], q4, &b4[2]);
            }
        }

        // scale (base-2 domain) + causal mask
        const bool needmask = (kt * 64 + 63 > rowbase);
        const int r0g = rowbase + g, r1g = r0g + 8;
        #pragma unroll
        for (int fn = 0; fn < 8; fn++) {
            const int cbase = kt * 64 + fn * 8 + tg * 2;
            float v0 = s[fn][0] * SCALE2, v1 = s[fn][1] * SCALE2;
            float v2 = s[fn][2] * SCALE2, v3 = s[fn][3] * SCALE2;
            if (needmask) {
                if (cbase     > r0g) v0 = -INFINITY;
                if (cbase + 1 > r0g) v1 = -INFINITY;
                if (cbase     > r1g) v2 = -INFINITY;
                if (cbase + 1 > r1g) v3 = -INFINITY;
            }
            s[fn][0] = v0; s[fn][1] = v1; s[fn][2] = v2; s[fn][3] = v3;
        }

        float mx0 = -INFINITY, mx1 = -INFINITY;
        #pragma unroll
        for (int fn = 0; fn < 8; fn++) {
            mx0 = fmaxf(mx0, fmaxf(s[fn][0], s[fn][1]));
            mx1 = fmaxf(mx1, fmaxf(s[fn][2], s[fn][3]));
        }
        mx0 = fmaxf(mx0, __shfl_xor_sync(0xffffffffu, mx0, 1));
        mx0 = fmaxf(mx0, __shfl_xor_sync(0xffffffffu, mx0, 2));
        mx1 = fmaxf(mx1, __shfl_xor_sync(0xffffffffu, mx1, 1));
        mx1 = fmaxf(mx1, __shfl_xor_sync(0xffffffffu, mx1, 2));

        const float mn0 = fmaxf(mrow0, mx0);
        const float mn1 = fmaxf(mrow1, mx1);
        const float al0 = ex2f(mrow0 - mn0);
        const float al1 = ex2f(mrow1 - mn1);

        float rs0 = 0.f, rs1 = 0.f;
        #pragma unroll
        for (int fn = 0; fn < 8; fn++) {
            float p0 = ex2f(s[fn][0] - mn0);
            float p1 = ex2f(s[fn][1] - mn0);
            float p2 = ex2f(s[fn][2] - mn1);
            float p3 = ex2f(s[fn][3] - mn1);
            s[fn][0] = p0; s[fn][1] = p1; s[fn][2] = p2; s[fn][3] = p3;
            rs0 += p0 + p1;
            rs1 += p2 + p3;
        }
        rs0 += __shfl_xor_sync(0xffffffffu, rs0, 1);
        rs0 += __shfl_xor_sync(0xffffffffu, rs0, 2);
        rs1 += __shfl_xor_sync(0xffffffffu, rs1, 1);
        rs1 += __shfl_xor_sync(0xffffffffu, rs1, 2);

        lrow0 = lrow0 * al0 + rs0;
        lrow1 = lrow1 * al1 + rs1;
        mrow0 = mn0; mrow1 = mn1;

        #pragma unroll
        for (int fn = 0; fn < 8; fn++) {
            o[fn][0] *= al0; o[fn][1] *= al0;
            o[fn][2] *= al1; o[fn][3] *= al1;
        }

        // O += P @ V (fp16, 1 term)
        const uint32_t vB = kB + 1 * ATT_KV1;
        #pragma unroll
        for (int kg = 0; kg < 4; kg++) {
            uint32_t ph[4];
            #pragma unroll
            for (int half = 0; half < 2; half++) {
                const int f = 2 * kg + half;
                __half2 t0 = __floats2half2_rn(s[f][0], s[f][1]);
                __half2 t1 = __floats2half2_rn(s[f][2], s[f][3]);
                ph[2 * half]     = *(uint32_t*)&t0;
                ph[2 * half + 1] = *(uint32_t*)&t1;
            }
            const int vrow = kg * 16 + vrowl;
            #pragma unroll
            for (int fp = 0; fp < 4; fp++) {
                uint32_t off = (uint32_t)(vrow * QSTR + fp * 16 + vcolp) * 2;
                uint32_t v4[4];
                ldsm_x4t(v4, vB + off);
                mma_f16(o[fp * 2 + 0], ph, &v4[0]);
                mma_f16(o[fp * 2 + 1], ph, &v4[2]);
            }
        }
    }

    const float inv0 = 1.f / lrow0;
    const float inv1 = 1.f / lrow1;
    const int q0 = rowbase + g;
    const int q1 = q0 + 8;
    #pragma unroll
    for (int fn = 0; fn < 8; fn++) {
        const int e = h * 64 + fn * 8 + tg * 2;
        size_t i0 = (size_t)(bb * SEQ + q0) * DMODEL + e;
        size_t i1 = (size_t)(bb * SEQ + q1) * DMODEL + e;
        h_split_store(g_ch, g_cl, i0, o[fn][0] * inv0, o[fn][1] * inv0);
        h_split_store(g_ch, g_cl, i1, o[fn][2] * inv1, o[fn][3] * inv1);
    }
}

// ---------------------------------------------------------------------------
extern "C" void kernel_launch(void* const* d_in, const int* in_sizes, int n_in,
                              void* d_out, int out_size)
{
    (void)in_sizes; (void)n_in; (void)out_size;
    const float* x  = (const float*)d_in[0];
    const float* Wq = (const float*)d_in[1];
    const float* Wk = (const float*)d_in[2];
    const float* Wv = (const float*)d_in[3];
    const float* Wo = (const float*)d_in[4];
    const float* bo = (const float*)d_in[5];
    float* out = (float*)d_out;

    cudaFuncSetAttribute(gemm_mma, cudaFuncAttributeMaxDynamicSharedMemorySize,
                         GEMM_SMEM);
    cudaFuncSetAttribute(attn_mma, cudaFuncAttributeMaxDynamicSharedMemorySize,
                         ATTN_SMEM);

    const int NX4 = MTOT * DMODEL / 4;
    const int NW4 = DMODEL * DMODEL / 4;

    precvt_x<<<NX4 / 256, 256>>>(x, NX4);
    precvt_w<<<dim3(NW4 / 256, 4), 256>>>(Wq, Wk, Wv, Wo, NW4);

    gemm_mma<<<dim3(DMODEL / 128, MTOT / 128, 3), 256, GEMM_SMEM>>>(0, nullptr, nullptr);
    attn_mma<<<(SEQ / 128) * HEADS * BATCH, 256, ATTN_SMEM>>>();
    gemm_mma<<<dim3(DMODEL / 128, MTOT / 128, 1), 256, GEMM_SMEM>>>(1, bo, out);
}

// round 11
// speedup vs baseline: 9.3047x; 1.2848x over previous
#include <cuda_runtime.h>
#include <cuda_fp16.h>
#include <math.h>
#include <stdint.h>

// Problem constants
constexpr int BATCH = 2;
constexpr int SEQ   = 2048;
constexpr int DMODEL= 1024;
constexpr int HEADS = 16;
constexpr int DHEAD = 64;
constexpr int MTOT  = BATCH * SEQ;           // 4096
// (1/sqrt(2048)) * log2(e) -- softmax runs in base-2 domain
constexpr float SCALE2 = 0.0318793566f;

// Scratch (allocation-free rule: __device__ globals). All fp16, single-plane.
__device__ __half g_x [MTOT * DMODEL];
__device__ __half g_w [4 * DMODEL * DMODEL];
__device__ __half g_q [BATCH * HEADS * SEQ * DHEAD];
__device__ __half g_k [BATCH * HEADS * SEQ * DHEAD];
__device__ __half g_v [BATCH * HEADS * SEQ * DHEAD];
__device__ __half g_c [MTOT * DMODEL];

// ---------------------------------------------------------------------------
// Portable tensor-core helpers (sm_80+ ISA)
// ---------------------------------------------------------------------------
__device__ __forceinline__ uint32_t smem_u32(const void* p) {
    uint32_t a;
    asm("{ .reg .u64 t; cvta.to.shared.u64 t, %1; cvt.u32.u64 %0, t; }"
        : "=r"(a) : "l"(p));
    return a;
}
__device__ __forceinline__ void ldsm_x4(uint32_t r[4], uint32_t a) {
    asm volatile("ldmatrix.sync.aligned.m8n8.x4.shared.b16 {%0,%1,%2,%3}, [%4];"
                 : "=r"(r[0]), "=r"(r[1]), "=r"(r[2]), "=r"(r[3]) : "r"(a));
}
__device__ __forceinline__ void ldsm_x4t(uint32_t r[4], uint32_t a) {
    asm volatile("ldmatrix.sync.aligned.m8n8.x4.trans.shared.b16 {%0,%1,%2,%3}, [%4];"
                 : "=r"(r[0]), "=r"(r[1]), "=r"(r[2]), "=r"(r[3]) : "r"(a));
}
__device__ __forceinline__ void mma_f16(float d[4], const uint32_t a[4],
                                        const uint32_t b[2]) {
    asm volatile(
        "mma.sync.aligned.m16n8k16.row.col.f32.f16.f16.f32 "
        "{%0,%1,%2,%3}, {%4,%5,%6,%7}, {%8,%9}, {%0,%1,%2,%3};"
        : "+f"(d[0]), "+f"(d[1]), "+f"(d[2]), "+f"(d[3])
        : "r"(a[0]), "r"(a[1]), "r"(a[2]), "r"(a[3]), "r"(b[0]), "r"(b[1]));
}
__device__ __forceinline__ void cp_async16(uint32_t dst, const void* src) {
    asm volatile("cp.async.cg.shared.global [%0], [%1], 16;"
                 :: "r"(dst), "l"(src) : "memory");
}
#define CP_COMMIT() asm volatile("cp.async.commit_group;" ::: "memory")
#define CP_WAIT(n)  asm volatile("cp.async.wait_group %0;" :: "n"(n) : "memory")

__device__ __forceinline__ float ex2f(float x) {
    float r;
    asm("ex2.approx.f32 %0, %1;" : "=f"(r) : "f"(x));
    return r;
}
__device__ __forceinline__ void h2_store(__half* p, size_t idx, float a, float b) {
    *(__half2*)&p[idx] = __floats2half2_rn(a, b);
}

// ---------------------------------------------------------------------------
// fp32 -> fp16 converts
// ---------------------------------------------------------------------------
__global__ __launch_bounds__(256) void precvt_x(const float* __restrict__ src,
                                                int n4)
{
    int i = blockIdx.x * 256 + threadIdx.x;
    if (i >= n4) return;
    float4 v = ((const float4*)src)[i];
    ((__half2*)g_x)[2 * i]     = __floats2half2_rn(v.x, v.y);
    ((__half2*)g_x)[2 * i + 1] = __floats2half2_rn(v.z, v.w);
}

__global__ __launch_bounds__(256) void precvt_w(const float* __restrict__ w0,
                                                const float* __restrict__ w1,
                                                const float* __restrict__ w2,
                                                const float* __restrict__ w3,
                                                int n4)
{
    const int z = blockIdx.y;
    const float* src = (z == 0) ? w0 : (z == 1) ? w1 : (z == 2) ? w2 : w3;
    __half* dst = g_w + (size_t)z * DMODEL * DMODEL;
    int i = blockIdx.x * 256 + threadIdx.x;
    if (i >= n4) return;
    float4 v = ((const float4*)src)[i];
    ((__half2*)dst)[2 * i]     = __floats2half2_rn(v.x, v.y);
    ((__half2*)dst)[2 * i + 1] = __floats2half2_rn(v.z, v.w);
}

// ---------------------------------------------------------------------------
// fp16 mma.sync GEMM (1-term everywhere): C[m][e] = sum_d A[m][d] * B[e][d]
// CTA 128x128, 8 warps, K slabs of 64, double-buffered cp.async, 2 CTAs/SM.
// ---------------------------------------------------------------------------
constexpr int GSTR = 72;
constexpr int GARR = 128 * GSTR * 2;                 // 18432 B
constexpr int GBUF = 2 * GARR;                       // 36864 B per buffer
constexpr int GEMM_SMEM = 2 * GBUF;                  // 73728 B

__global__ __launch_bounds__(256, 2)
void gemm_mma(int is_out, const float* __restrict__ bo, float* __restrict__ outp)
{
    extern __shared__ char smc[];
    const uint32_t sbase = smem_u32(smc);

    const int tid  = threadIdx.x;
    const int wid  = tid >> 5;
    const int lane = tid & 31;
    const int wy   = wid >> 2;
    const int wx   = wid & 3;

    const int m0 = blockIdx.y * 128;
    const int e0 = blockIdx.x * 128;
    const int z  = blockIdx.z;

    const __half* Aa = is_out ? g_c : g_x;
    const int wsel = is_out ? 3 : z;
    const __half* Bw = g_w + (size_t)wsel * DMODEL * DMODEL;

    auto stage = [&](int c, int buf) {
        const int k0 = c << 6;
        const uint32_t b = sbase + buf * GBUF;
        #pragma unroll
        for (int i = 0; i < 4; i++) {
            const int idx = i * 256 + tid;
            const int row = idx >> 3;
            const int col = (idx & 7) * 8;
            const uint32_t so = (uint32_t)(row * GSTR + col) * 2;
            cp_async16(b + 0 * GARR + so, Aa + (size_t)(m0 + row) * DMODEL + k0 + col);
            cp_async16(b + 1 * GARR + so, Bw + (size_t)(e0 + row) * DMODEL + k0 + col);
        }
    };

    const int arow  = (lane & 7) + ((lane >> 3) & 1) * 8;
    const int akoff = (lane >> 4) * 8;
    const int browp = ((lane >> 4) & 1) * 8 + (lane & 7);
    const int bkoff = ((lane >> 3) & 1) * 8;

    float acc[4][4][4] = {};

    stage(0, 0);
    CP_COMMIT();

    for (int c = 0; c < 16; c++) {
        if (c + 1 < 16) {
            stage(c + 1, (c + 1) & 1);
            CP_COMMIT();
            CP_WAIT(1);
        } else {
            CP_WAIT(0);
        }
        __syncthreads();

        const uint32_t b  = sbase + (c & 1) * GBUF;
        const uint32_t aB = b + 0 * GARR;
        const uint32_t bB = b + 1 * GARR;

        #pragma unroll
        for (int ks = 0; ks < 4; ks++) {
            const int k0 = ks * 16;
            uint32_t bh[2][4];
            #pragma unroll
            for (int fp = 0; fp < 2; fp++) {
                const uint32_t off =
                    (uint32_t)((wx * 32 + fp * 16 + browp) * GSTR + k0 + bkoff) * 2;
                ldsm_x4(bh[fp], bB + off);
            }
            #pragma unroll
            for (int fm = 0; fm < 4; fm++) {
                const uint32_t off =
                    (uint32_t)((wy * 64 + fm * 16 + arow) * GSTR + k0 + akoff) * 2;
                uint32_t ah[4];
                ldsm_x4(ah, aB + off);
                #pragma unroll
                for (int fp = 0; fp < 2; fp++)
                    #pragma unroll
                    for (int hf = 0; hf < 2; hf++)
                        mma_f16(acc[fm][fp * 2 + hf], ah, &bh[fp][hf * 2]);
            }
        }
        __syncthreads();
    }

    const int r0 = lane >> 2;
    const int c0 = (lane & 3) * 2;
    #pragma unroll
    for (int fm = 0; fm < 4; fm++)
        #pragma unroll
        for (int fn = 0; fn < 4; fn++) {
            const int m = m0 + wy * 64 + fm * 16 + r0;
            const int e = e0 + wx * 32 + fn * 8 + c0;
            if (is_out) {
                const float b0v = bo[e], b1v = bo[e + 1];
                float2 v0 = make_float2(acc[fm][fn][0] + b0v, acc[fm][fn][1] + b1v);
                float2 v1 = make_float2(acc[fm][fn][2] + b0v, acc[fm][fn][3] + b1v);
                *(float2*)&outp[(size_t)m * DMODEL + e]       = v0;
                *(float2*)&outp[(size_t)(m + 8) * DMODEL + e] = v1;
            } else {
                __half* dst = (z == 0) ? g_q : (z == 1) ? g_k : g_v;
                const int h = e >> 6, dh = e & 63;
                const int bi = m >> 11, n = m & (SEQ - 1);
                size_t i0 = (((size_t)bi * HEADS + h) * SEQ + n) * DHEAD + dh;
                size_t i1 = (((size_t)bi * HEADS + h) * SEQ + n + 8) * DHEAD + dh;
                h2_store(dst, i0, acc[fm][fn][0], acc[fm][fn][1]);
                h2_store(dst, i1, acc[fm][fn][2], acc[fm][fn][3]);
            }
        }
}

// ---------------------------------------------------------------------------
// FlashAttention-2 mma.sync, all-fp16 (as round 10; ctx stored plain fp16).
// ---------------------------------------------------------------------------
constexpr int QSTR = 72;
constexpr int ATT_Q   = 128 * QSTR * 2;        // 18432 B (Q)
constexpr int ATT_KV1 = 64 * QSTR * 2;         // 9216 B per array
constexpr int ATT_BUF = 2 * ATT_KV1;           // 18432 B (K, V)
constexpr int ATTN_SMEM = ATT_Q + 2 * ATT_BUF; // 55296 B

__global__ __launch_bounds__(256, 2) void attn_mma()
{
    extern __shared__ char smc[];
    const uint32_t sb  = smem_u32(smc);
    const uint32_t qB  = sb;

    const int tid  = threadIdx.x;
    const int wid  = tid >> 5;
    const int lane = tid & 31;
    const int bid  = blockIdx.x;
    const int qb = (SEQ / 128 - 1) - (bid >> 5);   // longest first
    const int hb = bid & 31;
    const int h  = hb & (HEADS - 1);
    const int bb = hb >> 4;

    const size_t hoff = ((size_t)bb * HEADS + h) * SEQ * DHEAD;
    const __half* Qg = g_q + hoff + (size_t)qb * 128 * DHEAD;
    const __half* Kg = g_k + hoff;
    const __half* Vg = g_v + hoff;

    auto stage_kv = [&](int kt, int buf) {
        const uint32_t base = sb + ATT_Q + buf * ATT_BUF;
        const size_t goff = (size_t)kt * 64 * DHEAD;
        #pragma unroll
        for (int i = 0; i < 2; i++) {
            int c = i * 256 + tid;
            int r = c >> 3, col = (c & 7) * 8;
            uint32_t so = (uint32_t)(r * QSTR + col) * 2;
            size_t go = goff + (size_t)r * DHEAD + col;
            cp_async16(base + 0 * ATT_KV1 + so, Kg + go);
            cp_async16(base + 1 * ATT_KV1 + so, Vg + go);
        }
    };

    #pragma unroll
    for (int i = 0; i < 4; i++) {
        int c = i * 256 + tid;
        int r = c >> 3, col = (c & 7) * 8;
        uint32_t so = (uint32_t)(r * QSTR + col) * 2;
        cp_async16(qB + so, Qg + (size_t)r * DHEAD + col);
    }
    stage_kv(0, 0);
    CP_COMMIT();
    CP_WAIT(0);
    __syncthreads();

    const int arow  = (lane & 7) + ((lane >> 3) & 1) * 8;
    const int akoff = (lane >> 4) * 8;
    const int browp = ((lane >> 4) & 1) * 8 + (lane & 7);
    const int bkoff = ((lane >> 3) & 1) * 8;
    const int vrowl = (lane & 7) + ((lane >> 3) & 1) * 8;
    const int vcolp = ((lane >> 4) & 1) * 8;

    const int g  = lane >> 2;
    const int tg = lane & 3;
    const int rowbase = qb * 128 + wid * 16;

    float o[8][4] = {};
    float mrow0 = -INFINITY, mrow1 = -INFINITY;
    float lrow0 = 0.f, lrow1 = 0.f;

    const int ktmax = 2 * qb + 1;
    for (int kt = 0; kt <= ktmax; kt++) {
        __syncthreads();
        if (kt < ktmax) {
            stage_kv(kt + 1, (kt + 1) & 1);
            CP_COMMIT();
            CP_WAIT(1);
        } else {
            CP_WAIT(0);
        }
        __syncthreads();

        const uint32_t kB = sb + ATT_Q + (kt & 1) * ATT_BUF;

        // S = Q @ K^T (fp16, 1 term)
        float s[8][4] = {};
        #pragma unroll
        for (int ks = 0; ks < 4; ks++) {
            uint32_t qoff = (uint32_t)((wid * 16 + arow) * QSTR + ks * 16 + akoff) * 2;
            uint32_t q4[4];
            ldsm_x4(q4, qB + qoff);
            #pragma unroll
            for (int fp = 0; fp < 4; fp++) {
                uint32_t off =
                    (uint32_t)((fp * 16 + browp) * QSTR + ks * 16 + bkoff) * 2;
                uint32_t b4[4];
                ldsm_x4(b4, kB + off);
                mma_f16(s[fp * 2 + 0], q4, &b4[0]);
                mma_f16(s[fp * 2 + 1], q4, &b4[2]);
            }
        }

        // scale (base-2 domain) + causal mask
        const bool needmask = (kt * 64 + 63 > rowbase);
        const int r0g = rowbase + g, r1g = r0g + 8;
        #pragma unroll
        for (int fn = 0; fn < 8; fn++) {
            const int cbase = kt * 64 + fn * 8 + tg * 2;
            float v0 = s[fn][0] * SCALE2, v1 = s[fn][1] * SCALE2;
            float v2 = s[fn][2] * SCALE2, v3 = s[fn][3] * SCALE2;
            if (needmask) {
                if (cbase     > r0g) v0 = -INFINITY;
                if (cbase + 1 > r0g) v1 = -INFINITY;
                if (cbase     > r1g) v2 = -INFINITY;
                if (cbase + 1 > r1g) v3 = -INFINITY;
            }
            s[fn][0] = v0; s[fn][1] = v1; s[fn][2] = v2; s[fn][3] = v3;
        }

        float mx0 = -INFINITY, mx1 = -INFINITY;
        #pragma unroll
        for (int fn = 0; fn < 8; fn++) {
            mx0 = fmaxf(mx0, fmaxf(s[fn][0], s[fn][1]));
            mx1 = fmaxf(mx1, fmaxf(s[fn][2], s[fn][3]));
        }
        mx0 = fmaxf(mx0, __shfl_xor_sync(0xffffffffu, mx0, 1));
        mx0 = fmaxf(mx0, __shfl_xor_sync(0xffffffffu, mx0, 2));
        mx1 = fmaxf(mx1, __shfl_xor_sync(0xffffffffu, mx1, 1));
        mx1 = fmaxf(mx1, __shfl_xor_sync(0xffffffffu, mx1, 2));

        const float mn0 = fmaxf(mrow0, mx0);
        const float mn1 = fmaxf(mrow1, mx1);
        const float al0 = ex2f(mrow0 - mn0);
        const float al1 = ex2f(mrow1 - mn1);

        float rs0 = 0.f, rs1 = 0.f;
        #pragma unroll
        for (int fn = 0; fn < 8; fn++) {
            float p0 = ex2f(s[fn][0] - mn0);
            float p1 = ex2f(s[fn][1] - mn0);
            float p2 = ex2f(s[fn][2] - mn1);
            float p3 = ex2f(s[fn][3] - mn1);
            s[fn][0] = p0; s[fn][1] = p1; s[fn][2] = p2; s[fn][3] = p3;
            rs0 += p0 + p1;
            rs1 += p2 + p3;
        }
        rs0 += __shfl_xor_sync(0xffffffffu, rs0, 1);
        rs0 += __shfl_xor_sync(0xffffffffu, rs0, 2);
        rs1 += __shfl_xor_sync(0xffffffffu, rs1, 1);
        rs1 += __shfl_xor_sync(0xffffffffu, rs1, 2);

        lrow0 = lrow0 * al0 + rs0;
        lrow1 = lrow1 * al1 + rs1;
        mrow0 = mn0; mrow1 = mn1;

        #pragma unroll
        for (int fn = 0; fn < 8; fn++) {
            o[fn][0] *= al0; o[fn][1] *= al0;
            o[fn][2] *= al1; o[fn][3] *= al1;
        }

        // O += P @ V (fp16, 1 term)
        const uint32_t vB = kB + 1 * ATT_KV1;
        #pragma unroll
        for (int kg = 0; kg < 4; kg++) {
            uint32_t ph[4];
            #pragma unroll
            for (int half = 0; half < 2; half++) {
                const int f = 2 * kg + half;
                __half2 t0 = __floats2half2_rn(s[f][0], s[f][1]);
                __half2 t1 = __floats2half2_rn(s[f][2], s[f][3]);
                ph[2 * half]     = *(uint32_t*)&t0;
                ph[2 * half + 1] = *(uint32_t*)&t1;
            }
            const int vrow = kg * 16 + vrowl;
            #pragma unroll
            for (int fp = 0; fp < 4; fp++) {
                uint32_t off = (uint32_t)(vrow * QSTR + fp * 16 + vcolp) * 2;
                uint32_t v4[4];
                ldsm_x4t(v4, vB + off);
                mma_f16(o[fp * 2 + 0], ph, &v4[0]);
                mma_f16(o[fp * 2 + 1], ph, &v4[2]);
            }
        }
    }

    const float inv0 = 1.f / lrow0;
    const float inv1 = 1.f / lrow1;
    const int q0 = rowbase + g;
    const int q1 = q0 + 8;
    #pragma unroll
    for (int fn = 0; fn < 8; fn++) {
        const int e = h * 64 + fn * 8 + tg * 2;
        size_t i0 = (size_t)(bb * SEQ + q0) * DMODEL + e;
        size_t i1 = (size_t)(bb * SEQ + q1) * DMODEL + e;
        h2_store(g_c, i0, o[fn][0] * inv0, o[fn][1] * inv0);
        h2_store(g_c, i1, o[fn][2] * inv1, o[fn][3] * inv1);
    }
}

// ---------------------------------------------------------------------------
extern "C" void kernel_launch(void* const* d_in, const int* in_sizes, int n_in,
                              void* d_out, int out_size)
{
    (void)in_sizes; (void)n_in; (void)out_size;
    const float* x  = (const float*)d_in[0];
    const float* Wq = (const float*)d_in[1];
    const float* Wk = (const float*)d_in[2];
    const float* Wv = (const float*)d_in[3];
    const float* Wo = (const float*)d_in[4];
    const float* bo = (const float*)d_in[5];
    float* out = (float*)d_out;

    cudaFuncSetAttribute(gemm_mma, cudaFuncAttributeMaxDynamicSharedMemorySize,
                         GEMM_SMEM);
    cudaFuncSetAttribute(attn_mma, cudaFuncAttributeMaxDynamicSharedMemorySize,
                         ATTN_SMEM);

    const int NX4 = MTOT * DMODEL / 4;
    const int NW4 = DMODEL * DMODEL / 4;

    precvt_x<<<NX4 / 256, 256>>>(x, NX4);
    precvt_w<<<dim3(NW4 / 256, 4), 256>>>(Wq, Wk, Wv, Wo, NW4);

    gemm_mma<<<dim3(DMODEL / 128, MTOT / 128, 3), 256, GEMM_SMEM>>>(0, nullptr, nullptr);
    attn_mma<<<(SEQ / 128) * HEADS * BATCH, 256, ATTN_SMEM>>>();
    gemm_mma<<<dim3(DMODEL / 128, MTOT / 128, 1), 256, GEMM_SMEM>>>(1, bo, out);
}